// round 9
// baseline (speedup 1.0000x reference)
#include <cuda_runtime.h>
#include <cuda_fp16.h>
#include <math.h>
#include <stdint.h>

// ---------------- problem constants ----------------
#define LSEQ 2048
#define DMODEL 768
#define KDIM 768
#define NHEAD 12
#define DHEAD 64
#define NCHUNK 16
#define CSIZE 128
#define LN_EPS 1e-5f
#define DEN_EPS 1e-6f

// ---------------- scratch (device globals) ----------------
__device__ __align__(128) __half g_a   [LSEQ * DMODEL];   // LN(x) fp16
__device__ __align__(128) __half g_x   [LSEQ * DMODEL];   // x fp16
__device__ __align__(128) __half g_wqkv[2304 * KDIM];     // W_qkv^T fp16
__device__ __align__(128) __half g_wsc [3072 * KDIM];     // [W_sem;W_ctx]^T fp16
__device__ __align__(128) __half g_wpr [768 * KDIM];      // W_proj^T fp16
__device__ __align__(128) __half g_at  [LSEQ * DMODEL];   // attn out fp16
__device__ __align__(128) float g_bsc[3072];
__device__ __align__(128) float g_qkv[LSEQ * 3 * DMODEL];
__device__ __align__(128) float g_semctx[LSEQ * 3072];
__device__ float g_qf[NHEAD * LSEQ * DHEAD];
__device__ float g_kf[NHEAD * LSEQ * DHEAD];
__device__ float g_vv[NHEAD * LSEQ * DHEAD];
__device__ float g_S [NHEAD * NCHUNK * DHEAD * DHEAD];
__device__ float g_Z [NHEAD * NCHUNK * DHEAD];

// ---------------- PTX helpers (family-portable only) ----------------
__device__ __forceinline__ uint32_t smem_u32(const void* p) {
    uint32_t a;
    asm("{ .reg .u64 t; cvta.to.shared.u64 t, %1; cvt.u32.u64 %0, t; }" : "=r"(a) : "l"(p));
    return a;
}
__device__ __forceinline__ void cp_async16(uint32_t dst, const void* src) {
    asm volatile("cp.async.cg.shared.global [%0], [%1], 16;" :: "r"(dst), "l"(src));
}
__device__ __forceinline__ void cp_commit() {
    asm volatile("cp.async.commit_group;" ::: "memory");
}
__device__ __forceinline__ void cp_wait1() {
    asm volatile("cp.async.wait_group 1;" ::: "memory");
}
#define LDSM4(r0, r1, r2, r3, a) \
    asm volatile("ldmatrix.sync.aligned.m8n8.x4.shared.b16 {%0,%1,%2,%3}, [%4];" \
                 : "=r"(r0), "=r"(r1), "=r"(r2), "=r"(r3) : "r"(a))
#define MMAF16(d, a0, a1, a2, a3, b0, b1) \
    asm volatile("mma.sync.aligned.m16n8k16.row.col.f32.f16.f16.f32 " \
                 "{%0,%1,%2,%3}, {%4,%5,%6,%7}, {%8,%9}, {%0,%1,%2,%3};" \
                 : "+f"((d)[0]), "+f"((d)[1]), "+f"((d)[2]), "+f"((d)[3]) \
                 : "r"(a0), "r"(a1), "r"(a2), "r"(a3), "r"(b0), "r"(b1))

// ---------------- GEMM: C[2048,Ntot] = A @ B^T + bias (fp16, BK=64) ----------------
#define BK 64
#define ROWB 144                      // 128 B data + 16 B pad -> conflict-free ldmatrix
#define TILEB (128 * ROWB)            // 18432 B per 128x64 tile
#define STAGEB (2 * TILEB)            // A, B
#define NSTAGE 3
#define GEMM_SMEM (NSTAGE * STAGEB)   // 110592 B -> 2 CTAs/SM
#define NKT (KDIM / BK)               // 12

__device__ __forceinline__ void g_load_stage(
    uint32_t smem_base, int s, int tid,
    const __half* a, const __half* b)
{
    uint32_t stb = smem_base + (uint32_t)(s % NSTAGE) * STAGEB;
    int kk = s * BK;
    #pragma unroll
    for (int t = 0; t < 2; t++) {
        const __half* base = t ? b : a;
        #pragma unroll
        for (int i = 0; i < 4; i++) {
            int c = tid + i * 256;          // 0..1023
            int r = c >> 3;                 // 0..127
            int seg = c & 7;                // 0..7 (8 x 16B = 128B row)
            cp_async16(stb + (uint32_t)t * TILEB + (uint32_t)(r * ROWB + seg * 16),
                       base + (size_t)r * KDIM + kk + seg * 8);
        }
    }
}

__global__ __launch_bounds__(256, 2)
void gemm_mma(const __half* __restrict__ A, const __half* __restrict__ BT,
              const float* __restrict__ bias, float* __restrict__ C, int Ntot)
{
    extern __shared__ __align__(128) char smem[];
    const int tid = threadIdx.x;
    const int wid = tid >> 5;
    const int lane = tid & 31;
    const int wm = wid & 1;        // M: 2 x 64
    const int wn = wid >> 1;       // N: 4 x 32
    const int bx = blockIdx.x, by = blockIdx.y;

    uint32_t smem_base = smem_u32(smem);

    const __half* a = A + (size_t)by * 128 * KDIM;
    const __half* b = BT + (size_t)bx * 128 * KDIM;

    float acc[4][4][4];
    #pragma unroll
    for (int i = 0; i < 4; i++)
        #pragma unroll
        for (int j = 0; j < 4; j++)
            #pragma unroll
            for (int t = 0; t < 4; t++) acc[i][j][t] = 0.f;

    const uint32_t a_row = (uint32_t)(lane & 15);
    const uint32_t a_byt = (uint32_t)((lane >> 4) * 16);
    const uint32_t b_row = (uint32_t)((lane & 7) + ((lane >> 4) << 3));
    const uint32_t b_byt = (uint32_t)(((lane >> 3) & 1) * 16);

    // prologue: 2 stages in flight
    g_load_stage(smem_base, 0, tid, a, b); cp_commit();
    g_load_stage(smem_base, 1, tid, a, b); cp_commit();

    for (int s = 0; s < NKT; s++) {
        cp_wait1();                 // group s retired
        __syncthreads();
        if (s + 2 < NKT) g_load_stage(smem_base, s + 2, tid, a, b);
        cp_commit();

        uint32_t stb = smem_base + (uint32_t)(s % NSTAGE) * STAGEB;
        #pragma unroll
        for (int k16 = 0; k16 < 4; k16++) {
            const uint32_t koff = (uint32_t)(k16 * 32);
            uint32_t af[4][4];
            #pragma unroll
            for (int mt = 0; mt < 4; mt++) {
                uint32_t addr = stb + (uint32_t)(wm * 64 + mt * 16 + a_row) * ROWB
                              + koff + a_byt;
                LDSM4(af[mt][0], af[mt][1], af[mt][2], af[mt][3], addr);
            }
            uint32_t bf[2][4];
            #pragma unroll
            for (int nb = 0; nb < 2; nb++) {
                uint32_t addr = stb + TILEB + (uint32_t)(wn * 32 + nb * 16 + b_row) * ROWB
                              + koff + b_byt;
                LDSM4(bf[nb][0], bf[nb][1], bf[nb][2], bf[nb][3], addr);
            }
            #pragma unroll
            for (int mt = 0; mt < 4; mt++)
                #pragma unroll
                for (int nt = 0; nt < 4; nt++)
                    MMAF16(acc[mt][nt],
                           af[mt][0], af[mt][1], af[mt][2], af[mt][3],
                           bf[nt >> 1][(nt & 1) * 2], bf[nt >> 1][(nt & 1) * 2 + 1]);
        }
    }

    int r0 = by * 128 + wm * 64 + (lane >> 2);
    int c0 = bx * 128 + wn * 32 + (lane & 3) * 2;
    #pragma unroll
    for (int mt = 0; mt < 4; mt++) {
        #pragma unroll
        for (int nt = 0; nt < 4; nt++) {
            int r = r0 + mt * 16;
            int c = c0 + nt * 8;
            float2 v0 = { acc[mt][nt][0] + bias[c], acc[mt][nt][1] + bias[c + 1] };
            float2 v1 = { acc[mt][nt][2] + bias[c], acc[mt][nt][3] + bias[c + 1] };
            *(float2*)&C[(size_t)r * Ntot + c] = v0;
            *(float2*)&C[(size_t)(r + 8) * Ntot + c] = v1;
        }
    }
}

// ---------------- merged weight transpose + fp16 convert (one launch) ----------------
__global__ void transpose_split_all(const float* __restrict__ Wq,
                                    const float* __restrict__ Ws,
                                    const float* __restrict__ Wc,
                                    const float* __restrict__ Wp)
{
    __shared__ float tile[32][33];
    int bx = blockIdx.x;
    const float* W; int N, rowOff;
    __half* oT;
    if (bx < 72)       { W = Wq; N = 2304; rowOff = 0;    oT = g_wqkv; }
    else if (bx < 120) { W = Ws; N = 1536; rowOff = 0;    oT = g_wsc;  bx -= 72; }
    else if (bx < 168) { W = Wc; N = 1536; rowOff = 1536; oT = g_wsc;  bx -= 120; }
    else               { W = Wp; N = 768;  rowOff = 0;    oT = g_wpr;  bx -= 168; }

    int n0 = bx * 32, k0 = blockIdx.y * 32;
    int tx = threadIdx.x, ty = threadIdx.y;   // (32, 8)
    #pragma unroll
    for (int i = 0; i < 4; i++)
        tile[ty + i * 8][tx] = W[(size_t)(k0 + ty + i * 8) * N + n0 + tx];
    __syncthreads();
    #pragma unroll
    for (int i = 0; i < 4; i++) {
        int n = ty + i * 8;
        oT[(size_t)(rowOff + n0 + n) * KDIM + k0 + tx] = __float2half(tile[tx][n]);
    }
}

__global__ void concat_bias(const float* __restrict__ bs, const float* __restrict__ bc) {
    int i = blockIdx.x * 256 + threadIdx.x;
    if (i < 1536) g_bsc[i] = bs[i];
    else if (i < 3072) g_bsc[i] = bc[i - 1536];
}

// ---------------- LayerNorm + fp16 convert (also converts raw x) ----------------
__global__ void ln_split_kernel(const float* __restrict__ x,
                                const float* __restrict__ gamma,
                                const float* __restrict__ beta) {
    int row = blockIdx.x;
    const float* xr = x + (size_t)row * DMODEL;
    int tid = threadIdx.x;
    __shared__ float red[8];

    float s = 0.f;
    for (int i = tid; i < DMODEL; i += 256) s += xr[i];
    #pragma unroll
    for (int o = 16; o > 0; o >>= 1) s += __shfl_down_sync(0xffffffffu, s, o);
    if ((tid & 31) == 0) red[tid >> 5] = s;
    __syncthreads();
    if (tid < 8) {
        s = red[tid];
        #pragma unroll
        for (int o = 4; o > 0; o >>= 1) s += __shfl_down_sync(0xffu, s, o);
        if (tid == 0) red[0] = s;
    }
    __syncthreads();
    float mu = red[0] * (1.f / DMODEL);
    __syncthreads();

    float v = 0.f;
    for (int i = tid; i < DMODEL; i += 256) { float d = xr[i] - mu; v += d * d; }
    #pragma unroll
    for (int o = 16; o > 0; o >>= 1) v += __shfl_down_sync(0xffffffffu, v, o);
    if ((tid & 31) == 0) red[tid >> 5] = v;
    __syncthreads();
    if (tid < 8) {
        v = red[tid];
        #pragma unroll
        for (int o = 4; o > 0; o >>= 1) v += __shfl_down_sync(0xffu, v, o);
        if (tid == 0) red[0] = v;
    }
    __syncthreads();
    float inv = rsqrtf(red[0] * (1.f / DMODEL) + LN_EPS);

    for (int i = tid; i < DMODEL; i += 256) {
        float xv = xr[i];
        float ln = (xv - mu) * inv * gamma[i] + beta[i];
        g_a[(size_t)row * DMODEL + i] = __float2half(ln);
        g_x[(size_t)row * DMODEL + i] = __float2half(xv);
    }
}

// ---------------- gate + feature map (fast-math intrinsics) ----------------
__device__ __forceinline__ float softplus_fast(float x) {
    return (x > 0.f) ? x + __logf(1.f + __expf(-x)) : __logf(1.f + __expf(x));
}

__global__ void features_kernel() {
    int idx = blockIdx.x * blockDim.x + threadIdx.x;
    if (idx >= LSEQ * DMODEL) return;
    int l = idx / DMODEL;
    int d = idx - l * DMODEL;

    const float* scr = g_semctx + (size_t)l * 3072;
    float sa = softplus_fast(scr[d]);
    float sp = scr[768 + d];
    float ca = softplus_fast(scr[1536 + d]);
    float cp = scr[2304 + d];
    float z = sa * ca * __cosf(sp - cp);
    float gate = 1.f / (1.f + __expf(-z));

    float q = g_qkv[(size_t)l * 3 * DMODEL + d];
    float k = g_qkv[(size_t)l * 3 * DMODEL + DMODEL + d] * gate;
    float v = g_qkv[(size_t)l * 3 * DMODEL + 2 * DMODEL + d];

    int h = d >> 6;
    int dh = d & 63;
    size_t o = (size_t)h * LSEQ * DHEAD + (size_t)l * DHEAD + dh;
    g_qf[o] = (q > 0.f) ? q + 1.f : __expf(q);
    g_kf[o] = (k > 0.f) ? k + 1.f : __expf(k);
    g_vv[o] = v;
}

// ---------------- phase A: per-chunk state sums ----------------
__global__ __launch_bounds__(256)
void chunk_sums_kernel() {
    int h = blockIdx.x / NCHUNK;
    int c = blockIdx.x % NCHUNK;
    const float* Kb = g_kf + (size_t)h * LSEQ * DHEAD + (size_t)c * CSIZE * DHEAD;
    const float* Vb = g_vv + (size_t)h * LSEQ * DHEAD + (size_t)c * CSIZE * DHEAD;

    __shared__ float ks[16][64];
    __shared__ float vs[16][64];
    int tid = threadIdx.x;
    int te = tid & 15;
    int td = tid >> 4;

    float acc[4][4];
    #pragma unroll
    for (int i = 0; i < 4; i++)
        #pragma unroll
        for (int j = 0; j < 4; j++) acc[i][j] = 0.f;
    float zacc[4] = {0.f, 0.f, 0.f, 0.f};

    int lr = tid >> 4;
    int lc = (tid & 15) * 4;

    for (int p0 = 0; p0 < CSIZE; p0 += 16) {
        *(float4*)&ks[lr][lc] = *(const float4*)&Kb[(size_t)(p0 + lr) * DHEAD + lc];
        *(float4*)&vs[lr][lc] = *(const float4*)&Vb[(size_t)(p0 + lr) * DHEAD + lc];
        __syncthreads();
        #pragma unroll
        for (int p = 0; p < 16; p++) {
            float kk[4], vvv[4];
            #pragma unroll
            for (int i = 0; i < 4; i++) kk[i] = ks[p][td * 4 + i];
            #pragma unroll
            for (int j = 0; j < 4; j++) vvv[j] = vs[p][te * 4 + j];
            #pragma unroll
            for (int i = 0; i < 4; i++)
                #pragma unroll
                for (int j = 0; j < 4; j++)
                    acc[i][j] = fmaf(kk[i], vvv[j], acc[i][j]);
            if (te == 0) {
                #pragma unroll
                for (int i = 0; i < 4; i++) zacc[i] += kk[i];
            }
        }
        __syncthreads();
    }

    float* Sb = g_S + (size_t)(h * NCHUNK + c) * DHEAD * DHEAD;
    #pragma unroll
    for (int i = 0; i < 4; i++)
        #pragma unroll
        for (int j = 0; j < 4; j++)
            Sb[(size_t)(td * 4 + i) * DHEAD + te * 4 + j] = acc[i][j];
    if (te == 0) {
        float* Zb = g_Z + (size_t)(h * NCHUNK + c) * DHEAD;
        #pragma unroll
        for (int i = 0; i < 4; i++) Zb[td * 4 + i] = zacc[i];
    }
}

// ---------------- phase B: exclusive scan over chunks (grid (12,4)) ----------------
__global__ __launch_bounds__(256)
void scan_states_kernel() {
    int h = blockIdx.x;
    int part = blockIdx.y;
    int tid = threadIdx.x;
    float pref[4] = {0.f, 0.f, 0.f, 0.f};
    float prefz = 0.f;

    for (int c = 0; c < NCHUNK; c++) {
        float* Sb = g_S + (size_t)(h * NCHUNK + c) * DHEAD * DHEAD + part * 1024;
        #pragma unroll
        for (int i = 0; i < 4; i++) {
            int idx = tid + i * 256;
            float cur = Sb[idx];
            Sb[idx] = pref[i];
            pref[i] += cur;
        }
        if (part == 0 && tid < DHEAD) {
            float* Zb = g_Z + (size_t)(h * NCHUNK + c) * DHEAD;
            float cur = Zb[tid];
            Zb[tid] = prefz;
            prefz += cur;
        }
    }
}

// ---------------- phase C: balanced causal output ----------------
// grid (192, 4): block (h,c,sub) handles rows [32*sub, 32*sub+32), 4 threads/row.
// Thread part p takes j = p, p+4, ... <= row; prefix d-range split 4-way;
// partials merged via shfl_xor(1),shfl_xor(2) (row's threads = adjacent lanes).
#define SMEM_C (2 * CSIZE * DHEAD * 4)   // worst case (sub=3): 64 KB

__global__ __launch_bounds__(128)
void chunk_attn_kernel() {
    int h = blockIdx.x / NCHUNK;
    int c = blockIdx.x % NCHUNK;
    int sub = blockIdx.y;                 // 0..3
    int R = (sub + 1) * 32;               // K/V rows needed
    extern __shared__ float sh[];
    float* Ks = sh;
    float* Vs = sh + R * DHEAD;

    int tid = threadIdx.x;
    int row = sub * 32 + (tid >> 2);
    int part = tid & 3;
    size_t base = (size_t)h * LSEQ * DHEAD + (size_t)c * CSIZE * DHEAD;

    const float4* Kg = (const float4*)(g_kf + base);
    const float4* Vg = (const float4*)(g_vv + base);
    for (int j = tid; j < R * DHEAD / 4; j += 128) {
        ((float4*)Ks)[j] = Kg[j];
        ((float4*)Vs)[j] = Vg[j];
    }
    __syncthreads();

    // full q for this row (compile-time indexed register array)
    const float* qrow = g_qf + base + (size_t)row * DHEAD;
    float q[DHEAD];
    {
        const float4* qp = (const float4*)qrow;
        #pragma unroll
        for (int i = 0; i < DHEAD / 4; i++) {
            float4 t = qp[i];
            q[4 * i + 0] = t.x; q[4 * i + 1] = t.y; q[4 * i + 2] = t.z; q[4 * i + 3] = t.w;
        }
    }

    const float* Pg = g_S + (size_t)(h * NCHUNK + c) * DHEAD * DHEAD;
    const float* Zg = g_Z + (size_t)(h * NCHUNK + c) * DHEAD;

    float out[DHEAD];
    #pragma unroll
    for (int e = 0; e < DHEAD; e++) out[e] = 0.f;
    float den = 0.f;

    // prefix part: d in [16*part, 16*part+16)  (qd re-read from gmem: runtime offset)
    {
        int d0 = part * 16;
        #pragma unroll 4
        for (int dd = 0; dd < 16; dd++) {
            int d = d0 + dd;
            float qd = __ldg(&qrow[d]);
            den = fmaf(qd, __ldg(&Zg[d]), den);
            const float4* pr = (const float4*)(Pg + d * DHEAD);
            #pragma unroll
            for (int i = 0; i < DHEAD / 4; i++) {
                float4 p = __ldg(&pr[i]);
                out[4 * i + 0] = fmaf(qd, p.x, out[4 * i + 0]);
                out[4 * i + 1] = fmaf(qd, p.y, out[4 * i + 1]);
                out[4 * i + 2] = fmaf(qd, p.z, out[4 * i + 2]);
                out[4 * i + 3] = fmaf(qd, p.w, out[4 * i + 3]);
            }
        }
    }

    // intra-chunk causal: j = part, part+4, ..., <= row
    for (int j = part; j <= row; j += 4) {
        const float4* kr = (const float4*)(Ks + j * DHEAD);
        float s0 = 0.f, s1 = 0.f, s2 = 0.f, s3 = 0.f;
        #pragma unroll
        for (int i = 0; i < DHEAD / 4; i += 4) {
            float4 k0 = kr[i], k1 = kr[i + 1], k2 = kr[i + 2], k3 = kr[i + 3];
            s0 = fmaf(q[4 * i + 0], k0.x, s0); s0 = fmaf(q[4 * i + 1], k0.y, s0);
            s0 = fmaf(q[4 * i + 2], k0.z, s0); s0 = fmaf(q[4 * i + 3], k0.w, s0);
            s1 = fmaf(q[4 * i + 4], k1.x, s1); s1 = fmaf(q[4 * i + 5], k1.y, s1);
            s1 = fmaf(q[4 * i + 6], k1.z, s1); s1 = fmaf(q[4 * i + 7], k1.w, s1);
            s2 = fmaf(q[4 * i + 8], k2.x, s2); s2 = fmaf(q[4 * i + 9], k2.y, s2);
            s2 = fmaf(q[4 * i + 10], k2.z, s2); s2 = fmaf(q[4 * i + 11], k2.w, s2);
            s3 = fmaf(q[4 * i + 12], k3.x, s3); s3 = fmaf(q[4 * i + 13], k3.y, s3);
            s3 = fmaf(q[4 * i + 14], k3.z, s3); s3 = fmaf(q[4 * i + 15], k3.w, s3);
        }
        float s = (s0 + s1) + (s2 + s3);
        den += s;
        const float4* vr = (const float4*)(Vs + j * DHEAD);
        #pragma unroll
        for (int i = 0; i < DHEAD / 4; i++) {
            float4 vv4 = vr[i];
            out[4 * i + 0] = fmaf(s, vv4.x, out[4 * i + 0]);
            out[4 * i + 1] = fmaf(s, vv4.y, out[4 * i + 1]);
            out[4 * i + 2] = fmaf(s, vv4.z, out[4 * i + 2]);
            out[4 * i + 3] = fmaf(s, vv4.w, out[4 * i + 3]);
        }
    }

    // merge 4 partials (row threads are adjacent lanes)
    #pragma unroll
    for (int e = 0; e < DHEAD; e++) {
        out[e] += __shfl_xor_sync(0xffffffffu, out[e], 1);
        out[e] += __shfl_xor_sync(0xffffffffu, out[e], 2);
    }
    den += __shfl_xor_sync(0xffffffffu, den, 1);
    den += __shfl_xor_sync(0xffffffffu, den, 2);

    if (part == 0) {
        float inv = 1.f / (den + DEN_EPS);
        int l = c * CSIZE + row;
        __half* op = g_at + (size_t)l * DMODEL + h * DHEAD;
        #pragma unroll
        for (int e = 0; e < DHEAD; e += 2) {
            __half2 hv = __floats2half2_rn(out[e] * inv, out[e + 1] * inv);
            *(__half2*)&op[e] = hv;
        }
    }
}

// ---------------- host launcher ----------------
extern "C" void kernel_launch(void* const* d_in, const int* in_sizes, int n_in,
                              void* d_out, int out_size) {
    const float* x      = (const float*)d_in[0];
    const float* W_qkv  = (const float*)d_in[1];
    const float* b_qkv  = (const float*)d_in[2];
    const float* W_sem  = (const float*)d_in[3];
    const float* b_sem  = (const float*)d_in[4];
    const float* W_ctx  = (const float*)d_in[5];
    const float* b_ctx  = (const float*)d_in[6];
    const float* W_proj = (const float*)d_in[7];
    const float* b_proj = (const float*)d_in[8];
    const float* ln_g   = (const float*)d_in[9];
    const float* ln_b   = (const float*)d_in[10];
    float* out = (float*)d_out;

    __half *p_a, *p_x, *p_wq, *p_ws, *p_wp, *p_at;
    float *p_bsc, *p_qkv, *p_semctx;
    cudaGetSymbolAddress((void**)&p_a, g_a);
    cudaGetSymbolAddress((void**)&p_x, g_x);
    cudaGetSymbolAddress((void**)&p_wq, g_wqkv);
    cudaGetSymbolAddress((void**)&p_ws, g_wsc);
    cudaGetSymbolAddress((void**)&p_wp, g_wpr);
    cudaGetSymbolAddress((void**)&p_at, g_at);
    cudaGetSymbolAddress((void**)&p_bsc, g_bsc);
    cudaGetSymbolAddress((void**)&p_qkv, g_qkv);
    cudaGetSymbolAddress((void**)&p_semctx, g_semctx);

    cudaFuncSetAttribute(gemm_mma, cudaFuncAttributeMaxDynamicSharedMemorySize, GEMM_SMEM);
    cudaFuncSetAttribute(chunk_attn_kernel, cudaFuncAttributeMaxDynamicSharedMemorySize, SMEM_C);

    // weight prep (single launch) + biases + LN
    transpose_split_all<<<dim3(192, 24), dim3(32, 8)>>>(W_qkv, W_sem, W_ctx, W_proj);
    concat_bias<<<12, 256>>>(b_sem, b_ctx);
    ln_split_kernel<<<LSEQ, 256>>>(x, ln_g, ln_b);

    // fp16 tensor-core GEMMs
    gemm_mma<<<dim3(2304 / 128, LSEQ / 128), 256, GEMM_SMEM>>>(p_a, p_wq, b_qkv, p_qkv, 2304);
    gemm_mma<<<dim3(3072 / 128, LSEQ / 128), 256, GEMM_SMEM>>>(p_x, p_ws, p_bsc, p_semctx, 3072);

    // gate + feature map
    features_kernel<<<(LSEQ * DMODEL + 255) / 256, 256>>>();

    // chunked linear attention
    chunk_sums_kernel<<<NHEAD * NCHUNK, 256>>>();
    scan_states_kernel<<<dim3(NHEAD, 4), 256>>>();
    chunk_attn_kernel<<<dim3(NHEAD * NCHUNK, 4), 128, SMEM_C>>>();

    // output projection
    gemm_mma<<<dim3(768 / 128, LSEQ / 128), 256, GEMM_SMEM>>>(p_at, p_wp, b_proj, out, 768);
}

// round 10
// speedup vs baseline: 1.4937x; 1.4937x over previous
#include <cuda_runtime.h>
#include <cuda_fp16.h>
#include <math.h>
#include <stdint.h>

// ---------------- problem constants ----------------
#define LSEQ 2048
#define DMODEL 768
#define KDIM 768
#define NHEAD 12
#define DHEAD 64
#define NCHUNK 16
#define CSIZE 128
#define LN_EPS 1e-5f
#define DEN_EPS 1e-6f

// ---------------- scratch (device globals) ----------------
__device__ __align__(128) __half g_a   [LSEQ * DMODEL];   // LN(x) fp16
__device__ __align__(128) __half g_x   [LSEQ * DMODEL];   // x fp16
__device__ __align__(128) __half g_wqkv[2304 * KDIM];     // W_qkv^T fp16
__device__ __align__(128) __half g_wsc [3072 * KDIM];     // [W_sem;W_ctx]^T fp16
__device__ __align__(128) __half g_wpr [768 * KDIM];      // W_proj^T fp16
__device__ __align__(128) __half g_at  [LSEQ * DMODEL];   // attn out fp16
__device__ __align__(128) float g_bsc[3072];
__device__ __align__(128) float g_qkv[LSEQ * 3 * DMODEL];
__device__ __align__(128) float g_semctx[LSEQ * 3072];
__device__ float g_qf[NHEAD * LSEQ * DHEAD];
__device__ float g_kf[NHEAD * LSEQ * DHEAD];
__device__ float g_vv[NHEAD * LSEQ * DHEAD];
__device__ float g_S [NHEAD * NCHUNK * DHEAD * DHEAD];
__device__ float g_Z [NHEAD * NCHUNK * DHEAD];

// ---------------- PTX helpers (family-portable only) ----------------
__device__ __forceinline__ uint32_t smem_u32(const void* p) {
    uint32_t a;
    asm("{ .reg .u64 t; cvta.to.shared.u64 t, %1; cvt.u32.u64 %0, t; }" : "=r"(a) : "l"(p));
    return a;
}
__device__ __forceinline__ void cp_async16(uint32_t dst, const void* src) {
    asm volatile("cp.async.cg.shared.global [%0], [%1], 16;" :: "r"(dst), "l"(src));
}
__device__ __forceinline__ void cp_commit() {
    asm volatile("cp.async.commit_group;" ::: "memory");
}
__device__ __forceinline__ void cp_wait1() {
    asm volatile("cp.async.wait_group 1;" ::: "memory");
}
#define LDSM4(r0, r1, r2, r3, a) \
    asm volatile("ldmatrix.sync.aligned.m8n8.x4.shared.b16 {%0,%1,%2,%3}, [%4];" \
                 : "=r"(r0), "=r"(r1), "=r"(r2), "=r"(r3) : "r"(a))
#define MMAF16(d, a0, a1, a2, a3, b0, b1) \
    asm volatile("mma.sync.aligned.m16n8k16.row.col.f32.f16.f16.f32 " \
                 "{%0,%1,%2,%3}, {%4,%5,%6,%7}, {%8,%9}, {%0,%1,%2,%3};" \
                 : "+f"((d)[0]), "+f"((d)[1]), "+f"((d)[2]), "+f"((d)[3]) \
                 : "r"(a0), "r"(a1), "r"(a2), "r"(a3), "r"(b0), "r"(b1))

// ---------------- GEMM: C[2048,Ntot] = A @ B^T + bias (fp16, BK=64) ----------------
#define BK 64
#define ROWB 144                      // 128 B data + 16 B pad -> conflict-free ldmatrix
#define TILEB (128 * ROWB)            // 18432 B per 128x64 tile
#define STAGEB (2 * TILEB)            // A, B
#define NSTAGE 3
#define GEMM_SMEM (NSTAGE * STAGEB)   // 110592 B -> 2 CTAs/SM
#define NKT (KDIM / BK)               // 12

__device__ __forceinline__ void g_load_stage(
    uint32_t smem_base, int s, int tid,
    const __half* a, const __half* b)
{
    uint32_t stb = smem_base + (uint32_t)(s % NSTAGE) * STAGEB;
    int kk = s * BK;
    #pragma unroll
    for (int t = 0; t < 2; t++) {
        const __half* base = t ? b : a;
        #pragma unroll
        for (int i = 0; i < 4; i++) {
            int c = tid + i * 256;          // 0..1023
            int r = c >> 3;                 // 0..127
            int seg = c & 7;                // 0..7 (8 x 16B = 128B row)
            cp_async16(stb + (uint32_t)t * TILEB + (uint32_t)(r * ROWB + seg * 16),
                       base + (size_t)r * KDIM + kk + seg * 8);
        }
    }
}

__global__ __launch_bounds__(256, 2)
void gemm_mma(const __half* __restrict__ A, const __half* __restrict__ BT,
              const float* __restrict__ bias, float* __restrict__ C, int Ntot)
{
    extern __shared__ __align__(128) char smem[];
    const int tid = threadIdx.x;
    const int wid = tid >> 5;
    const int lane = tid & 31;
    const int wm = wid & 1;        // M: 2 x 64
    const int wn = wid >> 1;       // N: 4 x 32
    const int bx = blockIdx.x, by = blockIdx.y;

    uint32_t smem_base = smem_u32(smem);

    const __half* a = A + (size_t)by * 128 * KDIM;
    const __half* b = BT + (size_t)bx * 128 * KDIM;

    float acc[4][4][4];
    #pragma unroll
    for (int i = 0; i < 4; i++)
        #pragma unroll
        for (int j = 0; j < 4; j++)
            #pragma unroll
            for (int t = 0; t < 4; t++) acc[i][j][t] = 0.f;

    const uint32_t a_row = (uint32_t)(lane & 15);
    const uint32_t a_byt = (uint32_t)((lane >> 4) * 16);
    const uint32_t b_row = (uint32_t)((lane & 7) + ((lane >> 4) << 3));
    const uint32_t b_byt = (uint32_t)(((lane >> 3) & 1) * 16);

    // prologue: 2 stages in flight
    g_load_stage(smem_base, 0, tid, a, b); cp_commit();
    g_load_stage(smem_base, 1, tid, a, b); cp_commit();

    for (int s = 0; s < NKT; s++) {
        cp_wait1();                 // group s retired
        __syncthreads();
        if (s + 2 < NKT) g_load_stage(smem_base, s + 2, tid, a, b);
        cp_commit();

        uint32_t stb = smem_base + (uint32_t)(s % NSTAGE) * STAGEB;
        #pragma unroll
        for (int k16 = 0; k16 < 4; k16++) {
            const uint32_t koff = (uint32_t)(k16 * 32);
            uint32_t af[4][4];
            #pragma unroll
            for (int mt = 0; mt < 4; mt++) {
                uint32_t addr = stb + (uint32_t)(wm * 64 + mt * 16 + a_row) * ROWB
                              + koff + a_byt;
                LDSM4(af[mt][0], af[mt][1], af[mt][2], af[mt][3], addr);
            }
            uint32_t bf[2][4];
            #pragma unroll
            for (int nb = 0; nb < 2; nb++) {
                uint32_t addr = stb + TILEB + (uint32_t)(wn * 32 + nb * 16 + b_row) * ROWB
                              + koff + b_byt;
                LDSM4(bf[nb][0], bf[nb][1], bf[nb][2], bf[nb][3], addr);
            }
            #pragma unroll
            for (int mt = 0; mt < 4; mt++)
                #pragma unroll
                for (int nt = 0; nt < 4; nt++)
                    MMAF16(acc[mt][nt],
                           af[mt][0], af[mt][1], af[mt][2], af[mt][3],
                           bf[nt >> 1][(nt & 1) * 2], bf[nt >> 1][(nt & 1) * 2 + 1]);
        }
    }

    int r0 = by * 128 + wm * 64 + (lane >> 2);
    int c0 = bx * 128 + wn * 32 + (lane & 3) * 2;
    #pragma unroll
    for (int mt = 0; mt < 4; mt++) {
        #pragma unroll
        for (int nt = 0; nt < 4; nt++) {
            int r = r0 + mt * 16;
            int c = c0 + nt * 8;
            float2 v0 = { acc[mt][nt][0] + bias[c], acc[mt][nt][1] + bias[c + 1] };
            float2 v1 = { acc[mt][nt][2] + bias[c], acc[mt][nt][3] + bias[c + 1] };
            *(float2*)&C[(size_t)r * Ntot + c] = v0;
            *(float2*)&C[(size_t)(r + 8) * Ntot + c] = v1;
        }
    }
}

// ---------------- merged weight transpose + fp16 convert (one launch) ----------------
__global__ void transpose_split_all(const float* __restrict__ Wq,
                                    const float* __restrict__ Ws,
                                    const float* __restrict__ Wc,
                                    const float* __restrict__ Wp)
{
    __shared__ float tile[32][33];
    int bx = blockIdx.x;
    const float* W; int N, rowOff;
    __half* oT;
    if (bx < 72)       { W = Wq; N = 2304; rowOff = 0;    oT = g_wqkv; }
    else if (bx < 120) { W = Ws; N = 1536; rowOff = 0;    oT = g_wsc;  bx -= 72; }
    else if (bx < 168) { W = Wc; N = 1536; rowOff = 1536; oT = g_wsc;  bx -= 120; }
    else               { W = Wp; N = 768;  rowOff = 0;    oT = g_wpr;  bx -= 168; }

    int n0 = bx * 32, k0 = blockIdx.y * 32;
    int tx = threadIdx.x, ty = threadIdx.y;   // (32, 8)
    #pragma unroll
    for (int i = 0; i < 4; i++)
        tile[ty + i * 8][tx] = W[(size_t)(k0 + ty + i * 8) * N + n0 + tx];
    __syncthreads();
    #pragma unroll
    for (int i = 0; i < 4; i++) {
        int n = ty + i * 8;
        oT[(size_t)(rowOff + n0 + n) * KDIM + k0 + tx] = __float2half(tile[tx][n]);
    }
}

__global__ void concat_bias(const float* __restrict__ bs, const float* __restrict__ bc) {
    int i = blockIdx.x * 256 + threadIdx.x;
    if (i < 1536) g_bsc[i] = bs[i];
    else if (i < 3072) g_bsc[i] = bc[i - 1536];
}

// ---------------- LayerNorm + fp16 convert (also converts raw x) ----------------
__global__ void ln_split_kernel(const float* __restrict__ x,
                                const float* __restrict__ gamma,
                                const float* __restrict__ beta) {
    int row = blockIdx.x;
    const float* xr = x + (size_t)row * DMODEL;
    int tid = threadIdx.x;
    __shared__ float red[8];

    float s = 0.f;
    for (int i = tid; i < DMODEL; i += 256) s += xr[i];
    #pragma unroll
    for (int o = 16; o > 0; o >>= 1) s += __shfl_down_sync(0xffffffffu, s, o);
    if ((tid & 31) == 0) red[tid >> 5] = s;
    __syncthreads();
    if (tid < 8) {
        s = red[tid];
        #pragma unroll
        for (int o = 4; o > 0; o >>= 1) s += __shfl_down_sync(0xffu, s, o);
        if (tid == 0) red[0] = s;
    }
    __syncthreads();
    float mu = red[0] * (1.f / DMODEL);
    __syncthreads();

    float v = 0.f;
    for (int i = tid; i < DMODEL; i += 256) { float d = xr[i] - mu; v += d * d; }
    #pragma unroll
    for (int o = 16; o > 0; o >>= 1) v += __shfl_down_sync(0xffffffffu, v, o);
    if ((tid & 31) == 0) red[tid >> 5] = v;
    __syncthreads();
    if (tid < 8) {
        v = red[tid];
        #pragma unroll
        for (int o = 4; o > 0; o >>= 1) v += __shfl_down_sync(0xffu, v, o);
        if (tid == 0) red[0] = v;
    }
    __syncthreads();
    float inv = rsqrtf(red[0] * (1.f / DMODEL) + LN_EPS);

    for (int i = tid; i < DMODEL; i += 256) {
        float xv = xr[i];
        float ln = (xv - mu) * inv * gamma[i] + beta[i];
        g_a[(size_t)row * DMODEL + i] = __float2half(ln);
        g_x[(size_t)row * DMODEL + i] = __float2half(xv);
    }
}

// ---------------- gate + feature map (fast-math intrinsics) ----------------
__device__ __forceinline__ float softplus_fast(float x) {
    return (x > 0.f) ? x + __logf(1.f + __expf(-x)) : __logf(1.f + __expf(x));
}

__global__ void features_kernel() {
    int idx = blockIdx.x * blockDim.x + threadIdx.x;
    if (idx >= LSEQ * DMODEL) return;
    int l = idx / DMODEL;
    int d = idx - l * DMODEL;

    const float* scr = g_semctx + (size_t)l * 3072;
    float sa = softplus_fast(scr[d]);
    float sp = scr[768 + d];
    float ca = softplus_fast(scr[1536 + d]);
    float cp = scr[2304 + d];
    float z = sa * ca * __cosf(sp - cp);
    float gate = 1.f / (1.f + __expf(-z));

    float q = g_qkv[(size_t)l * 3 * DMODEL + d];
    float k = g_qkv[(size_t)l * 3 * DMODEL + DMODEL + d] * gate;
    float v = g_qkv[(size_t)l * 3 * DMODEL + 2 * DMODEL + d];

    int h = d >> 6;
    int dh = d & 63;
    size_t o = (size_t)h * LSEQ * DHEAD + (size_t)l * DHEAD + dh;
    g_qf[o] = (q > 0.f) ? q + 1.f : __expf(q);
    g_kf[o] = (k > 0.f) ? k + 1.f : __expf(k);
    g_vv[o] = v;
}

// ---------------- phase A: per-chunk state sums ----------------
__global__ __launch_bounds__(256)
void chunk_sums_kernel() {
    int h = blockIdx.x / NCHUNK;
    int c = blockIdx.x % NCHUNK;
    const float* Kb = g_kf + (size_t)h * LSEQ * DHEAD + (size_t)c * CSIZE * DHEAD;
    const float* Vb = g_vv + (size_t)h * LSEQ * DHEAD + (size_t)c * CSIZE * DHEAD;

    __shared__ float ks[16][64];
    __shared__ float vs[16][64];
    int tid = threadIdx.x;
    int te = tid & 15;
    int td = tid >> 4;

    float acc[4][4];
    #pragma unroll
    for (int i = 0; i < 4; i++)
        #pragma unroll
        for (int j = 0; j < 4; j++) acc[i][j] = 0.f;
    float zacc[4] = {0.f, 0.f, 0.f, 0.f};

    int lr = tid >> 4;
    int lc = (tid & 15) * 4;

    for (int p0 = 0; p0 < CSIZE; p0 += 16) {
        *(float4*)&ks[lr][lc] = *(const float4*)&Kb[(size_t)(p0 + lr) * DHEAD + lc];
        *(float4*)&vs[lr][lc] = *(const float4*)&Vb[(size_t)(p0 + lr) * DHEAD + lc];
        __syncthreads();
        #pragma unroll
        for (int p = 0; p < 16; p++) {
            float kk[4], vvv[4];
            #pragma unroll
            for (int i = 0; i < 4; i++) kk[i] = ks[p][td * 4 + i];
            #pragma unroll
            for (int j = 0; j < 4; j++) vvv[j] = vs[p][te * 4 + j];
            #pragma unroll
            for (int i = 0; i < 4; i++)
                #pragma unroll
                for (int j = 0; j < 4; j++)
                    acc[i][j] = fmaf(kk[i], vvv[j], acc[i][j]);
            if (te == 0) {
                #pragma unroll
                for (int i = 0; i < 4; i++) zacc[i] += kk[i];
            }
        }
        __syncthreads();
    }

    float* Sb = g_S + (size_t)(h * NCHUNK + c) * DHEAD * DHEAD;
    #pragma unroll
    for (int i = 0; i < 4; i++)
        #pragma unroll
        for (int j = 0; j < 4; j++)
            Sb[(size_t)(td * 4 + i) * DHEAD + te * 4 + j] = acc[i][j];
    if (te == 0) {
        float* Zb = g_Z + (size_t)(h * NCHUNK + c) * DHEAD;
        #pragma unroll
        for (int i = 0; i < 4; i++) Zb[td * 4 + i] = zacc[i];
    }
}

// ---------------- phase B: exclusive scan over chunks (grid (12,4)) ----------------
__global__ __launch_bounds__(256)
void scan_states_kernel() {
    int h = blockIdx.x;
    int part = blockIdx.y;
    int tid = threadIdx.x;
    float pref[4] = {0.f, 0.f, 0.f, 0.f};
    float prefz = 0.f;

    for (int c = 0; c < NCHUNK; c++) {
        float* Sb = g_S + (size_t)(h * NCHUNK + c) * DHEAD * DHEAD + part * 1024;
        #pragma unroll
        for (int i = 0; i < 4; i++) {
            int idx = tid + i * 256;
            float cur = Sb[idx];
            Sb[idx] = pref[i];
            pref[i] += cur;
        }
        if (part == 0 && tid < DHEAD) {
            float* Zb = g_Z + (size_t)(h * NCHUNK + c) * DHEAD;
            float cur = Zb[tid];
            Zb[tid] = prefz;
            prefz += cur;
        }
    }
}

// ---------------- phase C: per-chunk causal output (K,V in smem; P,Z via L1) ----------------
#define SMEM_C (2 * CSIZE * DHEAD * 4)   // 65536 B

__global__ __launch_bounds__(128)
void chunk_attn_kernel() {
    int h = blockIdx.x / NCHUNK;
    int c = blockIdx.x % NCHUNK;
    extern __shared__ float sh[];
    float* Ks = sh;
    float* Vs = Ks + CSIZE * DHEAD;

    int tid = threadIdx.x;
    size_t base = (size_t)h * LSEQ * DHEAD + (size_t)c * CSIZE * DHEAD;

    const float4* Kg = (const float4*)(g_kf + base);
    const float4* Vg = (const float4*)(g_vv + base);
    for (int j = tid; j < CSIZE * DHEAD / 4; j += 128) {
        ((float4*)Ks)[j] = Kg[j];
        ((float4*)Vs)[j] = Vg[j];
    }
    __syncthreads();

    float q[DHEAD];
    {
        const float4* qp = (const float4*)(g_qf + base + (size_t)tid * DHEAD);
        #pragma unroll
        for (int i = 0; i < DHEAD / 4; i++) {
            float4 t = qp[i];
            q[4 * i + 0] = t.x; q[4 * i + 1] = t.y; q[4 * i + 2] = t.z; q[4 * i + 3] = t.w;
        }
    }

    const float* Pg = g_S + (size_t)(h * NCHUNK + c) * DHEAD * DHEAD;
    const float* Zg = g_Z + (size_t)(h * NCHUNK + c) * DHEAD;

    float out[DHEAD];
    float den = 0.f;
    #pragma unroll
    for (int d = 0; d < DHEAD; d++) den = fmaf(q[d], __ldg(&Zg[d]), den);
    #pragma unroll
    for (int e = 0; e < DHEAD; e++) out[e] = 0.f;
    #pragma unroll 4
    for (int d = 0; d < DHEAD; d++) {
        float qd = q[d];
        const float4* pr = (const float4*)(Pg + d * DHEAD);
        #pragma unroll
        for (int i = 0; i < DHEAD / 4; i++) {
            float4 p = __ldg(&pr[i]);
            out[4 * i + 0] = fmaf(qd, p.x, out[4 * i + 0]);
            out[4 * i + 1] = fmaf(qd, p.y, out[4 * i + 1]);
            out[4 * i + 2] = fmaf(qd, p.z, out[4 * i + 2]);
            out[4 * i + 3] = fmaf(qd, p.w, out[4 * i + 3]);
        }
    }

    for (int j = 0; j <= tid; j++) {
        const float4* kr = (const float4*)(Ks + j * DHEAD);
        float s0 = 0.f, s1 = 0.f, s2 = 0.f, s3 = 0.f;
        #pragma unroll
        for (int i = 0; i < DHEAD / 4; i += 4) {
            float4 k0 = kr[i], k1 = kr[i + 1], k2 = kr[i + 2], k3 = kr[i + 3];
            s0 = fmaf(q[4 * i + 0], k0.x, s0); s0 = fmaf(q[4 * i + 1], k0.y, s0);
            s0 = fmaf(q[4 * i + 2], k0.z, s0); s0 = fmaf(q[4 * i + 3], k0.w, s0);
            s1 = fmaf(q[4 * i + 4], k1.x, s1); s1 = fmaf(q[4 * i + 5], k1.y, s1);
            s1 = fmaf(q[4 * i + 6], k1.z, s1); s1 = fmaf(q[4 * i + 7], k1.w, s1);
            s2 = fmaf(q[4 * i + 8], k2.x, s2); s2 = fmaf(q[4 * i + 9], k2.y, s2);
            s2 = fmaf(q[4 * i + 10], k2.z, s2); s2 = fmaf(q[4 * i + 11], k2.w, s2);
            s3 = fmaf(q[4 * i + 12], k3.x, s3); s3 = fmaf(q[4 * i + 13], k3.y, s3);
            s3 = fmaf(q[4 * i + 14], k3.z, s3); s3 = fmaf(q[4 * i + 15], k3.w, s3);
        }
        float s = (s0 + s1) + (s2 + s3);
        den += s;
        const float4* vr = (const float4*)(Vs + j * DHEAD);
        #pragma unroll
        for (int i = 0; i < DHEAD / 4; i++) {
            float4 vv4 = vr[i];
            out[4 * i + 0] = fmaf(s, vv4.x, out[4 * i + 0]);
            out[4 * i + 1] = fmaf(s, vv4.y, out[4 * i + 1]);
            out[4 * i + 2] = fmaf(s, vv4.z, out[4 * i + 2]);
            out[4 * i + 3] = fmaf(s, vv4.w, out[4 * i + 3]);
        }
    }

    float inv = 1.f / (den + DEN_EPS);
    int l = c * CSIZE + tid;
    __half* op = g_at + (size_t)l * DMODEL + h * DHEAD;
    #pragma unroll
    for (int e = 0; e < DHEAD; e += 2) {
        __half2 hv = __floats2half2_rn(out[e] * inv, out[e + 1] * inv);
        *(__half2*)&op[e] = hv;
    }
}

// ---------------- host launcher ----------------
extern "C" void kernel_launch(void* const* d_in, const int* in_sizes, int n_in,
                              void* d_out, int out_size) {
    const float* x      = (const float*)d_in[0];
    const float* W_qkv  = (const float*)d_in[1];
    const float* b_qkv  = (const float*)d_in[2];
    const float* W_sem  = (const float*)d_in[3];
    const float* b_sem  = (const float*)d_in[4];
    const float* W_ctx  = (const float*)d_in[5];
    const float* b_ctx  = (const float*)d_in[6];
    const float* W_proj = (const float*)d_in[7];
    const float* b_proj = (const float*)d_in[8];
    const float* ln_g   = (const float*)d_in[9];
    const float* ln_b   = (const float*)d_in[10];
    float* out = (float*)d_out;

    __half *p_a, *p_x, *p_wq, *p_ws, *p_wp, *p_at;
    float *p_bsc, *p_qkv, *p_semctx;
    cudaGetSymbolAddress((void**)&p_a, g_a);
    cudaGetSymbolAddress((void**)&p_x, g_x);
    cudaGetSymbolAddress((void**)&p_wq, g_wqkv);
    cudaGetSymbolAddress((void**)&p_ws, g_wsc);
    cudaGetSymbolAddress((void**)&p_wp, g_wpr);
    cudaGetSymbolAddress((void**)&p_at, g_at);
    cudaGetSymbolAddress((void**)&p_bsc, g_bsc);
    cudaGetSymbolAddress((void**)&p_qkv, g_qkv);
    cudaGetSymbolAddress((void**)&p_semctx, g_semctx);

    cudaFuncSetAttribute(gemm_mma, cudaFuncAttributeMaxDynamicSharedMemorySize, GEMM_SMEM);
    cudaFuncSetAttribute(chunk_attn_kernel, cudaFuncAttributeMaxDynamicSharedMemorySize, SMEM_C);

    // weight prep (single launch) + biases + LN
    transpose_split_all<<<dim3(192, 24), dim3(32, 8)>>>(W_qkv, W_sem, W_ctx, W_proj);
    concat_bias<<<12, 256>>>(b_sem, b_ctx);
    ln_split_kernel<<<LSEQ, 256>>>(x, ln_g, ln_b);

    // fp16 tensor-core GEMMs
    gemm_mma<<<dim3(2304 / 128, LSEQ / 128), 256, GEMM_SMEM>>>(p_a, p_wq, b_qkv, p_qkv, 2304);
    gemm_mma<<<dim3(3072 / 128, LSEQ / 128), 256, GEMM_SMEM>>>(p_x, p_ws, p_bsc, p_semctx, 3072);

    // gate + feature map
    features_kernel<<<(LSEQ * DMODEL + 255) / 256, 256>>>();

    // chunked linear attention
    chunk_sums_kernel<<<NHEAD * NCHUNK, 256>>>();
    scan_states_kernel<<<dim3(NHEAD, 4), 256>>>();
    chunk_attn_kernel<<<NHEAD * NCHUNK, 128, SMEM_C>>>();

    // output projection
    gemm_mma<<<dim3(768 / 128, LSEQ / 128), 256, GEMM_SMEM>>>(p_at, p_wp, b_proj, out, 768);
}

// round 11
// speedup vs baseline: 1.5166x; 1.0153x over previous
#include <cuda_runtime.h>
#include <cuda_fp16.h>
#include <math.h>
#include <stdint.h>

// ---------------- problem constants ----------------
#define LSEQ 2048
#define DMODEL 768
#define KDIM 768
#define NHEAD 12
#define DHEAD 64
#define NCHUNK 16
#define CSIZE 128
#define LN_EPS 1e-5f
#define DEN_EPS 1e-6f

// ---------------- scratch (device globals) ----------------
__device__ __align__(128) __half g_a   [LSEQ * DMODEL];   // LN(x) fp16
__device__ __align__(128) __half g_x   [LSEQ * DMODEL];   // x fp16
__device__ __align__(128) __half g_wqkv[2304 * KDIM];     // W_qkv^T fp16
__device__ __align__(128) __half g_wsc [3072 * KDIM];     // [W_sem;W_ctx]^T fp16
__device__ __align__(128) __half g_wpr [768 * KDIM];      // W_proj^T fp16
__device__ __align__(128) __half g_at  [LSEQ * DMODEL];   // attn out fp16
__device__ __align__(128) float g_bsc[3072];
__device__ __align__(128) float g_qkv[LSEQ * 3 * DMODEL];
__device__ __align__(128) float g_semctx[LSEQ * 3072];
__device__ float g_qf[NHEAD * LSEQ * DHEAD];
__device__ float g_kf[NHEAD * LSEQ * DHEAD];
__device__ float g_vv[NHEAD * LSEQ * DHEAD];
__device__ float g_S [NHEAD * NCHUNK * DHEAD * DHEAD];
__device__ float g_Z [NHEAD * NCHUNK * DHEAD];

// ---------------- PTX helpers (family-portable only) ----------------
__device__ __forceinline__ uint32_t smem_u32(const void* p) {
    uint32_t a;
    asm("{ .reg .u64 t; cvta.to.shared.u64 t, %1; cvt.u32.u64 %0, t; }" : "=r"(a) : "l"(p));
    return a;
}
__device__ __forceinline__ void cp_async16(uint32_t dst, const void* src) {
    asm volatile("cp.async.cg.shared.global [%0], [%1], 16;" :: "r"(dst), "l"(src));
}
__device__ __forceinline__ void cp_commit() {
    asm volatile("cp.async.commit_group;" ::: "memory");
}
__device__ __forceinline__ void cp_wait1() {
    asm volatile("cp.async.wait_group 1;" ::: "memory");
}
__device__ __forceinline__ float tanh_fast(float x) {
    float y;
    asm("tanh.approx.f32 %0, %1;" : "=f"(y) : "f"(x));
    return y;
}
#define LDSM4(r0, r1, r2, r3, a) \
    asm volatile("ldmatrix.sync.aligned.m8n8.x4.shared.b16 {%0,%1,%2,%3}, [%4];" \
                 : "=r"(r0), "=r"(r1), "=r"(r2), "=r"(r3) : "r"(a))
#define MMAF16(d, a0, a1, a2, a3, b0, b1) \
    asm volatile("mma.sync.aligned.m16n8k16.row.col.f32.f16.f16.f32 " \
                 "{%0,%1,%2,%3}, {%4,%5,%6,%7}, {%8,%9}, {%0,%1,%2,%3};" \
                 : "+f"((d)[0]), "+f"((d)[1]), "+f"((d)[2]), "+f"((d)[3]) \
                 : "r"(a0), "r"(a1), "r"(a2), "r"(a3), "r"(b0), "r"(b1))

// ---------------- GEMM: C[2048,Ntot] = A @ B^T + bias (fp16, BK=64) ----------------
#define BK 64
#define ROWB 144                      // 128 B data + 16 B pad -> conflict-free ldmatrix
#define TILEB (128 * ROWB)            // 18432 B per 128x64 tile
#define STAGEB (2 * TILEB)            // A, B
#define NSTAGE 3
#define GEMM_SMEM (NSTAGE * STAGEB)   // 110592 B -> 2 CTAs/SM
#define NKT (KDIM / BK)               // 12

__device__ __forceinline__ void g_load_stage(
    uint32_t smem_base, int s, int tid,
    const __half* a, const __half* b)
{
    uint32_t stb = smem_base + (uint32_t)(s % NSTAGE) * STAGEB;
    int kk = s * BK;
    #pragma unroll
    for (int t = 0; t < 2; t++) {
        const __half* base = t ? b : a;
        #pragma unroll
        for (int i = 0; i < 4; i++) {
            int c = tid + i * 256;          // 0..1023
            int r = c >> 3;                 // 0..127
            int seg = c & 7;                // 0..7 (8 x 16B = 128B row)
            cp_async16(stb + (uint32_t)t * TILEB + (uint32_t)(r * ROWB + seg * 16),
                       base + (size_t)r * KDIM + kk + seg * 8);
        }
    }
}

__global__ __launch_bounds__(256, 2)
void gemm_mma(const __half* __restrict__ A, const __half* __restrict__ BT,
              const float* __restrict__ bias, float* __restrict__ C, int Ntot)
{
    extern __shared__ __align__(128) char smem[];
    const int tid = threadIdx.x;
    const int wid = tid >> 5;
    const int lane = tid & 31;
    const int wm = wid & 1;        // M: 2 x 64
    const int wn = wid >> 1;       // N: 4 x 32
    const int bx = blockIdx.x, by = blockIdx.y;

    uint32_t smem_base = smem_u32(smem);

    const __half* a = A + (size_t)by * 128 * KDIM;
    const __half* b = BT + (size_t)bx * 128 * KDIM;

    float acc[4][4][4];
    #pragma unroll
    for (int i = 0; i < 4; i++)
        #pragma unroll
        for (int j = 0; j < 4; j++)
            #pragma unroll
            for (int t = 0; t < 4; t++) acc[i][j][t] = 0.f;

    const uint32_t a_row = (uint32_t)(lane & 15);
    const uint32_t a_byt = (uint32_t)((lane >> 4) * 16);
    const uint32_t b_row = (uint32_t)((lane & 7) + ((lane >> 4) << 3));
    const uint32_t b_byt = (uint32_t)(((lane >> 3) & 1) * 16);

    // prologue: 2 stages in flight
    g_load_stage(smem_base, 0, tid, a, b); cp_commit();
    g_load_stage(smem_base, 1, tid, a, b); cp_commit();

    for (int s = 0; s < NKT; s++) {
        cp_wait1();                 // group s retired
        __syncthreads();
        if (s + 2 < NKT) g_load_stage(smem_base, s + 2, tid, a, b);
        cp_commit();

        uint32_t stb = smem_base + (uint32_t)(s % NSTAGE) * STAGEB;
        #pragma unroll
        for (int k16 = 0; k16 < 4; k16++) {
            const uint32_t koff = (uint32_t)(k16 * 32);
            uint32_t af[4][4];
            #pragma unroll
            for (int mt = 0; mt < 4; mt++) {
                uint32_t addr = stb + (uint32_t)(wm * 64 + mt * 16 + a_row) * ROWB
                              + koff + a_byt;
                LDSM4(af[mt][0], af[mt][1], af[mt][2], af[mt][3], addr);
            }
            uint32_t bf[2][4];
            #pragma unroll
            for (int nb = 0; nb < 2; nb++) {
                uint32_t addr = stb + TILEB + (uint32_t)(wn * 32 + nb * 16 + b_row) * ROWB
                              + koff + b_byt;
                LDSM4(bf[nb][0], bf[nb][1], bf[nb][2], bf[nb][3], addr);
            }
            #pragma unroll
            for (int mt = 0; mt < 4; mt++)
                #pragma unroll
                for (int nt = 0; nt < 4; nt++)
                    MMAF16(acc[mt][nt],
                           af[mt][0], af[mt][1], af[mt][2], af[mt][3],
                           bf[nt >> 1][(nt & 1) * 2], bf[nt >> 1][(nt & 1) * 2 + 1]);
        }
    }

    int r0 = by * 128 + wm * 64 + (lane >> 2);
    int c0 = bx * 128 + wn * 32 + (lane & 3) * 2;
    #pragma unroll
    for (int mt = 0; mt < 4; mt++) {
        #pragma unroll
        for (int nt = 0; nt < 4; nt++) {
            int r = r0 + mt * 16;
            int c = c0 + nt * 8;
            float2 v0 = { acc[mt][nt][0] + bias[c], acc[mt][nt][1] + bias[c + 1] };
            float2 v1 = { acc[mt][nt][2] + bias[c], acc[mt][nt][3] + bias[c + 1] };
            *(float2*)&C[(size_t)r * Ntot + c] = v0;
            *(float2*)&C[(size_t)(r + 8) * Ntot + c] = v1;
        }
    }
}

// ---------------- merged weight transpose + fp16 convert + bias concat ----------------
__global__ void transpose_split_all(const float* __restrict__ Wq,
                                    const float* __restrict__ Ws,
                                    const float* __restrict__ Wc,
                                    const float* __restrict__ Wp,
                                    const float* __restrict__ bs,
                                    const float* __restrict__ bc)
{
    __shared__ float tile[32][33];
    int bx = blockIdx.x;

    if (bx >= 192) {
        // bias concat: blockIdx.y in [0,24), 256 threads, 3072 elems
        int i = blockIdx.y * 256 + threadIdx.y * 32 + threadIdx.x;
        if (i < 1536) g_bsc[i] = bs[i];
        else if (i < 3072) g_bsc[i] = bc[i - 1536];
        return;
    }

    const float* W; int N, rowOff;
    __half* oT;
    if (bx < 72)       { W = Wq; N = 2304; rowOff = 0;    oT = g_wqkv; }
    else if (bx < 120) { W = Ws; N = 1536; rowOff = 0;    oT = g_wsc;  bx -= 72; }
    else if (bx < 168) { W = Wc; N = 1536; rowOff = 1536; oT = g_wsc;  bx -= 120; }
    else               { W = Wp; N = 768;  rowOff = 0;    oT = g_wpr;  bx -= 168; }

    int n0 = bx * 32, k0 = blockIdx.y * 32;
    int tx = threadIdx.x, ty = threadIdx.y;   // (32, 8)
    #pragma unroll
    for (int i = 0; i < 4; i++)
        tile[ty + i * 8][tx] = W[(size_t)(k0 + ty + i * 8) * N + n0 + tx];
    __syncthreads();
    #pragma unroll
    for (int i = 0; i < 4; i++) {
        int n = ty + i * 8;
        oT[(size_t)(rowOff + n0 + n) * KDIM + k0 + tx] = __float2half(tile[tx][n]);
    }
}

// ---------------- LayerNorm (single-pass sum+sumsq) + fp16 convert ----------------
__global__ void ln_split_kernel(const float* __restrict__ x,
                                const float* __restrict__ gamma,
                                const float* __restrict__ beta) {
    int row = blockIdx.x;
    const float* xr = x + (size_t)row * DMODEL;
    int tid = threadIdx.x;
    __shared__ float red1[8], red2[8];

    float s = 0.f, s2 = 0.f;
    for (int i = tid; i < DMODEL; i += 256) {
        float v = xr[i];
        s += v;
        s2 = fmaf(v, v, s2);
    }
    #pragma unroll
    for (int o = 16; o > 0; o >>= 1) {
        s  += __shfl_down_sync(0xffffffffu, s, o);
        s2 += __shfl_down_sync(0xffffffffu, s2, o);
    }
    if ((tid & 31) == 0) { red1[tid >> 5] = s; red2[tid >> 5] = s2; }
    __syncthreads();
    if (tid < 8) {
        s = red1[tid]; s2 = red2[tid];
        #pragma unroll
        for (int o = 4; o > 0; o >>= 1) {
            s  += __shfl_down_sync(0xffu, s, o);
            s2 += __shfl_down_sync(0xffu, s2, o);
        }
        if (tid == 0) { red1[0] = s; red2[0] = s2; }
    }
    __syncthreads();
    float mu = red1[0] * (1.f / DMODEL);
    float var = red2[0] * (1.f / DMODEL) - mu * mu;
    float inv = rsqrtf(var + LN_EPS);

    for (int i = tid; i < DMODEL; i += 256) {
        float xv = xr[i];
        float ln = (xv - mu) * inv * gamma[i] + beta[i];
        g_a[(size_t)row * DMODEL + i] = __float2half(ln);
        g_x[(size_t)row * DMODEL + i] = __float2half(xv);
    }
}

// ---------------- gate + feature map (MUFU-lean) ----------------
__device__ __forceinline__ float softplus_fast(float x) {
    return (x > 0.f) ? x + __logf(1.f + __expf(-x)) : __logf(1.f + __expf(x));
}

__global__ void features_kernel() {
    int idx = blockIdx.x * blockDim.x + threadIdx.x;
    if (idx >= LSEQ * DMODEL) return;
    int l = idx / DMODEL;
    int d = idx - l * DMODEL;

    const float* scr = g_semctx + (size_t)l * 3072;
    float sa = softplus_fast(scr[d]);
    float sp = scr[768 + d];
    float ca = softplus_fast(scr[1536 + d]);
    float cp = scr[2304 + d];
    float z = sa * ca * __cosf(sp - cp);
    // sigmoid(z) = 0.5*tanh(z/2) + 0.5  (1 MUFU, no division)
    float gate = fmaf(0.5f, tanh_fast(0.5f * z), 0.5f);

    float q = g_qkv[(size_t)l * 3 * DMODEL + d];
    float k = g_qkv[(size_t)l * 3 * DMODEL + DMODEL + d] * gate;
    float v = g_qkv[(size_t)l * 3 * DMODEL + 2 * DMODEL + d];

    int h = d >> 6;
    int dh = d & 63;
    size_t o = (size_t)h * LSEQ * DHEAD + (size_t)l * DHEAD + dh;
    g_qf[o] = (q > 0.f) ? q + 1.f : __expf(q);
    g_kf[o] = (k > 0.f) ? k + 1.f : __expf(k);
    g_vv[o] = v;
}

// ---------------- phase A: per-chunk state sums ----------------
__global__ __launch_bounds__(256)
void chunk_sums_kernel() {
    int h = blockIdx.x / NCHUNK;
    int c = blockIdx.x % NCHUNK;
    const float* Kb = g_kf + (size_t)h * LSEQ * DHEAD + (size_t)c * CSIZE * DHEAD;
    const float* Vb = g_vv + (size_t)h * LSEQ * DHEAD + (size_t)c * CSIZE * DHEAD;

    __shared__ float ks[16][64];
    __shared__ float vs[16][64];
    int tid = threadIdx.x;
    int te = tid & 15;
    int td = tid >> 4;

    float acc[4][4];
    #pragma unroll
    for (int i = 0; i < 4; i++)
        #pragma unroll
        for (int j = 0; j < 4; j++) acc[i][j] = 0.f;
    float zacc[4] = {0.f, 0.f, 0.f, 0.f};

    int lr = tid >> 4;
    int lc = (tid & 15) * 4;

    for (int p0 = 0; p0 < CSIZE; p0 += 16) {
        *(float4*)&ks[lr][lc] = *(const float4*)&Kb[(size_t)(p0 + lr) * DHEAD + lc];
        *(float4*)&vs[lr][lc] = *(const float4*)&Vb[(size_t)(p0 + lr) * DHEAD + lc];
        __syncthreads();
        #pragma unroll
        for (int p = 0; p < 16; p++) {
            float kk[4], vvv[4];
            #pragma unroll
            for (int i = 0; i < 4; i++) kk[i] = ks[p][td * 4 + i];
            #pragma unroll
            for (int j = 0; j < 4; j++) vvv[j] = vs[p][te * 4 + j];
            #pragma unroll
            for (int i = 0; i < 4; i++)
                #pragma unroll
                for (int j = 0; j < 4; j++)
                    acc[i][j] = fmaf(kk[i], vvv[j], acc[i][j]);
            if (te == 0) {
                #pragma unroll
                for (int i = 0; i < 4; i++) zacc[i] += kk[i];
            }
        }
        __syncthreads();
    }

    float* Sb = g_S + (size_t)(h * NCHUNK + c) * DHEAD * DHEAD;
    #pragma unroll
    for (int i = 0; i < 4; i++)
        #pragma unroll
        for (int j = 0; j < 4; j++)
            Sb[(size_t)(td * 4 + i) * DHEAD + te * 4 + j] = acc[i][j];
    if (te == 0) {
        float* Zb = g_Z + (size_t)(h * NCHUNK + c) * DHEAD;
        #pragma unroll
        for (int i = 0; i < 4; i++) Zb[td * 4 + i] = zacc[i];
    }
}

// ---------------- phase B: exclusive scan over chunks (grid (12,4)) ----------------
__global__ __launch_bounds__(256)
void scan_states_kernel() {
    int h = blockIdx.x;
    int part = blockIdx.y;
    int tid = threadIdx.x;
    float pref[4] = {0.f, 0.f, 0.f, 0.f};
    float prefz = 0.f;

    for (int c = 0; c < NCHUNK; c++) {
        float* Sb = g_S + (size_t)(h * NCHUNK + c) * DHEAD * DHEAD + part * 1024;
        #pragma unroll
        for (int i = 0; i < 4; i++) {
            int idx = tid + i * 256;
            float cur = Sb[idx];
            Sb[idx] = pref[i];
            pref[i] += cur;
        }
        if (part == 0 && tid < DHEAD) {
            float* Zb = g_Z + (size_t)(h * NCHUNK + c) * DHEAD;
            float cur = Zb[tid];
            Zb[tid] = prefz;
            prefz += cur;
        }
    }
}

// ---------------- phase C: per-chunk causal output (K,V in smem; P,Z via L1) ----------------
#define SMEM_C (2 * CSIZE * DHEAD * 4)   // 65536 B

__global__ __launch_bounds__(128)
void chunk_attn_kernel() {
    int h = blockIdx.x / NCHUNK;
    int c = blockIdx.x % NCHUNK;
    extern __shared__ float sh[];
    float* Ks = sh;
    float* Vs = Ks + CSIZE * DHEAD;

    int tid = threadIdx.x;
    size_t base = (size_t)h * LSEQ * DHEAD + (size_t)c * CSIZE * DHEAD;

    const float4* Kg = (const float4*)(g_kf + base);
    const float4* Vg = (const float4*)(g_vv + base);
    for (int j = tid; j < CSIZE * DHEAD / 4; j += 128) {
        ((float4*)Ks)[j] = Kg[j];
        ((float4*)Vs)[j] = Vg[j];
    }
    __syncthreads();

    float q[DHEAD];
    {
        const float4* qp = (const float4*)(g_qf + base + (size_t)tid * DHEAD);
        #pragma unroll
        for (int i = 0; i < DHEAD / 4; i++) {
            float4 t = qp[i];
            q[4 * i + 0] = t.x; q[4 * i + 1] = t.y; q[4 * i + 2] = t.z; q[4 * i + 3] = t.w;
        }
    }

    const float* Pg = g_S + (size_t)(h * NCHUNK + c) * DHEAD * DHEAD;
    const float* Zg = g_Z + (size_t)(h * NCHUNK + c) * DHEAD;

    float out[DHEAD];
    float den = 0.f;
    #pragma unroll
    for (int d = 0; d < DHEAD; d++) den = fmaf(q[d], __ldg(&Zg[d]), den);
    #pragma unroll
    for (int e = 0; e < DHEAD; e++) out[e] = 0.f;
    #pragma unroll 4
    for (int d = 0; d < DHEAD; d++) {
        float qd = q[d];
        const float4* pr = (const float4*)(Pg + d * DHEAD);
        #pragma unroll
        for (int i = 0; i < DHEAD / 4; i++) {
            float4 p = __ldg(&pr[i]);
            out[4 * i + 0] = fmaf(qd, p.x, out[4 * i + 0]);
            out[4 * i + 1] = fmaf(qd, p.y, out[4 * i + 1]);
            out[4 * i + 2] = fmaf(qd, p.z, out[4 * i + 2]);
            out[4 * i + 3] = fmaf(qd, p.w, out[4 * i + 3]);
        }
    }

    for (int j = 0; j <= tid; j++) {
        const float4* kr = (const float4*)(Ks + j * DHEAD);
        float s0 = 0.f, s1 = 0.f, s2 = 0.f, s3 = 0.f;
        #pragma unroll
        for (int i = 0; i < DHEAD / 4; i += 4) {
            float4 k0 = kr[i], k1 = kr[i + 1], k2 = kr[i + 2], k3 = kr[i + 3];
            s0 = fmaf(q[4 * i + 0], k0.x, s0); s0 = fmaf(q[4 * i + 1], k0.y, s0);
            s0 = fmaf(q[4 * i + 2], k0.z, s0); s0 = fmaf(q[4 * i + 3], k0.w, s0);
            s1 = fmaf(q[4 * i + 4], k1.x, s1); s1 = fmaf(q[4 * i + 5], k1.y, s1);
            s1 = fmaf(q[4 * i + 6], k1.z, s1); s1 = fmaf(q[4 * i + 7], k1.w, s1);
            s2 = fmaf(q[4 * i + 8], k2.x, s2); s2 = fmaf(q[4 * i + 9], k2.y, s2);
            s2 = fmaf(q[4 * i + 10], k2.z, s2); s2 = fmaf(q[4 * i + 11], k2.w, s2);
            s3 = fmaf(q[4 * i + 12], k3.x, s3); s3 = fmaf(q[4 * i + 13], k3.y, s3);
            s3 = fmaf(q[4 * i + 14], k3.z, s3); s3 = fmaf(q[4 * i + 15], k3.w, s3);
        }
        float s = (s0 + s1) + (s2 + s3);
        den += s;
        const float4* vr = (const float4*)(Vs + j * DHEAD);
        #pragma unroll
        for (int i = 0; i < DHEAD / 4; i++) {
            float4 vv4 = vr[i];
            out[4 * i + 0] = fmaf(s, vv4.x, out[4 * i + 0]);
            out[4 * i + 1] = fmaf(s, vv4.y, out[4 * i + 1]);
            out[4 * i + 2] = fmaf(s, vv4.z, out[4 * i + 2]);
            out[4 * i + 3] = fmaf(s, vv4.w, out[4 * i + 3]);
        }
    }

    float inv = 1.f / (den + DEN_EPS);
    int l = c * CSIZE + tid;
    __half* op = g_at + (size_t)l * DMODEL + h * DHEAD;
    #pragma unroll
    for (int e = 0; e < DHEAD; e += 2) {
        __half2 hv = __floats2half2_rn(out[e] * inv, out[e + 1] * inv);
        *(__half2*)&op[e] = hv;
    }
}

// ---------------- host launcher ----------------
extern "C" void kernel_launch(void* const* d_in, const int* in_sizes, int n_in,
                              void* d_out, int out_size) {
    const float* x      = (const float*)d_in[0];
    const float* W_qkv  = (const float*)d_in[1];
    const float* b_qkv  = (const float*)d_in[2];
    const float* W_sem  = (const float*)d_in[3];
    const float* b_sem  = (const float*)d_in[4];
    const float* W_ctx  = (const float*)d_in[5];
    const float* b_ctx  = (const float*)d_in[6];
    const float* W_proj = (const float*)d_in[7];
    const float* b_proj = (const float*)d_in[8];
    const float* ln_g   = (const float*)d_in[9];
    const float* ln_b   = (const float*)d_in[10];
    float* out = (float*)d_out;

    __half *p_a, *p_x, *p_wq, *p_ws, *p_wp, *p_at;
    float *p_bsc, *p_qkv, *p_semctx;
    cudaGetSymbolAddress((void**)&p_a, g_a);
    cudaGetSymbolAddress((void**)&p_x, g_x);
    cudaGetSymbolAddress((void**)&p_wq, g_wqkv);
    cudaGetSymbolAddress((void**)&p_ws, g_wsc);
    cudaGetSymbolAddress((void**)&p_wp, g_wpr);
    cudaGetSymbolAddress((void**)&p_at, g_at);
    cudaGetSymbolAddress((void**)&p_bsc, g_bsc);
    cudaGetSymbolAddress((void**)&p_qkv, g_qkv);
    cudaGetSymbolAddress((void**)&p_semctx, g_semctx);

    cudaFuncSetAttribute(gemm_mma, cudaFuncAttributeMaxDynamicSharedMemorySize, GEMM_SMEM);
    cudaFuncSetAttribute(chunk_attn_kernel, cudaFuncAttributeMaxDynamicSharedMemorySize, SMEM_C);

    // weight prep (transpose + fp16 + bias concat, single launch) + LN
    transpose_split_all<<<dim3(193, 24), dim3(32, 8)>>>(W_qkv, W_sem, W_ctx, W_proj,
                                                        b_sem, b_ctx);
    ln_split_kernel<<<LSEQ, 256>>>(x, ln_g, ln_b);

    // fp16 tensor-core GEMMs
    gemm_mma<<<dim3(2304 / 128, LSEQ / 128), 256, GEMM_SMEM>>>(p_a, p_wq, b_qkv, p_qkv, 2304);
    gemm_mma<<<dim3(3072 / 128, LSEQ / 128), 256, GEMM_SMEM>>>(p_x, p_ws, p_bsc, p_semctx, 3072);

    // gate + feature map
    features_kernel<<<(LSEQ * DMODEL + 255) / 256, 256>>>();

    // chunked linear attention
    chunk_sums_kernel<<<NHEAD * NCHUNK, 256>>>();
    scan_states_kernel<<<dim3(NHEAD, 4), 256>>>();
    chunk_attn_kernel<<<NHEAD * NCHUNK, 128, SMEM_C>>>();

    // output projection
    gemm_mma<<<dim3(768 / 128, LSEQ / 128), 256, GEMM_SMEM>>>(p_at, p_wp, b_proj, out, 768);
}

// round 12
// speedup vs baseline: 1.5561x; 1.0261x over previous
#include <cuda_runtime.h>
#include <cuda_fp16.h>
#include <math.h>
#include <stdint.h>

// ---------------- problem constants ----------------
#define LSEQ 2048
#define DMODEL 768
#define KDIM 768
#define NHEAD 12
#define DHEAD 64
#define NCHUNK 16
#define CSIZE 128
#define LN_EPS 1e-5f
#define DEN_EPS 1e-6f

// ---------------- scratch (device globals) ----------------
__device__ __align__(128) __half g_a   [LSEQ * DMODEL];   // LN(x) fp16
__device__ __align__(128) __half g_x   [LSEQ * DMODEL];   // x fp16
__device__ __align__(128) __half g_wqkv[2304 * KDIM];     // W_qkv^T fp16
__device__ __align__(128) __half g_wsc [3072 * KDIM];     // [W_sem;W_ctx]^T fp16
__device__ __align__(128) __half g_wpr [768 * KDIM];      // W_proj^T fp16
__device__ __align__(128) __half g_at  [LSEQ * DMODEL];   // attn out fp16
__device__ __align__(128) float g_bsc[3072];
__device__ __align__(128) float g_qkv[LSEQ * 3 * DMODEL];
__device__ __align__(128) float g_semctx[LSEQ * 3072];
__device__ float g_qf[NHEAD * LSEQ * DHEAD];
__device__ float g_kf[NHEAD * LSEQ * DHEAD];
__device__ float g_vv[NHEAD * LSEQ * DHEAD];
__device__ float g_S [NHEAD * NCHUNK * DHEAD * DHEAD];
__device__ float g_Z [NHEAD * NCHUNK * DHEAD];

// ---------------- PTX helpers (family-portable only) ----------------
__device__ __forceinline__ uint32_t smem_u32(const void* p) {
    uint32_t a;
    asm("{ .reg .u64 t; cvta.to.shared.u64 t, %1; cvt.u32.u64 %0, t; }" : "=r"(a) : "l"(p));
    return a;
}
__device__ __forceinline__ void cp_async16(uint32_t dst, const void* src) {
    asm volatile("cp.async.cg.shared.global [%0], [%1], 16;" :: "r"(dst), "l"(src));
}
__device__ __forceinline__ void cp_commit() {
    asm volatile("cp.async.commit_group;" ::: "memory");
}
__device__ __forceinline__ void cp_wait1() {
    asm volatile("cp.async.wait_group 1;" ::: "memory");
}
__device__ __forceinline__ float tanh_fast(float x) {
    float y;
    asm("tanh.approx.f32 %0, %1;" : "=f"(y) : "f"(x));
    return y;
}
#define LDSM4(r0, r1, r2, r3, a) \
    asm volatile("ldmatrix.sync.aligned.m8n8.x4.shared.b16 {%0,%1,%2,%3}, [%4];" \
                 : "=r"(r0), "=r"(r1), "=r"(r2), "=r"(r3) : "r"(a))
#define MMAF16(d, a0, a1, a2, a3, b0, b1) \
    asm volatile("mma.sync.aligned.m16n8k16.row.col.f32.f16.f16.f32 " \
                 "{%0,%1,%2,%3}, {%4,%5,%6,%7}, {%8,%9}, {%0,%1,%2,%3};" \
                 : "+f"((d)[0]), "+f"((d)[1]), "+f"((d)[2]), "+f"((d)[3]) \
                 : "r"(a0), "r"(a1), "r"(a2), "r"(a3), "r"(b0), "r"(b1))

// ---------------- GEMM: C[2048,Ntot] = A @ B^T + bias (fp16, BK=64) ----------------
#define BK 64
#define ROWB 144                      // 128 B data + 16 B pad -> conflict-free ldmatrix
#define TILEB (128 * ROWB)            // 18432 B per 128x64 tile
#define STAGEB (2 * TILEB)            // A, B
#define NSTAGE 3
#define GEMM_SMEM (NSTAGE * STAGEB)   // 110592 B -> 2 CTAs/SM
#define NKT (KDIM / BK)               // 12

__device__ __forceinline__ void g_load_stage(
    uint32_t smem_base, int s, int tid,
    const __half* a, const __half* b)
{
    uint32_t stb = smem_base + (uint32_t)(s % NSTAGE) * STAGEB;
    int kk = s * BK;
    #pragma unroll
    for (int t = 0; t < 2; t++) {
        const __half* base = t ? b : a;
        #pragma unroll
        for (int i = 0; i < 4; i++) {
            int c = tid + i * 256;          // 0..1023
            int r = c >> 3;                 // 0..127
            int seg = c & 7;                // 0..7 (8 x 16B = 128B row)
            cp_async16(stb + (uint32_t)t * TILEB + (uint32_t)(r * ROWB + seg * 16),
                       base + (size_t)r * KDIM + kk + seg * 8);
        }
    }
}

__global__ __launch_bounds__(256, 2)
void gemm_mma(const __half* __restrict__ A, const __half* __restrict__ BT,
              const float* __restrict__ bias, float* __restrict__ C, int Ntot)
{
    extern __shared__ __align__(128) char smem[];
    const int tid = threadIdx.x;
    const int wid = tid >> 5;
    const int lane = tid & 31;
    const int wm = wid & 1;        // M: 2 x 64
    const int wn = wid >> 1;       // N: 4 x 32
    const int bx = blockIdx.x, by = blockIdx.y;

    uint32_t smem_base = smem_u32(smem);

    const __half* a = A + (size_t)by * 128 * KDIM;
    const __half* b = BT + (size_t)bx * 128 * KDIM;

    float acc[4][4][4];
    #pragma unroll
    for (int i = 0; i < 4; i++)
        #pragma unroll
        for (int j = 0; j < 4; j++)
            #pragma unroll
            for (int t = 0; t < 4; t++) acc[i][j][t] = 0.f;

    const uint32_t a_row = (uint32_t)(lane & 15);
    const uint32_t a_byt = (uint32_t)((lane >> 4) * 16);
    const uint32_t b_row = (uint32_t)((lane & 7) + ((lane >> 4) << 3));
    const uint32_t b_byt = (uint32_t)(((lane >> 3) & 1) * 16);

    // prologue: 2 stages in flight
    g_load_stage(smem_base, 0, tid, a, b); cp_commit();
    g_load_stage(smem_base, 1, tid, a, b); cp_commit();

    for (int s = 0; s < NKT; s++) {
        cp_wait1();                 // group s retired
        __syncthreads();
        if (s + 2 < NKT) g_load_stage(smem_base, s + 2, tid, a, b);
        cp_commit();

        uint32_t stb = smem_base + (uint32_t)(s % NSTAGE) * STAGEB;
        #pragma unroll
        for (int k16 = 0; k16 < 4; k16++) {
            const uint32_t koff = (uint32_t)(k16 * 32);
            uint32_t af[4][4];
            #pragma unroll
            for (int mt = 0; mt < 4; mt++) {
                uint32_t addr = stb + (uint32_t)(wm * 64 + mt * 16 + a_row) * ROWB
                              + koff + a_byt;
                LDSM4(af[mt][0], af[mt][1], af[mt][2], af[mt][3], addr);
            }
            uint32_t bf[2][4];
            #pragma unroll
            for (int nb = 0; nb < 2; nb++) {
                uint32_t addr = stb + TILEB + (uint32_t)(wn * 32 + nb * 16 + b_row) * ROWB
                              + koff + b_byt;
                LDSM4(bf[nb][0], bf[nb][1], bf[nb][2], bf[nb][3], addr);
            }
            #pragma unroll
            for (int mt = 0; mt < 4; mt++)
                #pragma unroll
                for (int nt = 0; nt < 4; nt++)
                    MMAF16(acc[mt][nt],
                           af[mt][0], af[mt][1], af[mt][2], af[mt][3],
                           bf[nt >> 1][(nt & 1) * 2], bf[nt >> 1][(nt & 1) * 2 + 1]);
        }
    }

    int r0 = by * 128 + wm * 64 + (lane >> 2);
    int c0 = bx * 128 + wn * 32 + (lane & 3) * 2;
    #pragma unroll
    for (int mt = 0; mt < 4; mt++) {
        #pragma unroll
        for (int nt = 0; nt < 4; nt++) {
            int r = r0 + mt * 16;
            int c = c0 + nt * 8;
            float2 v0 = { acc[mt][nt][0] + bias[c], acc[mt][nt][1] + bias[c + 1] };
            float2 v1 = { acc[mt][nt][2] + bias[c], acc[mt][nt][3] + bias[c + 1] };
            *(float2*)&C[(size_t)r * Ntot + c] = v0;
            *(float2*)&C[(size_t)(r + 8) * Ntot + c] = v1;
        }
    }
}

// ---------------- prep: weight transpose + fp16, bias concat, LN (one launch) ----------------
// bx in [0,192): weight transpose; bx == 192: bias concat; bx in [193,279): LN rows
__global__ void prep_kernel(const float* __restrict__ Wq,
                            const float* __restrict__ Ws,
                            const float* __restrict__ Wc,
                            const float* __restrict__ Wp,
                            const float* __restrict__ bs,
                            const float* __restrict__ bc,
                            const float* __restrict__ x,
                            const float* __restrict__ gamma,
                            const float* __restrict__ beta)
{
    __shared__ float tile[32][33];
    __shared__ float red1[8], red2[8];
    int bx = blockIdx.x;
    int tid = threadIdx.y * 32 + threadIdx.x;

    if (bx == 192) {
        int i = blockIdx.y * 128 + tid;  // 24*128 = 3072
        if (i < 1536) g_bsc[i] = bs[i];
        else if (i < 3072) g_bsc[i] = bc[i - 1536];
        return;
    }
    if (bx >= 193) {
        // LayerNorm: row = (bx-193)*24 + by, rows 0..2047 (86*24 = 2064 >= 2048)
        int row = (bx - 193) * 24 + blockIdx.y;
        if (row >= LSEQ) return;
        const float* xr = x + (size_t)row * DMODEL;

        float s = 0.f, s2 = 0.f;
        for (int i = tid; i < DMODEL; i += 256) {
            float v = xr[i];
            s += v;
            s2 = fmaf(v, v, s2);
        }
        #pragma unroll
        for (int o = 16; o > 0; o >>= 1) {
            s  += __shfl_down_sync(0xffffffffu, s, o);
            s2 += __shfl_down_sync(0xffffffffu, s2, o);
        }
        if ((tid & 31) == 0) { red1[tid >> 5] = s; red2[tid >> 5] = s2; }
        __syncthreads();
        if (tid < 8) {
            s = red1[tid]; s2 = red2[tid];
            #pragma unroll
            for (int o = 4; o > 0; o >>= 1) {
                s  += __shfl_down_sync(0xffu, s, o);
                s2 += __shfl_down_sync(0xffu, s2, o);
            }
            if (tid == 0) { red1[0] = s; red2[0] = s2; }
        }
        __syncthreads();
        float mu = red1[0] * (1.f / DMODEL);
        float var = red2[0] * (1.f / DMODEL) - mu * mu;
        float inv = rsqrtf(var + LN_EPS);

        for (int i = tid; i < DMODEL; i += 256) {
            float xv = xr[i];
            float ln = (xv - mu) * inv * gamma[i] + beta[i];
            g_a[(size_t)row * DMODEL + i] = __float2half(ln);
            g_x[(size_t)row * DMODEL + i] = __float2half(xv);
        }
        return;
    }

    // weight transpose + fp16
    const float* W; int N, rowOff;
    __half* oT;
    if (bx < 72)       { W = Wq; N = 2304; rowOff = 0;    oT = g_wqkv; }
    else if (bx < 120) { W = Ws; N = 1536; rowOff = 0;    oT = g_wsc;  bx -= 72; }
    else if (bx < 168) { W = Wc; N = 1536; rowOff = 1536; oT = g_wsc;  bx -= 120; }
    else               { W = Wp; N = 768;  rowOff = 0;    oT = g_wpr;  bx -= 168; }

    int n0 = bx * 32, k0 = blockIdx.y * 32;
    int tx = threadIdx.x, ty = threadIdx.y;   // (32, 8)
    #pragma unroll
    for (int i = 0; i < 4; i++)
        tile[ty + i * 8][tx] = W[(size_t)(k0 + ty + i * 8) * N + n0 + tx];
    __syncthreads();
    #pragma unroll
    for (int i = 0; i < 4; i++) {
        int n = ty + i * 8;
        oT[(size_t)(rowOff + n0 + n) * KDIM + k0 + tx] = __float2half(tile[tx][n]);
    }
}

// ---------------- gate + feature map (vectorized x4, branchless softplus) ----------------
__device__ __forceinline__ float softplus_nb(float x) {
    // |x| <= ~10 here -> no overflow; branchless
    return __logf(1.f + __expf(x));
}
__device__ __forceinline__ float elu1(float x) {
    return (x > 0.f) ? x + 1.f : __expf(x);
}

__global__ void features_kernel() {
    int idx4 = blockIdx.x * blockDim.x + threadIdx.x;   // 393216 threads
    if (idx4 >= LSEQ * DMODEL / 4) return;
    int l = idx4 / (DMODEL / 4);
    int d = (idx4 - l * (DMODEL / 4)) * 4;

    const float* scr = g_semctx + (size_t)l * 3072;
    float4 sa4 = *(const float4*)(scr + d);
    float4 sp4 = *(const float4*)(scr + 768 + d);
    float4 ca4 = *(const float4*)(scr + 1536 + d);
    float4 cp4 = *(const float4*)(scr + 2304 + d);

    const float* qr = g_qkv + (size_t)l * 2304;
    float4 q4 = *(const float4*)(qr + d);
    float4 k4 = *(const float4*)(qr + 768 + d);
    float4 v4 = *(const float4*)(qr + 1536 + d);

    float4 qf4, kf4;
    {
        float z, gate;
        z = softplus_nb(sa4.x) * softplus_nb(ca4.x) * __cosf(sp4.x - cp4.x);
        gate = fmaf(0.5f, tanh_fast(0.5f * z), 0.5f);
        qf4.x = elu1(q4.x); kf4.x = elu1(k4.x * gate);
        z = softplus_nb(sa4.y) * softplus_nb(ca4.y) * __cosf(sp4.y - cp4.y);
        gate = fmaf(0.5f, tanh_fast(0.5f * z), 0.5f);
        qf4.y = elu1(q4.y); kf4.y = elu1(k4.y * gate);
        z = softplus_nb(sa4.z) * softplus_nb(ca4.z) * __cosf(sp4.z - cp4.z);
        gate = fmaf(0.5f, tanh_fast(0.5f * z), 0.5f);
        qf4.z = elu1(q4.z); kf4.z = elu1(k4.z * gate);
        z = softplus_nb(sa4.w) * softplus_nb(ca4.w) * __cosf(sp4.w - cp4.w);
        gate = fmaf(0.5f, tanh_fast(0.5f * z), 0.5f);
        qf4.w = elu1(q4.w); kf4.w = elu1(k4.w * gate);
    }

    int h = d >> 6;
    int dh = d & 63;
    size_t o = (size_t)h * LSEQ * DHEAD + (size_t)l * DHEAD + dh;
    *(float4*)&g_qf[o] = qf4;
    *(float4*)&g_kf[o] = kf4;
    *(float4*)&g_vv[o] = v4;
}

// ---------------- phase A: per-chunk state sums ----------------
__global__ __launch_bounds__(256)
void chunk_sums_kernel() {
    int h = blockIdx.x / NCHUNK;
    int c = blockIdx.x % NCHUNK;
    const float* Kb = g_kf + (size_t)h * LSEQ * DHEAD + (size_t)c * CSIZE * DHEAD;
    const float* Vb = g_vv + (size_t)h * LSEQ * DHEAD + (size_t)c * CSIZE * DHEAD;

    __shared__ float ks[16][64];
    __shared__ float vs[16][64];
    int tid = threadIdx.x;
    int te = tid & 15;
    int td = tid >> 4;

    float acc[4][4];
    #pragma unroll
    for (int i = 0; i < 4; i++)
        #pragma unroll
        for (int j = 0; j < 4; j++) acc[i][j] = 0.f;
    float zacc[4] = {0.f, 0.f, 0.f, 0.f};

    int lr = tid >> 4;
    int lc = (tid & 15) * 4;

    for (int p0 = 0; p0 < CSIZE; p0 += 16) {
        *(float4*)&ks[lr][lc] = *(const float4*)&Kb[(size_t)(p0 + lr) * DHEAD + lc];
        *(float4*)&vs[lr][lc] = *(const float4*)&Vb[(size_t)(p0 + lr) * DHEAD + lc];
        __syncthreads();
        #pragma unroll
        for (int p = 0; p < 16; p++) {
            float kk[4], vvv[4];
            #pragma unroll
            for (int i = 0; i < 4; i++) kk[i] = ks[p][td * 4 + i];
            #pragma unroll
            for (int j = 0; j < 4; j++) vvv[j] = vs[p][te * 4 + j];
            #pragma unroll
            for (int i = 0; i < 4; i++)
                #pragma unroll
                for (int j = 0; j < 4; j++)
                    acc[i][j] = fmaf(kk[i], vvv[j], acc[i][j]);
            if (te == 0) {
                #pragma unroll
                for (int i = 0; i < 4; i++) zacc[i] += kk[i];
            }
        }
        __syncthreads();
    }

    float* Sb = g_S + (size_t)(h * NCHUNK + c) * DHEAD * DHEAD;
    #pragma unroll
    for (int i = 0; i < 4; i++)
        #pragma unroll
        for (int j = 0; j < 4; j++)
            Sb[(size_t)(td * 4 + i) * DHEAD + te * 4 + j] = acc[i][j];
    if (te == 0) {
        float* Zb = g_Z + (size_t)(h * NCHUNK + c) * DHEAD;
        #pragma unroll
        for (int i = 0; i < 4; i++) Zb[td * 4 + i] = zacc[i];
    }
}

// ---------------- phase B: exclusive scan over chunks (grid (12,4)) ----------------
__global__ __launch_bounds__(256)
void scan_states_kernel() {
    int h = blockIdx.x;
    int part = blockIdx.y;
    int tid = threadIdx.x;
    float pref[4] = {0.f, 0.f, 0.f, 0.f};
    float prefz = 0.f;

    for (int c = 0; c < NCHUNK; c++) {
        float* Sb = g_S + (size_t)(h * NCHUNK + c) * DHEAD * DHEAD + part * 1024;
        #pragma unroll
        for (int i = 0; i < 4; i++) {
            int idx = tid + i * 256;
            float cur = Sb[idx];
            Sb[idx] = pref[i];
            pref[i] += cur;
        }
        if (part == 0 && tid < DHEAD) {
            float* Zb = g_Z + (size_t)(h * NCHUNK + c) * DHEAD;
            float cur = Zb[tid];
            Zb[tid] = prefz;
            prefz += cur;
        }
    }
}

// ---------------- phase C: per-chunk causal output (K,V in smem; P,Z via L1) ----------------
#define SMEM_C (2 * CSIZE * DHEAD * 4)   // 65536 B

__global__ __launch_bounds__(128)
void chunk_attn_kernel() {
    int h = blockIdx.x / NCHUNK;
    int c = blockIdx.x % NCHUNK;
    extern __shared__ float sh[];
    float* Ks = sh;
    float* Vs = Ks + CSIZE * DHEAD;

    int tid = threadIdx.x;
    size_t base = (size_t)h * LSEQ * DHEAD + (size_t)c * CSIZE * DHEAD;

    const float4* Kg = (const float4*)(g_kf + base);
    const float4* Vg = (const float4*)(g_vv + base);
    for (int j = tid; j < CSIZE * DHEAD / 4; j += 128) {
        ((float4*)Ks)[j] = Kg[j];
        ((float4*)Vs)[j] = Vg[j];
    }
    __syncthreads();

    float q[DHEAD];
    {
        const float4* qp = (const float4*)(g_qf + base + (size_t)tid * DHEAD);
        #pragma unroll
        for (int i = 0; i < DHEAD / 4; i++) {
            float4 t = qp[i];
            q[4 * i + 0] = t.x; q[4 * i + 1] = t.y; q[4 * i + 2] = t.z; q[4 * i + 3] = t.w;
        }
    }

    const float* Pg = g_S + (size_t)(h * NCHUNK + c) * DHEAD * DHEAD;
    const float* Zg = g_Z + (size_t)(h * NCHUNK + c) * DHEAD;

    float out[DHEAD];
    float den = 0.f;
    #pragma unroll
    for (int d = 0; d < DHEAD; d++) den = fmaf(q[d], __ldg(&Zg[d]), den);
    #pragma unroll
    for (int e = 0; e < DHEAD; e++) out[e] = 0.f;
    #pragma unroll 4
    for (int d = 0; d < DHEAD; d++) {
        float qd = q[d];
        const float4* pr = (const float4*)(Pg + d * DHEAD);
        #pragma unroll
        for (int i = 0; i < DHEAD / 4; i++) {
            float4 p = __ldg(&pr[i]);
            out[4 * i + 0] = fmaf(qd, p.x, out[4 * i + 0]);
            out[4 * i + 1] = fmaf(qd, p.y, out[4 * i + 1]);
            out[4 * i + 2] = fmaf(qd, p.z, out[4 * i + 2]);
            out[4 * i + 3] = fmaf(qd, p.w, out[4 * i + 3]);
        }
    }

    for (int j = 0; j <= tid; j++) {
        const float4* kr = (const float4*)(Ks + j * DHEAD);
        float s0 = 0.f, s1 = 0.f, s2 = 0.f, s3 = 0.f;
        #pragma unroll
        for (int i = 0; i < DHEAD / 4; i += 4) {
            float4 k0 = kr[i], k1 = kr[i + 1], k2 = kr[i + 2], k3 = kr[i + 3];
            s0 = fmaf(q[4 * i + 0], k0.x, s0); s0 = fmaf(q[4 * i + 1], k0.y, s0);
            s0 = fmaf(q[4 * i + 2], k0.z, s0); s0 = fmaf(q[4 * i + 3], k0.w, s0);
            s1 = fmaf(q[4 * i + 4], k1.x, s1); s1 = fmaf(q[4 * i + 5], k1.y, s1);
            s1 = fmaf(q[4 * i + 6], k1.z, s1); s1 = fmaf(q[4 * i + 7], k1.w, s1);
            s2 = fmaf(q[4 * i + 8], k2.x, s2); s2 = fmaf(q[4 * i + 9], k2.y, s2);
            s2 = fmaf(q[4 * i + 10], k2.z, s2); s2 = fmaf(q[4 * i + 11], k2.w, s2);
            s3 = fmaf(q[4 * i + 12], k3.x, s3); s3 = fmaf(q[4 * i + 13], k3.y, s3);
            s3 = fmaf(q[4 * i + 14], k3.z, s3); s3 = fmaf(q[4 * i + 15], k3.w, s3);
        }
        float s = (s0 + s1) + (s2 + s3);
        den += s;
        const float4* vr = (const float4*)(Vs + j * DHEAD);
        #pragma unroll
        for (int i = 0; i < DHEAD / 4; i++) {
            float4 vv4 = vr[i];
            out[4 * i + 0] = fmaf(s, vv4.x, out[4 * i + 0]);
            out[4 * i + 1] = fmaf(s, vv4.y, out[4 * i + 1]);
            out[4 * i + 2] = fmaf(s, vv4.z, out[4 * i + 2]);
            out[4 * i + 3] = fmaf(s, vv4.w, out[4 * i + 3]);
        }
    }

    float inv = 1.f / (den + DEN_EPS);
    int l = c * CSIZE + tid;
    __half* op = g_at + (size_t)l * DMODEL + h * DHEAD;
    #pragma unroll
    for (int e = 0; e < DHEAD; e += 2) {
        __half2 hv = __floats2half2_rn(out[e] * inv, out[e + 1] * inv);
        *(__half2*)&op[e] = hv;
    }
}

// ---------------- host launcher ----------------
extern "C" void kernel_launch(void* const* d_in, const int* in_sizes, int n_in,
                              void* d_out, int out_size) {
    const float* x      = (const float*)d_in[0];
    const float* W_qkv  = (const float*)d_in[1];
    const float* b_qkv  = (const float*)d_in[2];
    const float* W_sem  = (const float*)d_in[3];
    const float* b_sem  = (const float*)d_in[4];
    const float* W_ctx  = (const float*)d_in[5];
    const float* b_ctx  = (const float*)d_in[6];
    const float* W_proj = (const float*)d_in[7];
    const float* b_proj = (const float*)d_in[8];
    const float* ln_g   = (const float*)d_in[9];
    const float* ln_b   = (const float*)d_in[10];
    float* out = (float*)d_out;

    __half *p_a, *p_x, *p_wq, *p_ws, *p_wp, *p_at;
    float *p_bsc, *p_qkv, *p_semctx;
    cudaGetSymbolAddress((void**)&p_a, g_a);
    cudaGetSymbolAddress((void**)&p_x, g_x);
    cudaGetSymbolAddress((void**)&p_wq, g_wqkv);
    cudaGetSymbolAddress((void**)&p_ws, g_wsc);
    cudaGetSymbolAddress((void**)&p_wp, g_wpr);
    cudaGetSymbolAddress((void**)&p_at, g_at);
    cudaGetSymbolAddress((void**)&p_bsc, g_bsc);
    cudaGetSymbolAddress((void**)&p_qkv, g_qkv);
    cudaGetSymbolAddress((void**)&p_semctx, g_semctx);

    cudaFuncSetAttribute(gemm_mma, cudaFuncAttributeMaxDynamicSharedMemorySize, GEMM_SMEM);
    cudaFuncSetAttribute(chunk_attn_kernel, cudaFuncAttributeMaxDynamicSharedMemorySize, SMEM_C);

    // prep: transpose + fp16 + bias concat + LN (single launch)
    prep_kernel<<<dim3(279, 24), dim3(32, 8)>>>(W_qkv, W_sem, W_ctx, W_proj,
                                                b_sem, b_ctx, x, ln_g, ln_b);

    // fp16 tensor-core GEMMs
    gemm_mma<<<dim3(2304 / 128, LSEQ / 128), 256, GEMM_SMEM>>>(p_a, p_wq, b_qkv, p_qkv, 2304);
    gemm_mma<<<dim3(3072 / 128, LSEQ / 128), 256, GEMM_SMEM>>>(p_x, p_ws, p_bsc, p_semctx, 3072);

    // gate + feature map (x4 vectorized)
    features_kernel<<<(LSEQ * DMODEL / 4 + 255) / 256, 256>>>();

    // chunked linear attention
    chunk_sums_kernel<<<NHEAD * NCHUNK, 256>>>();
    scan_states_kernel<<<dim3(NHEAD, 4), 256>>>();
    chunk_attn_kernel<<<NHEAD * NCHUNK, 128, SMEM_C>>>();

    // output projection
    gemm_mma<<<dim3(768 / 128, LSEQ / 128), 256, GEMM_SMEM>>>(p_at, p_wp, b_proj, out, 768);
}

// round 13
// speedup vs baseline: 1.5752x; 1.0123x over previous
#include <cuda_runtime.h>
#include <cuda_fp16.h>
#include <math.h>
#include <stdint.h>

// ---------------- problem constants ----------------
#define LSEQ 2048
#define DMODEL 768
#define KDIM 768
#define NHEAD 12
#define DHEAD 64
#define NCHUNK 16
#define CSIZE 128
#define LN_EPS 1e-5f
#define DEN_EPS 1e-6f

// ---------------- scratch (device globals) ----------------
__device__ __align__(128) __half g_a   [LSEQ * DMODEL];   // LN(x) fp16
__device__ __align__(128) __half g_x   [LSEQ * DMODEL];   // x fp16
__device__ __align__(128) __half g_wqkv[2304 * KDIM];     // W_qkv^T fp16
__device__ __align__(128) __half g_wsc [3072 * KDIM];     // [W_sem;W_ctx]^T fp16
__device__ __align__(128) __half g_wpr [768 * KDIM];      // W_proj^T fp16
__device__ __align__(128) __half g_at  [LSEQ * DMODEL];   // attn out fp16
__device__ __align__(128) float g_bsc[3072];
__device__ __align__(128) __half g_qkvh  [LSEQ * 3 * DMODEL];  // qkv GEMM out fp16
__device__ __align__(128) __half g_semh  [LSEQ * 3072];        // sem/ctx GEMM out fp16
__device__ float g_qf[NHEAD * LSEQ * DHEAD];
__device__ float g_kf[NHEAD * LSEQ * DHEAD];
__device__ float g_vv[NHEAD * LSEQ * DHEAD];
__device__ float g_S [NHEAD * NCHUNK * DHEAD * DHEAD];
__device__ float g_Z [NHEAD * NCHUNK * DHEAD];

// ---------------- PTX helpers (family-portable only) ----------------
__device__ __forceinline__ uint32_t smem_u32(const void* p) {
    uint32_t a;
    asm("{ .reg .u64 t; cvta.to.shared.u64 t, %1; cvt.u32.u64 %0, t; }" : "=r"(a) : "l"(p));
    return a;
}
__device__ __forceinline__ void cp_async16(uint32_t dst, const void* src) {
    asm volatile("cp.async.cg.shared.global [%0], [%1], 16;" :: "r"(dst), "l"(src));
}
__device__ __forceinline__ void cp_commit() {
    asm volatile("cp.async.commit_group;" ::: "memory");
}
__device__ __forceinline__ void cp_wait1() {
    asm volatile("cp.async.wait_group 1;" ::: "memory");
}
__device__ __forceinline__ float tanh_fast(float x) {
    float y;
    asm("tanh.approx.f32 %0, %1;" : "=f"(y) : "f"(x));
    return y;
}
__device__ __forceinline__ float4 ld4h(const __half* p) {
    uint2 u = *(const uint2*)p;
    float2 fa = __half22float2(*(__half2*)&u.x);
    float2 fb = __half22float2(*(__half2*)&u.y);
    return make_float4(fa.x, fa.y, fb.x, fb.y);
}
#define LDSM4(r0, r1, r2, r3, a) \
    asm volatile("ldmatrix.sync.aligned.m8n8.x4.shared.b16 {%0,%1,%2,%3}, [%4];" \
                 : "=r"(r0), "=r"(r1), "=r"(r2), "=r"(r3) : "r"(a))
#define MMAF16(d, a0, a1, a2, a3, b0, b1) \
    asm volatile("mma.sync.aligned.m16n8k16.row.col.f32.f16.f16.f32 " \
                 "{%0,%1,%2,%3}, {%4,%5,%6,%7}, {%8,%9}, {%0,%1,%2,%3};" \
                 : "+f"((d)[0]), "+f"((d)[1]), "+f"((d)[2]), "+f"((d)[3]) \
                 : "r"(a0), "r"(a1), "r"(a2), "r"(a3), "r"(b0), "r"(b1))

// ---------------- GEMM: C[2048,Ntot] = A @ B^T + bias (fp16, BK=64) ----------------
#define BK 64
#define ROWB 144
#define TILEB (128 * ROWB)
#define STAGEB (2 * TILEB)
#define NSTAGE 3
#define GEMM_SMEM (NSTAGE * STAGEB)   // 110592 B -> 2 CTAs/SM
#define NKT (KDIM / BK)               // 12

__device__ __forceinline__ void g_load_stage(
    uint32_t smem_base, int s, int tid,
    const __half* a, const __half* b)
{
    uint32_t stb = smem_base + (uint32_t)(s % NSTAGE) * STAGEB;
    int kk = s * BK;
    #pragma unroll
    for (int t = 0; t < 2; t++) {
        const __half* base = t ? b : a;
        #pragma unroll
        for (int i = 0; i < 4; i++) {
            int c = tid + i * 256;
            int r = c >> 3;
            int seg = c & 7;
            cp_async16(stb + (uint32_t)t * TILEB + (uint32_t)(r * ROWB + seg * 16),
                       base + (size_t)r * KDIM + kk + seg * 8);
        }
    }
}

// OUTH=1: store fp16; OUTH=0: store fp32
template<int OUTH>
__global__ __launch_bounds__(256, 2)
void gemm_mma(const __half* __restrict__ A, const __half* __restrict__ BT,
              const float* __restrict__ bias, void* __restrict__ Cv, int Ntot)
{
    extern __shared__ __align__(128) char smem[];
    const int tid = threadIdx.x;
    const int wid = tid >> 5;
    const int lane = tid & 31;
    const int wm = wid & 1;
    const int wn = wid >> 1;
    const int bx = blockIdx.x, by = blockIdx.y;

    uint32_t smem_base = smem_u32(smem);

    const __half* a = A + (size_t)by * 128 * KDIM;
    const __half* b = BT + (size_t)bx * 128 * KDIM;

    float acc[4][4][4];
    #pragma unroll
    for (int i = 0; i < 4; i++)
        #pragma unroll
        for (int j = 0; j < 4; j++)
            #pragma unroll
            for (int t = 0; t < 4; t++) acc[i][j][t] = 0.f;

    const uint32_t a_row = (uint32_t)(lane & 15);
    const uint32_t a_byt = (uint32_t)((lane >> 4) * 16);
    const uint32_t b_row = (uint32_t)((lane & 7) + ((lane >> 4) << 3));
    const uint32_t b_byt = (uint32_t)(((lane >> 3) & 1) * 16);

    g_load_stage(smem_base, 0, tid, a, b); cp_commit();
    g_load_stage(smem_base, 1, tid, a, b); cp_commit();

    for (int s = 0; s < NKT; s++) {
        cp_wait1();
        __syncthreads();
        if (s + 2 < NKT) g_load_stage(smem_base, s + 2, tid, a, b);
        cp_commit();

        uint32_t stb = smem_base + (uint32_t)(s % NSTAGE) * STAGEB;
        #pragma unroll
        for (int k16 = 0; k16 < 4; k16++) {
            const uint32_t koff = (uint32_t)(k16 * 32);
            uint32_t af[4][4];
            #pragma unroll
            for (int mt = 0; mt < 4; mt++) {
                uint32_t addr = stb + (uint32_t)(wm * 64 + mt * 16 + a_row) * ROWB
                              + koff + a_byt;
                LDSM4(af[mt][0], af[mt][1], af[mt][2], af[mt][3], addr);
            }
            uint32_t bf[2][4];
            #pragma unroll
            for (int nb = 0; nb < 2; nb++) {
                uint32_t addr = stb + TILEB + (uint32_t)(wn * 32 + nb * 16 + b_row) * ROWB
                              + koff + b_byt;
                LDSM4(bf[nb][0], bf[nb][1], bf[nb][2], bf[nb][3], addr);
            }
            #pragma unroll
            for (int mt = 0; mt < 4; mt++)
                #pragma unroll
                for (int nt = 0; nt < 4; nt++)
                    MMAF16(acc[mt][nt],
                           af[mt][0], af[mt][1], af[mt][2], af[mt][3],
                           bf[nt >> 1][(nt & 1) * 2], bf[nt >> 1][(nt & 1) * 2 + 1]);
        }
    }

    int r0 = by * 128 + wm * 64 + (lane >> 2);
    int c0 = bx * 128 + wn * 32 + (lane & 3) * 2;
    #pragma unroll
    for (int mt = 0; mt < 4; mt++) {
        #pragma unroll
        for (int nt = 0; nt < 4; nt++) {
            int r = r0 + mt * 16;
            int c = c0 + nt * 8;
            float b0 = bias[c], b1 = bias[c + 1];
            if (OUTH) {
                __half* C = (__half*)Cv;
                *(__half2*)&C[(size_t)r * Ntot + c] =
                    __floats2half2_rn(acc[mt][nt][0] + b0, acc[mt][nt][1] + b1);
                *(__half2*)&C[(size_t)(r + 8) * Ntot + c] =
                    __floats2half2_rn(acc[mt][nt][2] + b0, acc[mt][nt][3] + b1);
            } else {
                float* C = (float*)Cv;
                float2 v0 = { acc[mt][nt][0] + b0, acc[mt][nt][1] + b1 };
                float2 v1 = { acc[mt][nt][2] + b0, acc[mt][nt][3] + b1 };
                *(float2*)&C[(size_t)r * Ntot + c] = v0;
                *(float2*)&C[(size_t)(r + 8) * Ntot + c] = v1;
            }
        }
    }
}

// ---------------- prep: weight transpose + fp16, bias concat, LN (one launch) ----------------
__global__ void prep_kernel(const float* __restrict__ Wq,
                            const float* __restrict__ Ws,
                            const float* __restrict__ Wc,
                            const float* __restrict__ Wp,
                            const float* __restrict__ bs,
                            const float* __restrict__ bc,
                            const float* __restrict__ x,
                            const float* __restrict__ gamma,
                            const float* __restrict__ beta)
{
    __shared__ float tile[32][33];
    __shared__ float red1[8], red2[8];
    int bx = blockIdx.x;
    int tid = threadIdx.y * 32 + threadIdx.x;

    if (bx == 192) {
        int i = blockIdx.y * 128 + tid;
        if (i < 1536) g_bsc[i] = bs[i];
        else if (i < 3072) g_bsc[i] = bc[i - 1536];
        return;
    }
    if (bx >= 193) {
        int row = (bx - 193) * 24 + blockIdx.y;
        if (row >= LSEQ) return;
        const float* xr = x + (size_t)row * DMODEL;

        float s = 0.f, s2 = 0.f;
        for (int i = tid; i < DMODEL; i += 256) {
            float v = xr[i];
            s += v;
            s2 = fmaf(v, v, s2);
        }
        #pragma unroll
        for (int o = 16; o > 0; o >>= 1) {
            s  += __shfl_down_sync(0xffffffffu, s, o);
            s2 += __shfl_down_sync(0xffffffffu, s2, o);
        }
        if ((tid & 31) == 0) { red1[tid >> 5] = s; red2[tid >> 5] = s2; }
        __syncthreads();
        if (tid < 8) {
            s = red1[tid]; s2 = red2[tid];
            #pragma unroll
            for (int o = 4; o > 0; o >>= 1) {
                s  += __shfl_down_sync(0xffu, s, o);
                s2 += __shfl_down_sync(0xffu, s2, o);
            }
            if (tid == 0) { red1[0] = s; red2[0] = s2; }
        }
        __syncthreads();
        float mu = red1[0] * (1.f / DMODEL);
        float var = red2[0] * (1.f / DMODEL) - mu * mu;
        float inv = rsqrtf(var + LN_EPS);

        for (int i = tid; i < DMODEL; i += 256) {
            float xv = xr[i];
            float ln = (xv - mu) * inv * gamma[i] + beta[i];
            g_a[(size_t)row * DMODEL + i] = __float2half(ln);
            g_x[(size_t)row * DMODEL + i] = __float2half(xv);
        }
        return;
    }

    const float* W; int N, rowOff;
    __half* oT;
    if (bx < 72)       { W = Wq; N = 2304; rowOff = 0;    oT = g_wqkv; }
    else if (bx < 120) { W = Ws; N = 1536; rowOff = 0;    oT = g_wsc;  bx -= 72; }
    else if (bx < 168) { W = Wc; N = 1536; rowOff = 1536; oT = g_wsc;  bx -= 120; }
    else               { W = Wp; N = 768;  rowOff = 0;    oT = g_wpr;  bx -= 168; }

    int n0 = bx * 32, k0 = blockIdx.y * 32;
    int tx = threadIdx.x, ty = threadIdx.y;
    #pragma unroll
    for (int i = 0; i < 4; i++)
        tile[ty + i * 8][tx] = W[(size_t)(k0 + ty + i * 8) * N + n0 + tx];
    __syncthreads();
    #pragma unroll
    for (int i = 0; i < 4; i++) {
        int n = ty + i * 8;
        oT[(size_t)(rowOff + n0 + n) * KDIM + k0 + tx] = __float2half(tile[tx][n]);
    }
}

// ---------------- gate + feature map (fp16 in, x4 vectorized) ----------------
__device__ __forceinline__ float softplus_nb(float x) {
    return __logf(1.f + __expf(x));
}
__device__ __forceinline__ float elu1(float x) {
    return (x > 0.f) ? x + 1.f : __expf(x);
}

__global__ void features_kernel() {
    int idx4 = blockIdx.x * blockDim.x + threadIdx.x;
    if (idx4 >= LSEQ * DMODEL / 4) return;
    int l = idx4 / (DMODEL / 4);
    int d = (idx4 - l * (DMODEL / 4)) * 4;

    const __half* scr = g_semh + (size_t)l * 3072;
    float4 sa4 = ld4h(scr + d);
    float4 sp4 = ld4h(scr + 768 + d);
    float4 ca4 = ld4h(scr + 1536 + d);
    float4 cp4 = ld4h(scr + 2304 + d);

    const __half* qr = g_qkvh + (size_t)l * 2304;
    float4 q4 = ld4h(qr + d);
    float4 k4 = ld4h(qr + 768 + d);
    float4 v4 = ld4h(qr + 1536 + d);

    float4 qf4, kf4;
    {
        float z, gate;
        z = softplus_nb(sa4.x) * softplus_nb(ca4.x) * __cosf(sp4.x - cp4.x);
        gate = fmaf(0.5f, tanh_fast(0.5f * z), 0.5f);
        qf4.x = elu1(q4.x); kf4.x = elu1(k4.x * gate);
        z = softplus_nb(sa4.y) * softplus_nb(ca4.y) * __cosf(sp4.y - cp4.y);
        gate = fmaf(0.5f, tanh_fast(0.5f * z), 0.5f);
        qf4.y = elu1(q4.y); kf4.y = elu1(k4.y * gate);
        z = softplus_nb(sa4.z) * softplus_nb(ca4.z) * __cosf(sp4.z - cp4.z);
        gate = fmaf(0.5f, tanh_fast(0.5f * z), 0.5f);
        qf4.z = elu1(q4.z); kf4.z = elu1(k4.z * gate);
        z = softplus_nb(sa4.w) * softplus_nb(ca4.w) * __cosf(sp4.w - cp4.w);
        gate = fmaf(0.5f, tanh_fast(0.5f * z), 0.5f);
        qf4.w = elu1(q4.w); kf4.w = elu1(k4.w * gate);
    }

    int h = d >> 6;
    int dh = d & 63;
    size_t o = (size_t)h * LSEQ * DHEAD + (size_t)l * DHEAD + dh;
    *(float4*)&g_qf[o] = qf4;
    *(float4*)&g_kf[o] = kf4;
    *(float4*)&g_vv[o] = v4;
}

// ---------------- phase A: per-chunk state sums ----------------
__global__ __launch_bounds__(256)
void chunk_sums_kernel() {
    int h = blockIdx.x / NCHUNK;
    int c = blockIdx.x % NCHUNK;
    const float* Kb = g_kf + (size_t)h * LSEQ * DHEAD + (size_t)c * CSIZE * DHEAD;
    const float* Vb = g_vv + (size_t)h * LSEQ * DHEAD + (size_t)c * CSIZE * DHEAD;

    __shared__ float ks[16][64];
    __shared__ float vs[16][64];
    int tid = threadIdx.x;
    int te = tid & 15;
    int td = tid >> 4;

    float acc[4][4];
    #pragma unroll
    for (int i = 0; i < 4; i++)
        #pragma unroll
        for (int j = 0; j < 4; j++) acc[i][j] = 0.f;
    float zacc[4] = {0.f, 0.f, 0.f, 0.f};

    int lr = tid >> 4;
    int lc = (tid & 15) * 4;

    for (int p0 = 0; p0 < CSIZE; p0 += 16) {
        *(float4*)&ks[lr][lc] = *(const float4*)&Kb[(size_t)(p0 + lr) * DHEAD + lc];
        *(float4*)&vs[lr][lc] = *(const float4*)&Vb[(size_t)(p0 + lr) * DHEAD + lc];
        __syncthreads();
        #pragma unroll
        for (int p = 0; p < 16; p++) {
            float kk[4], vvv[4];
            #pragma unroll
            for (int i = 0; i < 4; i++) kk[i] = ks[p][td * 4 + i];
            #pragma unroll
            for (int j = 0; j < 4; j++) vvv[j] = vs[p][te * 4 + j];
            #pragma unroll
            for (int i = 0; i < 4; i++)
                #pragma unroll
                for (int j = 0; j < 4; j++)
                    acc[i][j] = fmaf(kk[i], vvv[j], acc[i][j]);
            if (te == 0) {
                #pragma unroll
                for (int i = 0; i < 4; i++) zacc[i] += kk[i];
            }
        }
        __syncthreads();
    }

    float* Sb = g_S + (size_t)(h * NCHUNK + c) * DHEAD * DHEAD;
    #pragma unroll
    for (int i = 0; i < 4; i++)
        #pragma unroll
        for (int j = 0; j < 4; j++)
            Sb[(size_t)(td * 4 + i) * DHEAD + te * 4 + j] = acc[i][j];
    if (te == 0) {
        float* Zb = g_Z + (size_t)(h * NCHUNK + c) * DHEAD;
        #pragma unroll
        for (int i = 0; i < 4; i++) Zb[td * 4 + i] = zacc[i];
    }
}

// ---------------- phase B: exclusive scan over chunks (grid (12,4)) ----------------
__global__ __launch_bounds__(256)
void scan_states_kernel() {
    int h = blockIdx.x;
    int part = blockIdx.y;
    int tid = threadIdx.x;
    float pref[4] = {0.f, 0.f, 0.f, 0.f};
    float prefz = 0.f;

    for (int c = 0; c < NCHUNK; c++) {
        float* Sb = g_S + (size_t)(h * NCHUNK + c) * DHEAD * DHEAD + part * 1024;
        #pragma unroll
        for (int i = 0; i < 4; i++) {
            int idx = tid + i * 256;
            float cur = Sb[idx];
            Sb[idx] = pref[i];
            pref[i] += cur;
        }
        if (part == 0 && tid < DHEAD) {
            float* Zb = g_Z + (size_t)(h * NCHUNK + c) * DHEAD;
            float cur = Zb[tid];
            Zb[tid] = prefz;
            prefz += cur;
        }
    }
}

// ---------------- phase C: per-chunk causal output (K,V in smem; P,Z via L1) ----------------
#define SMEM_C (2 * CSIZE * DHEAD * 4)   // 65536 B

__global__ __launch_bounds__(128)
void chunk_attn_kernel() {
    int h = blockIdx.x / NCHUNK;
    int c = blockIdx.x % NCHUNK;
    extern __shared__ float sh[];
    float* Ks = sh;
    float* Vs = Ks + CSIZE * DHEAD;

    int tid = threadIdx.x;
    size_t base = (size_t)h * LSEQ * DHEAD + (size_t)c * CSIZE * DHEAD;

    const float4* Kg = (const float4*)(g_kf + base);
    const float4* Vg = (const float4*)(g_vv + base);
    for (int j = tid; j < CSIZE * DHEAD / 4; j += 128) {
        ((float4*)Ks)[j] = Kg[j];
        ((float4*)Vs)[j] = Vg[j];
    }
    __syncthreads();

    float q[DHEAD];
    {
        const float4* qp = (const float4*)(g_qf + base + (size_t)tid * DHEAD);
        #pragma unroll
        for (int i = 0; i < DHEAD / 4; i++) {
            float4 t = qp[i];
            q[4 * i + 0] = t.x; q[4 * i + 1] = t.y; q[4 * i + 2] = t.z; q[4 * i + 3] = t.w;
        }
    }

    const float* Pg = g_S + (size_t)(h * NCHUNK + c) * DHEAD * DHEAD;
    const float* Zg = g_Z + (size_t)(h * NCHUNK + c) * DHEAD;

    float out[DHEAD];
    float den = 0.f;
    #pragma unroll
    for (int d = 0; d < DHEAD; d++) den = fmaf(q[d], __ldg(&Zg[d]), den);
    #pragma unroll
    for (int e = 0; e < DHEAD; e++) out[e] = 0.f;
    #pragma unroll 4
    for (int d = 0; d < DHEAD; d++) {
        float qd = q[d];
        const float4* pr = (const float4*)(Pg + d * DHEAD);
        #pragma unroll
        for (int i = 0; i < DHEAD / 4; i++) {
            float4 p = __ldg(&pr[i]);
            out[4 * i + 0] = fmaf(qd, p.x, out[4 * i + 0]);
            out[4 * i + 1] = fmaf(qd, p.y, out[4 * i + 1]);
            out[4 * i + 2] = fmaf(qd, p.z, out[4 * i + 2]);
            out[4 * i + 3] = fmaf(qd, p.w, out[4 * i + 3]);
        }
    }

    for (int j = 0; j <= tid; j++) {
        const float4* kr = (const float4*)(Ks + j * DHEAD);
        float s0 = 0.f, s1 = 0.f, s2 = 0.f, s3 = 0.f;
        #pragma unroll
        for (int i = 0; i < DHEAD / 4; i += 4) {
            float4 k0 = kr[i], k1 = kr[i + 1], k2 = kr[i + 2], k3 = kr[i + 3];
            s0 = fmaf(q[4 * i + 0], k0.x, s0); s0 = fmaf(q[4 * i + 1], k0.y, s0);
            s0 = fmaf(q[4 * i + 2], k0.z, s0); s0 = fmaf(q[4 * i + 3], k0.w, s0);
            s1 = fmaf(q[4 * i + 4], k1.x, s1); s1 = fmaf(q[4 * i + 5], k1.y, s1);
            s1 = fmaf(q[4 * i + 6], k1.z, s1); s1 = fmaf(q[4 * i + 7], k1.w, s1);
            s2 = fmaf(q[4 * i + 8], k2.x, s2); s2 = fmaf(q[4 * i + 9], k2.y, s2);
            s2 = fmaf(q[4 * i + 10], k2.z, s2); s2 = fmaf(q[4 * i + 11], k2.w, s2);
            s3 = fmaf(q[4 * i + 12], k3.x, s3); s3 = fmaf(q[4 * i + 13], k3.y, s3);
            s3 = fmaf(q[4 * i + 14], k3.z, s3); s3 = fmaf(q[4 * i + 15], k3.w, s3);
        }
        float s = (s0 + s1) + (s2 + s3);
        den += s;
        const float4* vr = (const float4*)(Vs + j * DHEAD);
        #pragma unroll
        for (int i = 0; i < DHEAD / 4; i++) {
            float4 vv4 = vr[i];
            out[4 * i + 0] = fmaf(s, vv4.x, out[4 * i + 0]);
            out[4 * i + 1] = fmaf(s, vv4.y, out[4 * i + 1]);
            out[4 * i + 2] = fmaf(s, vv4.z, out[4 * i + 2]);
            out[4 * i + 3] = fmaf(s, vv4.w, out[4 * i + 3]);
        }
    }

    float inv = 1.f / (den + DEN_EPS);
    int l = c * CSIZE + tid;
    __half* op = g_at + (size_t)l * DMODEL + h * DHEAD;
    #pragma unroll
    for (int e = 0; e < DHEAD; e += 2) {
        __half2 hv = __floats2half2_rn(out[e] * inv, out[e + 1] * inv);
        *(__half2*)&op[e] = hv;
    }
}

// ---------------- host launcher ----------------
extern "C" void kernel_launch(void* const* d_in, const int* in_sizes, int n_in,
                              void* d_out, int out_size) {
    const float* x      = (const float*)d_in[0];
    const float* W_qkv  = (const float*)d_in[1];
    const float* b_qkv  = (const float*)d_in[2];
    const float* W_sem  = (const float*)d_in[3];
    const float* b_sem  = (const float*)d_in[4];
    const float* W_ctx  = (const float*)d_in[5];
    const float* b_ctx  = (const float*)d_in[6];
    const float* W_proj = (const float*)d_in[7];
    const float* b_proj = (const float*)d_in[8];
    const float* ln_g   = (const float*)d_in[9];
    const float* ln_b   = (const float*)d_in[10];
    float* out = (float*)d_out;

    __half *p_a, *p_x, *p_wq, *p_ws, *p_wp, *p_at, *p_qkvh, *p_semh;
    float *p_bsc;
    cudaGetSymbolAddress((void**)&p_a, g_a);
    cudaGetSymbolAddress((void**)&p_x, g_x);
    cudaGetSymbolAddress((void**)&p_wq, g_wqkv);
    cudaGetSymbolAddress((void**)&p_ws, g_wsc);
    cudaGetSymbolAddress((void**)&p_wp, g_wpr);
    cudaGetSymbolAddress((void**)&p_at, g_at);
    cudaGetSymbolAddress((void**)&p_bsc, g_bsc);
    cudaGetSymbolAddress((void**)&p_qkvh, g_qkvh);
    cudaGetSymbolAddress((void**)&p_semh, g_semh);

    cudaFuncSetAttribute(gemm_mma<1>, cudaFuncAttributeMaxDynamicSharedMemorySize, GEMM_SMEM);
    cudaFuncSetAttribute(gemm_mma<0>, cudaFuncAttributeMaxDynamicSharedMemorySize, GEMM_SMEM);
    cudaFuncSetAttribute(chunk_attn_kernel, cudaFuncAttributeMaxDynamicSharedMemorySize, SMEM_C);

    // prep: transpose + fp16 + bias concat + LN (single launch)
    prep_kernel<<<dim3(279, 24), dim3(32, 8)>>>(W_qkv, W_sem, W_ctx, W_proj,
                                                b_sem, b_ctx, x, ln_g, ln_b);

    // fp16 tensor-core GEMMs (fp16 outputs for intermediates)
    gemm_mma<1><<<dim3(2304 / 128, LSEQ / 128), 256, GEMM_SMEM>>>(p_a, p_wq, b_qkv, p_qkvh, 2304);
    gemm_mma<1><<<dim3(3072 / 128, LSEQ / 128), 256, GEMM_SMEM>>>(p_x, p_ws, p_bsc, p_semh, 3072);

    // gate + feature map (fp16 in, x4 vectorized)
    features_kernel<<<(LSEQ * DMODEL / 4 + 255) / 256, 256>>>();

    // chunked linear attention
    chunk_sums_kernel<<<NHEAD * NCHUNK, 256>>>();
    scan_states_kernel<<<dim3(NHEAD, 4), 256>>>();
    chunk_attn_kernel<<<NHEAD * NCHUNK, 128, SMEM_C>>>();

    // output projection (fp32 out -> d_out)
    gemm_mma<0><<<dim3(768 / 128, LSEQ / 128), 256, GEMM_SMEM>>>(p_at, p_wp, b_proj, out, 768);
}

// round 14
// speedup vs baseline: 1.5972x; 1.0140x over previous
#include <cuda_runtime.h>
#include <cuda_fp16.h>
#include <math.h>
#include <stdint.h>

// ---------------- problem constants ----------------
#define LSEQ 2048
#define DMODEL 768
#define KDIM 768
#define NHEAD 12
#define DHEAD 64
#define NCHUNK 16
#define CSIZE 128
#define LN_EPS 1e-5f
#define DEN_EPS 1e-6f

// ---------------- scratch (device globals) ----------------
__device__ __align__(128) __half g_a   [LSEQ * DMODEL];   // LN(x) fp16
__device__ __align__(128) __half g_x   [LSEQ * DMODEL];   // x fp16
__device__ __align__(128) __half g_wqkv[2304 * KDIM];     // W_qkv^T fp16
__device__ __align__(128) __half g_wsc [3072 * KDIM];     // [W_sem;W_ctx]^T fp16
__device__ __align__(128) __half g_wpr [768 * KDIM];      // W_proj^T fp16
__device__ __align__(128) __half g_at  [LSEQ * DMODEL];   // attn out fp16
__device__ __align__(128) float g_bsc[3072];
__device__ __align__(128) __half g_qkvh[LSEQ * 3 * DMODEL];  // qkv GEMM out fp16
__device__ __align__(128) __half g_semh[LSEQ * 3072];        // sem/ctx GEMM out fp16
__device__ __align__(128) __half g_qf[NHEAD * LSEQ * DHEAD]; // features fp16
__device__ __align__(128) __half g_kf[NHEAD * LSEQ * DHEAD];
__device__ __align__(128) __half g_vv[NHEAD * LSEQ * DHEAD];
__device__ float g_S [NHEAD * NCHUNK * DHEAD * DHEAD];
__device__ float g_Z [NHEAD * NCHUNK * DHEAD];

// ---------------- PTX helpers (family-portable only) ----------------
__device__ __forceinline__ uint32_t smem_u32(const void* p) {
    uint32_t a;
    asm("{ .reg .u64 t; cvta.to.shared.u64 t, %1; cvt.u32.u64 %0, t; }" : "=r"(a) : "l"(p));
    return a;
}
__device__ __forceinline__ void cp_async16(uint32_t dst, const void* src) {
    asm volatile("cp.async.cg.shared.global [%0], [%1], 16;" :: "r"(dst), "l"(src));
}
__device__ __forceinline__ void cp_commit() {
    asm volatile("cp.async.commit_group;" ::: "memory");
}
__device__ __forceinline__ void cp_wait1() {
    asm volatile("cp.async.wait_group 1;" ::: "memory");
}
__device__ __forceinline__ float tanh_fast(float x) {
    float y;
    asm("tanh.approx.f32 %0, %1;" : "=f"(y) : "f"(x));
    return y;
}
__device__ __forceinline__ float4 ld4h(const __half* p) {
    uint2 u = *(const uint2*)p;
    float2 fa = __half22float2(*(__half2*)&u.x);
    float2 fb = __half22float2(*(__half2*)&u.y);
    return make_float4(fa.x, fa.y, fb.x, fb.y);
}
__device__ __forceinline__ void st4h(__half* p, float4 v) {
    uint2 u;
    *(__half2*)&u.x = __floats2half2_rn(v.x, v.y);
    *(__half2*)&u.y = __floats2half2_rn(v.z, v.w);
    *(uint2*)p = u;
}
#define LDSM4(r0, r1, r2, r3, a) \
    asm volatile("ldmatrix.sync.aligned.m8n8.x4.shared.b16 {%0,%1,%2,%3}, [%4];" \
                 : "=r"(r0), "=r"(r1), "=r"(r2), "=r"(r3) : "r"(a))
#define MMAF16(d, a0, a1, a2, a3, b0, b1) \
    asm volatile("mma.sync.aligned.m16n8k16.row.col.f32.f16.f16.f32 " \
                 "{%0,%1,%2,%3}, {%4,%5,%6,%7}, {%8,%9}, {%0,%1,%2,%3};" \
                 : "+f"((d)[0]), "+f"((d)[1]), "+f"((d)[2]), "+f"((d)[3]) \
                 : "r"(a0), "r"(a1), "r"(a2), "r"(a3), "r"(b0), "r"(b1))

// ---------------- GEMM: C[2048,Ntot] = A @ B^T + bias (fp16, BK=64) ----------------
#define BK 64
#define ROWB 144
#define TILEB (128 * ROWB)
#define STAGEB (2 * TILEB)
#define NSTAGE 3
#define GEMM_SMEM (NSTAGE * STAGEB)   // 110592 B -> 2 CTAs/SM
#define NKT (KDIM / BK)               // 12

__device__ __forceinline__ void g_load_stage(
    uint32_t smem_base, int s, int tid,
    const __half* a, const __half* b)
{
    uint32_t stb = smem_base + (uint32_t)(s % NSTAGE) * STAGEB;
    int kk = s * BK;
    #pragma unroll
    for (int t = 0; t < 2; t++) {
        const __half* base = t ? b : a;
        #pragma unroll
        for (int i = 0; i < 4; i++) {
            int c = tid + i * 256;
            int r = c >> 3;
            int seg = c & 7;
            cp_async16(stb + (uint32_t)t * TILEB + (uint32_t)(r * ROWB + seg * 16),
                       base + (size_t)r * KDIM + kk + seg * 8);
        }
    }
}

// OUTH=1: store fp16; OUTH=0: store fp32
template<int OUTH>
__global__ __launch_bounds__(256, 2)
void gemm_mma(const __half* __restrict__ A, const __half* __restrict__ BT,
              const float* __restrict__ bias, void* __restrict__ Cv, int Ntot)
{
    extern __shared__ __align__(128) char smem[];
    const int tid = threadIdx.x;
    const int wid = tid >> 5;
    const int lane = tid & 31;
    const int wm = wid & 1;
    const int wn = wid >> 1;
    const int bx = blockIdx.x, by = blockIdx.y;

    uint32_t smem_base = smem_u32(smem);

    const __half* a = A + (size_t)by * 128 * KDIM;
    const __half* b = BT + (size_t)bx * 128 * KDIM;

    float acc[4][4][4];
    #pragma unroll
    for (int i = 0; i < 4; i++)
        #pragma unroll
        for (int j = 0; j < 4; j++)
            #pragma unroll
            for (int t = 0; t < 4; t++) acc[i][j][t] = 0.f;

    const uint32_t a_row = (uint32_t)(lane & 15);
    const uint32_t a_byt = (uint32_t)((lane >> 4) * 16);
    const uint32_t b_row = (uint32_t)((lane & 7) + ((lane >> 4) << 3));
    const uint32_t b_byt = (uint32_t)(((lane >> 3) & 1) * 16);

    g_load_stage(smem_base, 0, tid, a, b); cp_commit();
    g_load_stage(smem_base, 1, tid, a, b); cp_commit();

    for (int s = 0; s < NKT; s++) {
        cp_wait1();
        __syncthreads();
        if (s + 2 < NKT) g_load_stage(smem_base, s + 2, tid, a, b);
        cp_commit();

        uint32_t stb = smem_base + (uint32_t)(s % NSTAGE) * STAGEB;
        #pragma unroll
        for (int k16 = 0; k16 < 4; k16++) {
            const uint32_t koff = (uint32_t)(k16 * 32);
            uint32_t af[4][4];
            #pragma unroll
            for (int mt = 0; mt < 4; mt++) {
                uint32_t addr = stb + (uint32_t)(wm * 64 + mt * 16 + a_row) * ROWB
                              + koff + a_byt;
                LDSM4(af[mt][0], af[mt][1], af[mt][2], af[mt][3], addr);
            }
            uint32_t bf[2][4];
            #pragma unroll
            for (int nb = 0; nb < 2; nb++) {
                uint32_t addr = stb + TILEB + (uint32_t)(wn * 32 + nb * 16 + b_row) * ROWB
                              + koff + b_byt;
                LDSM4(bf[nb][0], bf[nb][1], bf[nb][2], bf[nb][3], addr);
            }
            #pragma unroll
            for (int mt = 0; mt < 4; mt++)
                #pragma unroll
                for (int nt = 0; nt < 4; nt++)
                    MMAF16(acc[mt][nt],
                           af[mt][0], af[mt][1], af[mt][2], af[mt][3],
                           bf[nt >> 1][(nt & 1) * 2], bf[nt >> 1][(nt & 1) * 2 + 1]);
        }
    }

    int r0 = by * 128 + wm * 64 + (lane >> 2);
    int c0 = bx * 128 + wn * 32 + (lane & 3) * 2;
    #pragma unroll
    for (int mt = 0; mt < 4; mt++) {
        #pragma unroll
        for (int nt = 0; nt < 4; nt++) {
            int r = r0 + mt * 16;
            int c = c0 + nt * 8;
            float b0 = bias[c], b1 = bias[c + 1];
            if (OUTH) {
                __half* C = (__half*)Cv;
                *(__half2*)&C[(size_t)r * Ntot + c] =
                    __floats2half2_rn(acc[mt][nt][0] + b0, acc[mt][nt][1] + b1);
                *(__half2*)&C[(size_t)(r + 8) * Ntot + c] =
                    __floats2half2_rn(acc[mt][nt][2] + b0, acc[mt][nt][3] + b1);
            } else {
                float* C = (float*)Cv;
                float2 v0 = { acc[mt][nt][0] + b0, acc[mt][nt][1] + b1 };
                float2 v1 = { acc[mt][nt][2] + b0, acc[mt][nt][3] + b1 };
                *(float2*)&C[(size_t)r * Ntot + c] = v0;
                *(float2*)&C[(size_t)(r + 8) * Ntot + c] = v1;
            }
        }
    }
}

// ---------------- prep: weight transpose + fp16, bias concat, LN (one launch) ----------------
__global__ void prep_kernel(const float* __restrict__ Wq,
                            const float* __restrict__ Ws,
                            const float* __restrict__ Wc,
                            const float* __restrict__ Wp,
                            const float* __restrict__ bs,
                            const float* __restrict__ bc,
                            const float* __restrict__ x,
                            const float* __restrict__ gamma,
                            const float* __restrict__ beta)
{
    __shared__ float tile[32][33];
    __shared__ float red1[8], red2[8];
    int bx = blockIdx.x;
    int tid = threadIdx.y * 32 + threadIdx.x;

    if (bx == 192) {
        int i = blockIdx.y * 128 + tid;
        if (i < 1536) g_bsc[i] = bs[i];
        else if (i < 3072) g_bsc[i] = bc[i - 1536];
        return;
    }
    if (bx >= 193) {
        int row = (bx - 193) * 24 + blockIdx.y;
        if (row >= LSEQ) return;
        const float* xr = x + (size_t)row * DMODEL;

        float s = 0.f, s2 = 0.f;
        for (int i = tid; i < DMODEL; i += 256) {
            float v = xr[i];
            s += v;
            s2 = fmaf(v, v, s2);
        }
        #pragma unroll
        for (int o = 16; o > 0; o >>= 1) {
            s  += __shfl_down_sync(0xffffffffu, s, o);
            s2 += __shfl_down_sync(0xffffffffu, s2, o);
        }
        if ((tid & 31) == 0) { red1[tid >> 5] = s; red2[tid >> 5] = s2; }
        __syncthreads();
        if (tid < 8) {
            s = red1[tid]; s2 = red2[tid];
            #pragma unroll
            for (int o = 4; o > 0; o >>= 1) {
                s  += __shfl_down_sync(0xffu, s, o);
                s2 += __shfl_down_sync(0xffu, s2, o);
            }
            if (tid == 0) { red1[0] = s; red2[0] = s2; }
        }
        __syncthreads();
        float mu = red1[0] * (1.f / DMODEL);
        float var = red2[0] * (1.f / DMODEL) - mu * mu;
        float inv = rsqrtf(var + LN_EPS);

        for (int i = tid; i < DMODEL; i += 256) {
            float xv = xr[i];
            float ln = (xv - mu) * inv * gamma[i] + beta[i];
            g_a[(size_t)row * DMODEL + i] = __float2half(ln);
            g_x[(size_t)row * DMODEL + i] = __float2half(xv);
        }
        return;
    }

    const float* W; int N, rowOff;
    __half* oT;
    if (bx < 72)       { W = Wq; N = 2304; rowOff = 0;    oT = g_wqkv; }
    else if (bx < 120) { W = Ws; N = 1536; rowOff = 0;    oT = g_wsc;  bx -= 72; }
    else if (bx < 168) { W = Wc; N = 1536; rowOff = 1536; oT = g_wsc;  bx -= 120; }
    else               { W = Wp; N = 768;  rowOff = 0;    oT = g_wpr;  bx -= 168; }

    int n0 = bx * 32, k0 = blockIdx.y * 32;
    int tx = threadIdx.x, ty = threadIdx.y;
    #pragma unroll
    for (int i = 0; i < 4; i++)
        tile[ty + i * 8][tx] = W[(size_t)(k0 + ty + i * 8) * N + n0 + tx];
    __syncthreads();
    #pragma unroll
    for (int i = 0; i < 4; i++) {
        int n = ty + i * 8;
        oT[(size_t)(rowOff + n0 + n) * KDIM + k0 + tx] = __float2half(tile[tx][n]);
    }
}

// ---------------- gate + feature map (fp16 in/out, x4 vectorized) ----------------
__device__ __forceinline__ float softplus_nb(float x) {
    return __logf(1.f + __expf(x));
}
__device__ __forceinline__ float elu1(float x) {
    return (x > 0.f) ? x + 1.f : __expf(x);
}

__global__ void features_kernel() {
    int idx4 = blockIdx.x * blockDim.x + threadIdx.x;
    if (idx4 >= LSEQ * DMODEL / 4) return;
    int l = idx4 / (DMODEL / 4);
    int d = (idx4 - l * (DMODEL / 4)) * 4;

    const __half* scr = g_semh + (size_t)l * 3072;
    float4 sa4 = ld4h(scr + d);
    float4 sp4 = ld4h(scr + 768 + d);
    float4 ca4 = ld4h(scr + 1536 + d);
    float4 cp4 = ld4h(scr + 2304 + d);

    const __half* qr = g_qkvh + (size_t)l * 2304;
    float4 q4 = ld4h(qr + d);
    float4 k4 = ld4h(qr + 768 + d);
    float4 v4 = ld4h(qr + 1536 + d);

    float4 qf4, kf4;
    {
        float z, gate;
        z = softplus_nb(sa4.x) * softplus_nb(ca4.x) * __cosf(sp4.x - cp4.x);
        gate = fmaf(0.5f, tanh_fast(0.5f * z), 0.5f);
        qf4.x = elu1(q4.x); kf4.x = elu1(k4.x * gate);
        z = softplus_nb(sa4.y) * softplus_nb(ca4.y) * __cosf(sp4.y - cp4.y);
        gate = fmaf(0.5f, tanh_fast(0.5f * z), 0.5f);
        qf4.y = elu1(q4.y); kf4.y = elu1(k4.y * gate);
        z = softplus_nb(sa4.z) * softplus_nb(ca4.z) * __cosf(sp4.z - cp4.z);
        gate = fmaf(0.5f, tanh_fast(0.5f * z), 0.5f);
        qf4.z = elu1(q4.z); kf4.z = elu1(k4.z * gate);
        z = softplus_nb(sa4.w) * softplus_nb(ca4.w) * __cosf(sp4.w - cp4.w);
        gate = fmaf(0.5f, tanh_fast(0.5f * z), 0.5f);
        qf4.w = elu1(q4.w); kf4.w = elu1(k4.w * gate);
    }

    int h = d >> 6;
    int dh = d & 63;
    size_t o = (size_t)h * LSEQ * DHEAD + (size_t)l * DHEAD + dh;
    st4h(&g_qf[o], qf4);
    st4h(&g_kf[o], kf4);
    st4h(&g_vv[o], v4);
}

// ---------------- phase A: per-chunk state sums (fp16 global, fp32 smem/compute) ----------------
__global__ __launch_bounds__(256)
void chunk_sums_kernel() {
    int h = blockIdx.x / NCHUNK;
    int c = blockIdx.x % NCHUNK;
    const __half* Kb = g_kf + (size_t)h * LSEQ * DHEAD + (size_t)c * CSIZE * DHEAD;
    const __half* Vb = g_vv + (size_t)h * LSEQ * DHEAD + (size_t)c * CSIZE * DHEAD;

    __shared__ float ks[16][64];
    __shared__ float vs[16][64];
    int tid = threadIdx.x;
    int te = tid & 15;
    int td = tid >> 4;

    float acc[4][4];
    #pragma unroll
    for (int i = 0; i < 4; i++)
        #pragma unroll
        for (int j = 0; j < 4; j++) acc[i][j] = 0.f;
    float zacc[4] = {0.f, 0.f, 0.f, 0.f};

    int lr = tid >> 4;
    int lc = (tid & 15) * 4;

    for (int p0 = 0; p0 < CSIZE; p0 += 16) {
        *(float4*)&ks[lr][lc] = ld4h(&Kb[(size_t)(p0 + lr) * DHEAD + lc]);
        *(float4*)&vs[lr][lc] = ld4h(&Vb[(size_t)(p0 + lr) * DHEAD + lc]);
        __syncthreads();
        #pragma unroll
        for (int p = 0; p < 16; p++) {
            float kk[4], vvv[4];
            #pragma unroll
            for (int i = 0; i < 4; i++) kk[i] = ks[p][td * 4 + i];
            #pragma unroll
            for (int j = 0; j < 4; j++) vvv[j] = vs[p][te * 4 + j];
            #pragma unroll
            for (int i = 0; i < 4; i++)
                #pragma unroll
                for (int j = 0; j < 4; j++)
                    acc[i][j] = fmaf(kk[i], vvv[j], acc[i][j]);
            if (te == 0) {
                #pragma unroll
                for (int i = 0; i < 4; i++) zacc[i] += kk[i];
            }
        }
        __syncthreads();
    }

    float* Sb = g_S + (size_t)(h * NCHUNK + c) * DHEAD * DHEAD;
    #pragma unroll
    for (int i = 0; i < 4; i++)
        #pragma unroll
        for (int j = 0; j < 4; j++)
            Sb[(size_t)(td * 4 + i) * DHEAD + te * 4 + j] = acc[i][j];
    if (te == 0) {
        float* Zb = g_Z + (size_t)(h * NCHUNK + c) * DHEAD;
        #pragma unroll
        for (int i = 0; i < 4; i++) Zb[td * 4 + i] = zacc[i];
    }
}

// ---------------- phase B: exclusive scan over chunks (grid (12,4)) ----------------
__global__ __launch_bounds__(256)
void scan_states_kernel() {
    int h = blockIdx.x;
    int part = blockIdx.y;
    int tid = threadIdx.x;
    float pref[4] = {0.f, 0.f, 0.f, 0.f};
    float prefz = 0.f;

    for (int c = 0; c < NCHUNK; c++) {
        float* Sb = g_S + (size_t)(h * NCHUNK + c) * DHEAD * DHEAD + part * 1024;
        #pragma unroll
        for (int i = 0; i < 4; i++) {
            int idx = tid + i * 256;
            float cur = Sb[idx];
            Sb[idx] = pref[i];
            pref[i] += cur;
        }
        if (part == 0 && tid < DHEAD) {
            float* Zb = g_Z + (size_t)(h * NCHUNK + c) * DHEAD;
            float cur = Zb[tid];
            Zb[tid] = prefz;
            prefz += cur;
        }
    }
}

// ---------------- phase C: per-chunk causal output (fp16 global, fp32 smem) ----------------
#define SMEM_C (2 * CSIZE * DHEAD * 4)   // 65536 B

__global__ __launch_bounds__(128)
void chunk_attn_kernel() {
    int h = blockIdx.x / NCHUNK;
    int c = blockIdx.x % NCHUNK;
    extern __shared__ float sh[];
    float* Ks = sh;
    float* Vs = Ks + CSIZE * DHEAD;

    int tid = threadIdx.x;
    size_t base = (size_t)h * LSEQ * DHEAD + (size_t)c * CSIZE * DHEAD;

    const __half* Kg = g_kf + base;
    const __half* Vg = g_vv + base;
    for (int j = tid; j < CSIZE * DHEAD / 4; j += 128) {
        ((float4*)Ks)[j] = ld4h(Kg + 4 * j);
        ((float4*)Vs)[j] = ld4h(Vg + 4 * j);
    }
    __syncthreads();

    float q[DHEAD];
    {
        const __half* qp = g_qf + base + (size_t)tid * DHEAD;
        #pragma unroll
        for (int i = 0; i < DHEAD / 4; i++) {
            float4 t = ld4h(qp + 4 * i);
            q[4 * i + 0] = t.x; q[4 * i + 1] = t.y; q[4 * i + 2] = t.z; q[4 * i + 3] = t.w;
        }
    }

    const float* Pg = g_S + (size_t)(h * NCHUNK + c) * DHEAD * DHEAD;
    const float* Zg = g_Z + (size_t)(h * NCHUNK + c) * DHEAD;

    float out[DHEAD];
    float den = 0.f;
    #pragma unroll
    for (int d = 0; d < DHEAD; d++) den = fmaf(q[d], __ldg(&Zg[d]), den);
    #pragma unroll
    for (int e = 0; e < DHEAD; e++) out[e] = 0.f;
    #pragma unroll 4
    for (int d = 0; d < DHEAD; d++) {
        float qd = q[d];
        const float4* pr = (const float4*)(Pg + d * DHEAD);
        #pragma unroll
        for (int i = 0; i < DHEAD / 4; i++) {
            float4 p = __ldg(&pr[i]);
            out[4 * i + 0] = fmaf(qd, p.x, out[4 * i + 0]);
            out[4 * i + 1] = fmaf(qd, p.y, out[4 * i + 1]);
            out[4 * i + 2] = fmaf(qd, p.z, out[4 * i + 2]);
            out[4 * i + 3] = fmaf(qd, p.w, out[4 * i + 3]);
        }
    }

    for (int j = 0; j <= tid; j++) {
        const float4* kr = (const float4*)(Ks + j * DHEAD);
        float s0 = 0.f, s1 = 0.f, s2 = 0.f, s3 = 0.f;
        #pragma unroll
        for (int i = 0; i < DHEAD / 4; i += 4) {
            float4 k0 = kr[i], k1 = kr[i + 1], k2 = kr[i + 2], k3 = kr[i + 3];
            s0 = fmaf(q[4 * i + 0], k0.x, s0); s0 = fmaf(q[4 * i + 1], k0.y, s0);
            s0 = fmaf(q[4 * i + 2], k0.z, s0); s0 = fmaf(q[4 * i + 3], k0.w, s0);
            s1 = fmaf(q[4 * i + 4], k1.x, s1); s1 = fmaf(q[4 * i + 5], k1.y, s1);
            s1 = fmaf(q[4 * i + 6], k1.z, s1); s1 = fmaf(q[4 * i + 7], k1.w, s1);
            s2 = fmaf(q[4 * i + 8], k2.x, s2); s2 = fmaf(q[4 * i + 9], k2.y, s2);
            s2 = fmaf(q[4 * i + 10], k2.z, s2); s2 = fmaf(q[4 * i + 11], k2.w, s2);
            s3 = fmaf(q[4 * i + 12], k3.x, s3); s3 = fmaf(q[4 * i + 13], k3.y, s3);
            s3 = fmaf(q[4 * i + 14], k3.z, s3); s3 = fmaf(q[4 * i + 15], k3.w, s3);
        }
        float s = (s0 + s1) + (s2 + s3);
        den += s;
        const float4* vr = (const float4*)(Vs + j * DHEAD);
        #pragma unroll
        for (int i = 0; i < DHEAD / 4; i++) {
            float4 vv4 = vr[i];
            out[4 * i + 0] = fmaf(s, vv4.x, out[4 * i + 0]);
            out[4 * i + 1] = fmaf(s, vv4.y, out[4 * i + 1]);
            out[4 * i + 2] = fmaf(s, vv4.z, out[4 * i + 2]);
            out[4 * i + 3] = fmaf(s, vv4.w, out[4 * i + 3]);
        }
    }

    float inv = 1.f / (den + DEN_EPS);
    int l = c * CSIZE + tid;
    __half* op = g_at + (size_t)l * DMODEL + h * DHEAD;
    #pragma unroll
    for (int e = 0; e < DHEAD; e += 2) {
        __half2 hv = __floats2half2_rn(out[e] * inv, out[e + 1] * inv);
        *(__half2*)&op[e] = hv;
    }
}

// ---------------- host launcher ----------------
extern "C" void kernel_launch(void* const* d_in, const int* in_sizes, int n_in,
                              void* d_out, int out_size) {
    const float* x      = (const float*)d_in[0];
    const float* W_qkv  = (const float*)d_in[1];
    const float* b_qkv  = (const float*)d_in[2];
    const float* W_sem  = (const float*)d_in[3];
    const float* b_sem  = (const float*)d_in[4];
    const float* W_ctx  = (const float*)d_in[5];
    const float* b_ctx  = (const float*)d_in[6];
    const float* W_proj = (const float*)d_in[7];
    const float* b_proj = (const float*)d_in[8];
    const float* ln_g   = (const float*)d_in[9];
    const float* ln_b   = (const float*)d_in[10];
    float* out = (float*)d_out;

    __half *p_a, *p_x, *p_wq, *p_ws, *p_wp, *p_at, *p_qkvh, *p_semh;
    float *p_bsc;
    cudaGetSymbolAddress((void**)&p_a, g_a);
    cudaGetSymbolAddress((void**)&p_x, g_x);
    cudaGetSymbolAddress((void**)&p_wq, g_wqkv);
    cudaGetSymbolAddress((void**)&p_ws, g_wsc);
    cudaGetSymbolAddress((void**)&p_wp, g_wpr);
    cudaGetSymbolAddress((void**)&p_at, g_at);
    cudaGetSymbolAddress((void**)&p_bsc, g_bsc);
    cudaGetSymbolAddress((void**)&p_qkvh, g_qkvh);
    cudaGetSymbolAddress((void**)&p_semh, g_semh);

    cudaFuncSetAttribute(gemm_mma<1>, cudaFuncAttributeMaxDynamicSharedMemorySize, GEMM_SMEM);
    cudaFuncSetAttribute(gemm_mma<0>, cudaFuncAttributeMaxDynamicSharedMemorySize, GEMM_SMEM);
    cudaFuncSetAttribute(chunk_attn_kernel, cudaFuncAttributeMaxDynamicSharedMemorySize, SMEM_C);

    // prep: transpose + fp16 + bias concat + LN (single launch)
    prep_kernel<<<dim3(279, 24), dim3(32, 8)>>>(W_qkv, W_sem, W_ctx, W_proj,
                                                b_sem, b_ctx, x, ln_g, ln_b);

    // fp16 tensor-core GEMMs (fp16 outputs for intermediates)
    gemm_mma<1><<<dim3(2304 / 128, LSEQ / 128), 256, GEMM_SMEM>>>(p_a, p_wq, b_qkv, p_qkvh, 2304);
    gemm_mma<1><<<dim3(3072 / 128, LSEQ / 128), 256, GEMM_SMEM>>>(p_x, p_ws, p_bsc, p_semh, 3072);

    // gate + feature map (fp16 in/out)
    features_kernel<<<(LSEQ * DMODEL / 4 + 255) / 256, 256>>>();

    // chunked linear attention
    chunk_sums_kernel<<<NHEAD * NCHUNK, 256>>>();
    scan_states_kernel<<<dim3(NHEAD, 4), 256>>>();
    chunk_attn_kernel<<<NHEAD * NCHUNK, 128, SMEM_C>>>();

    // output projection (fp32 out -> d_out)
    gemm_mma<0><<<dim3(768 / 128, LSEQ / 128), 256, GEMM_SMEM>>>(p_at, p_wp, b_proj, out, 768);
}

// round 15
// speedup vs baseline: 1.6130x; 1.0099x over previous
#include <cuda_runtime.h>
#include <cuda_fp16.h>
#include <math.h>
#include <stdint.h>

// ---------------- problem constants ----------------
#define LSEQ 2048
#define DMODEL 768
#define KDIM 768
#define NHEAD 12
#define DHEAD 64
#define NCHUNK 16
#define CSIZE 128
#define LN_EPS 1e-5f
#define DEN_EPS 1e-6f

// ---------------- scratch (device globals) ----------------
__device__ __align__(128) __half g_a   [LSEQ * DMODEL];   // LN(x) fp16
__device__ __align__(128) __half g_x   [LSEQ * DMODEL];   // x fp16
__device__ __align__(128) __half g_wqkv[2304 * KDIM];     // W_qkv^T fp16
__device__ __align__(128) __half g_wsc [3072 * KDIM];     // [W_sem;W_ctx]^T fp16
__device__ __align__(128) __half g_wpr [768 * KDIM];      // W_proj^T fp16
__device__ __align__(128) __half g_at  [LSEQ * DMODEL];   // attn out fp16
__device__ __align__(128) float g_bsc[3072];
__device__ __align__(128) __half g_qkvh[LSEQ * 3 * DMODEL];  // qkv GEMM out fp16
__device__ __align__(128) __half g_semh[LSEQ * 3072];        // sem/ctx GEMM out fp16
__device__ __align__(128) __half g_qf[NHEAD * LSEQ * DHEAD]; // features fp16
__device__ __align__(128) __half g_kf[NHEAD * LSEQ * DHEAD];
__device__ __align__(128) __half g_vv[NHEAD * LSEQ * DHEAD];
__device__ float g_S [NHEAD * NCHUNK * DHEAD * DHEAD];
__device__ float g_Z [NHEAD * NCHUNK * DHEAD];

// ---------------- PTX helpers (family-portable only) ----------------
__device__ __forceinline__ uint32_t smem_u32(const void* p) {
    uint32_t a;
    asm("{ .reg .u64 t; cvta.to.shared.u64 t, %1; cvt.u32.u64 %0, t; }" : "=r"(a) : "l"(p));
    return a;
}
__device__ __forceinline__ void cp_async16(uint32_t dst, const void* src) {
    asm volatile("cp.async.cg.shared.global [%0], [%1], 16;" :: "r"(dst), "l"(src));
}
__device__ __forceinline__ void cp_commit() {
    asm volatile("cp.async.commit_group;" ::: "memory");
}
__device__ __forceinline__ void cp_wait1() {
    asm volatile("cp.async.wait_group 1;" ::: "memory");
}
__device__ __forceinline__ float tanh_fast(float x) {
    float y;
    asm("tanh.approx.f32 %0, %1;" : "=f"(y) : "f"(x));
    return y;
}
__device__ __forceinline__ float4 ld4h(const __half* p) {
    uint2 u = *(const uint2*)p;
    float2 fa = __half22float2(*(__half2*)&u.x);
    float2 fb = __half22float2(*(__half2*)&u.y);
    return make_float4(fa.x, fa.y, fb.x, fb.y);
}
__device__ __forceinline__ void st4h(__half* p, float4 v) {
    uint2 u;
    *(__half2*)&u.x = __floats2half2_rn(v.x, v.y);
    *(__half2*)&u.y = __floats2half2_rn(v.z, v.w);
    *(uint2*)p = u;
}
#define LDSM4(r0, r1, r2, r3, a) \
    asm volatile("ldmatrix.sync.aligned.m8n8.x4.shared.b16 {%0,%1,%2,%3}, [%4];" \
                 : "=r"(r0), "=r"(r1), "=r"(r2), "=r"(r3) : "r"(a))
#define MMAF16(d, a0, a1, a2, a3, b0, b1) \
    asm volatile("mma.sync.aligned.m16n8k16.row.col.f32.f16.f16.f32 " \
                 "{%0,%1,%2,%3}, {%4,%5,%6,%7}, {%8,%9}, {%0,%1,%2,%3};" \
                 : "+f"((d)[0]), "+f"((d)[1]), "+f"((d)[2]), "+f"((d)[3]) \
                 : "r"(a0), "r"(a1), "r"(a2), "r"(a3), "r"(b0), "r"(b1))

// ---------------- GEMM: C[2048,Ntot] = A @ B^T + bias (fp16, BK=64) ----------------
#define BK 64
#define ROWB 144
#define TILEB (128 * ROWB)
#define STAGEB (2 * TILEB)
#define NSTAGE 3
#define GEMM_SMEM (NSTAGE * STAGEB)   // 110592 B -> 2 CTAs/SM
#define NKT (KDIM / BK)               // 12

__device__ __forceinline__ void g_load_stage(
    uint32_t smem_base, int s, int tid,
    const __half* a, const __half* b)
{
    uint32_t stb = smem_base + (uint32_t)(s % NSTAGE) * STAGEB;
    int kk = s * BK;
    #pragma unroll
    for (int t = 0; t < 2; t++) {
        const __half* base = t ? b : a;
        #pragma unroll
        for (int i = 0; i < 4; i++) {
            int c = tid + i * 256;
            int r = c >> 3;
            int seg = c & 7;
            cp_async16(stb + (uint32_t)t * TILEB + (uint32_t)(r * ROWB + seg * 16),
                       base + (size_t)r * KDIM + kk + seg * 8);
        }
    }
}

// OUTH=1: store fp16; OUTH=0: store fp32
template<int OUTH>
__global__ __launch_bounds__(256, 2)
void gemm_mma(const __half* __restrict__ A, const __half* __restrict__ BT,
              const float* __restrict__ bias, void* __restrict__ Cv, int Ntot)
{
    extern __shared__ __align__(128) char smem[];
    const int tid = threadIdx.x;
    const int wid = tid >> 5;
    const int lane = tid & 31;
    const int wm = wid & 1;
    const int wn = wid >> 1;
    const int bx = blockIdx.x, by = blockIdx.y;

    uint32_t smem_base = smem_u32(smem);

    const __half* a = A + (size_t)by * 128 * KDIM;
    const __half* b = BT + (size_t)bx * 128 * KDIM;

    float acc[4][4][4];
    #pragma unroll
    for (int i = 0; i < 4; i++)
        #pragma unroll
        for (int j = 0; j < 4; j++)
            #pragma unroll
            for (int t = 0; t < 4; t++) acc[i][j][t] = 0.f;

    const uint32_t a_row = (uint32_t)(lane & 15);
    const uint32_t a_byt = (uint32_t)((lane >> 4) * 16);
    const uint32_t b_row = (uint32_t)((lane & 7) + ((lane >> 4) << 3));
    const uint32_t b_byt = (uint32_t)(((lane >> 3) & 1) * 16);

    g_load_stage(smem_base, 0, tid, a, b); cp_commit();
    g_load_stage(smem_base, 1, tid, a, b); cp_commit();

    for (int s = 0; s < NKT; s++) {
        cp_wait1();
        __syncthreads();
        if (s + 2 < NKT) g_load_stage(smem_base, s + 2, tid, a, b);
        cp_commit();

        uint32_t stb = smem_base + (uint32_t)(s % NSTAGE) * STAGEB;
        #pragma unroll
        for (int k16 = 0; k16 < 4; k16++) {
            const uint32_t koff = (uint32_t)(k16 * 32);
            uint32_t af[4][4];
            #pragma unroll
            for (int mt = 0; mt < 4; mt++) {
                uint32_t addr = stb + (uint32_t)(wm * 64 + mt * 16 + a_row) * ROWB
                              + koff + a_byt;
                LDSM4(af[mt][0], af[mt][1], af[mt][2], af[mt][3], addr);
            }
            uint32_t bf[2][4];
            #pragma unroll
            for (int nb = 0; nb < 2; nb++) {
                uint32_t addr = stb + TILEB + (uint32_t)(wn * 32 + nb * 16 + b_row) * ROWB
                              + koff + b_byt;
                LDSM4(bf[nb][0], bf[nb][1], bf[nb][2], bf[nb][3], addr);
            }
            #pragma unroll
            for (int mt = 0; mt < 4; mt++)
                #pragma unroll
                for (int nt = 0; nt < 4; nt++)
                    MMAF16(acc[mt][nt],
                           af[mt][0], af[mt][1], af[mt][2], af[mt][3],
                           bf[nt >> 1][(nt & 1) * 2], bf[nt >> 1][(nt & 1) * 2 + 1]);
        }
    }

    int r0 = by * 128 + wm * 64 + (lane >> 2);
    int c0 = bx * 128 + wn * 32 + (lane & 3) * 2;
    #pragma unroll
    for (int mt = 0; mt < 4; mt++) {
        #pragma unroll
        for (int nt = 0; nt < 4; nt++) {
            int r = r0 + mt * 16;
            int c = c0 + nt * 8;
            float b0 = bias[c], b1 = bias[c + 1];
            if (OUTH) {
                __half* C = (__half*)Cv;
                *(__half2*)&C[(size_t)r * Ntot + c] =
                    __floats2half2_rn(acc[mt][nt][0] + b0, acc[mt][nt][1] + b1);
                *(__half2*)&C[(size_t)(r + 8) * Ntot + c] =
                    __floats2half2_rn(acc[mt][nt][2] + b0, acc[mt][nt][3] + b1);
            } else {
                float* C = (float*)Cv;
                float2 v0 = { acc[mt][nt][0] + b0, acc[mt][nt][1] + b1 };
                float2 v1 = { acc[mt][nt][2] + b0, acc[mt][nt][3] + b1 };
                *(float2*)&C[(size_t)r * Ntot + c] = v0;
                *(float2*)&C[(size_t)(r + 8) * Ntot + c] = v1;
            }
        }
    }
}

// ---------------- prep: weight transpose + fp16, bias concat, LN (one launch) ----------------
__global__ void prep_kernel(const float* __restrict__ Wq,
                            const float* __restrict__ Ws,
                            const float* __restrict__ Wc,
                            const float* __restrict__ Wp,
                            const float* __restrict__ bs,
                            const float* __restrict__ bc,
                            const float* __restrict__ x,
                            const float* __restrict__ gamma,
                            const float* __restrict__ beta)
{
    __shared__ float tile[32][33];
    __shared__ float red1[8], red2[8];
    int bx = blockIdx.x;
    int tid = threadIdx.y * 32 + threadIdx.x;

    if (bx == 192) {
        int i = blockIdx.y * 128 + tid;
        if (i < 1536) g_bsc[i] = bs[i];
        else if (i < 3072) g_bsc[i] = bc[i - 1536];
        return;
    }
    if (bx >= 193) {
        int row = (bx - 193) * 24 + blockIdx.y;
        if (row >= LSEQ) return;
        const float* xr = x + (size_t)row * DMODEL;

        float s = 0.f, s2 = 0.f;
        for (int i = tid; i < DMODEL; i += 256) {
            float v = xr[i];
            s += v;
            s2 = fmaf(v, v, s2);
        }
        #pragma unroll
        for (int o = 16; o > 0; o >>= 1) {
            s  += __shfl_down_sync(0xffffffffu, s, o);
            s2 += __shfl_down_sync(0xffffffffu, s2, o);
        }
        if ((tid & 31) == 0) { red1[tid >> 5] = s; red2[tid >> 5] = s2; }
        __syncthreads();
        if (tid < 8) {
            s = red1[tid]; s2 = red2[tid];
            #pragma unroll
            for (int o = 4; o > 0; o >>= 1) {
                s  += __shfl_down_sync(0xffu, s, o);
                s2 += __shfl_down_sync(0xffu, s2, o);
            }
            if (tid == 0) { red1[0] = s; red2[0] = s2; }
        }
        __syncthreads();
        float mu = red1[0] * (1.f / DMODEL);
        float var = red2[0] * (1.f / DMODEL) - mu * mu;
        float inv = rsqrtf(var + LN_EPS);

        for (int i = tid; i < DMODEL; i += 256) {
            float xv = xr[i];
            float ln = (xv - mu) * inv * gamma[i] + beta[i];
            g_a[(size_t)row * DMODEL + i] = __float2half(ln);
            g_x[(size_t)row * DMODEL + i] = __float2half(xv);
        }
        return;
    }

    const float* W; int N, rowOff;
    __half* oT;
    if (bx < 72)       { W = Wq; N = 2304; rowOff = 0;    oT = g_wqkv; }
    else if (bx < 120) { W = Ws; N = 1536; rowOff = 0;    oT = g_wsc;  bx -= 72; }
    else if (bx < 168) { W = Wc; N = 1536; rowOff = 1536; oT = g_wsc;  bx -= 120; }
    else               { W = Wp; N = 768;  rowOff = 0;    oT = g_wpr;  bx -= 168; }

    int n0 = bx * 32, k0 = blockIdx.y * 32;
    int tx = threadIdx.x, ty = threadIdx.y;
    #pragma unroll
    for (int i = 0; i < 4; i++)
        tile[ty + i * 8][tx] = W[(size_t)(k0 + ty + i * 8) * N + n0 + tx];
    __syncthreads();
    #pragma unroll
    for (int i = 0; i < 4; i++) {
        int n = ty + i * 8;
        oT[(size_t)(rowOff + n0 + n) * KDIM + k0 + tx] = __float2half(tile[tx][n]);
    }
}

// ---------------- gate + feature map (fp16 in/out, x4 vectorized) ----------------
__device__ __forceinline__ float softplus_nb(float x) {
    return __logf(1.f + __expf(x));
}
__device__ __forceinline__ float elu1(float x) {
    return (x > 0.f) ? x + 1.f : __expf(x);
}

__global__ void features_kernel() {
    int idx4 = blockIdx.x * blockDim.x + threadIdx.x;
    if (idx4 >= LSEQ * DMODEL / 4) return;
    int l = idx4 / (DMODEL / 4);
    int d = (idx4 - l * (DMODEL / 4)) * 4;

    const __half* scr = g_semh + (size_t)l * 3072;
    float4 sa4 = ld4h(scr + d);
    float4 sp4 = ld4h(scr + 768 + d);
    float4 ca4 = ld4h(scr + 1536 + d);
    float4 cp4 = ld4h(scr + 2304 + d);

    const __half* qr = g_qkvh + (size_t)l * 2304;
    float4 q4 = ld4h(qr + d);
    float4 k4 = ld4h(qr + 768 + d);
    float4 v4 = ld4h(qr + 1536 + d);

    float4 qf4, kf4;
    {
        float z, gate;
        z = softplus_nb(sa4.x) * softplus_nb(ca4.x) * __cosf(sp4.x - cp4.x);
        gate = fmaf(0.5f, tanh_fast(0.5f * z), 0.5f);
        qf4.x = elu1(q4.x); kf4.x = elu1(k4.x * gate);
        z = softplus_nb(sa4.y) * softplus_nb(ca4.y) * __cosf(sp4.y - cp4.y);
        gate = fmaf(0.5f, tanh_fast(0.5f * z), 0.5f);
        qf4.y = elu1(q4.y); kf4.y = elu1(k4.y * gate);
        z = softplus_nb(sa4.z) * softplus_nb(ca4.z) * __cosf(sp4.z - cp4.z);
        gate = fmaf(0.5f, tanh_fast(0.5f * z), 0.5f);
        qf4.z = elu1(q4.z); kf4.z = elu1(k4.z * gate);
        z = softplus_nb(sa4.w) * softplus_nb(ca4.w) * __cosf(sp4.w - cp4.w);
        gate = fmaf(0.5f, tanh_fast(0.5f * z), 0.5f);
        qf4.w = elu1(q4.w); kf4.w = elu1(k4.w * gate);
    }

    int h = d >> 6;
    int dh = d & 63;
    size_t o = (size_t)h * LSEQ * DHEAD + (size_t)l * DHEAD + dh;
    st4h(&g_qf[o], qf4);
    st4h(&g_kf[o], kf4);
    st4h(&g_vv[o], v4);
}

// ---------------- phase A: per-chunk state sums (fp16 global, fp32 smem/compute) ----------------
__global__ __launch_bounds__(256)
void chunk_sums_kernel() {
    int h = blockIdx.x / NCHUNK;
    int c = blockIdx.x % NCHUNK;
    const __half* Kb = g_kf + (size_t)h * LSEQ * DHEAD + (size_t)c * CSIZE * DHEAD;
    const __half* Vb = g_vv + (size_t)h * LSEQ * DHEAD + (size_t)c * CSIZE * DHEAD;

    __shared__ float ks[16][64];
    __shared__ float vs[16][64];
    int tid = threadIdx.x;
    int te = tid & 15;
    int td = tid >> 4;

    float acc[4][4];
    #pragma unroll
    for (int i = 0; i < 4; i++)
        #pragma unroll
        for (int j = 0; j < 4; j++) acc[i][j] = 0.f;
    float zacc[4] = {0.f, 0.f, 0.f, 0.f};

    int lr = tid >> 4;
    int lc = (tid & 15) * 4;

    for (int p0 = 0; p0 < CSIZE; p0 += 16) {
        *(float4*)&ks[lr][lc] = ld4h(&Kb[(size_t)(p0 + lr) * DHEAD + lc]);
        *(float4*)&vs[lr][lc] = ld4h(&Vb[(size_t)(p0 + lr) * DHEAD + lc]);
        __syncthreads();
        #pragma unroll
        for (int p = 0; p < 16; p++) {
            float kk[4], vvv[4];
            #pragma unroll
            for (int i = 0; i < 4; i++) kk[i] = ks[p][td * 4 + i];
            #pragma unroll
            for (int j = 0; j < 4; j++) vvv[j] = vs[p][te * 4 + j];
            #pragma unroll
            for (int i = 0; i < 4; i++)
                #pragma unroll
                for (int j = 0; j < 4; j++)
                    acc[i][j] = fmaf(kk[i], vvv[j], acc[i][j]);
            if (te == 0) {
                #pragma unroll
                for (int i = 0; i < 4; i++) zacc[i] += kk[i];
            }
        }
        __syncthreads();
    }

    float* Sb = g_S + (size_t)(h * NCHUNK + c) * DHEAD * DHEAD;
    #pragma unroll
    for (int i = 0; i < 4; i++)
        #pragma unroll
        for (int j = 0; j < 4; j++)
            Sb[(size_t)(td * 4 + i) * DHEAD + te * 4 + j] = acc[i][j];
    if (te == 0) {
        float* Zb = g_Z + (size_t)(h * NCHUNK + c) * DHEAD;
        #pragma unroll
        for (int i = 0; i < 4; i++) Zb[td * 4 + i] = zacc[i];
    }
}

// ---------------- phase B: exclusive scan over chunks (grid (12,4)) ----------------
__global__ __launch_bounds__(256)
void scan_states_kernel() {
    int h = blockIdx.x;
    int part = blockIdx.y;
    int tid = threadIdx.x;
    float pref[4] = {0.f, 0.f, 0.f, 0.f};
    float prefz = 0.f;

    for (int c = 0; c < NCHUNK; c++) {
        float* Sb = g_S + (size_t)(h * NCHUNK + c) * DHEAD * DHEAD + part * 1024;
        #pragma unroll
        for (int i = 0; i < 4; i++) {
            int idx = tid + i * 256;
            float cur = Sb[idx];
            Sb[idx] = pref[i];
            pref[i] += cur;
        }
        if (part == 0 && tid < DHEAD) {
            float* Zb = g_Z + (size_t)(h * NCHUNK + c) * DHEAD;
            float cur = Zb[tid];
            Zb[tid] = prefz;
            prefz += cur;
        }
    }
}

// ---------------- phase C: per-chunk causal output (SMSP-staggered row mapping) ----------------
#define SMEM_C (2 * CSIZE * DHEAD * 4)   // 65536 B

__global__ __launch_bounds__(128)
void chunk_attn_kernel() {
    int h = blockIdx.x / NCHUNK;
    int c = blockIdx.x % NCHUNK;
    extern __shared__ float sh[];
    float* Ks = sh;
    float* Vs = Ks + CSIZE * DHEAD;

    int tid = threadIdx.x;
    // Stagger row-range across warps per block: warp w of block b handles
    // row range ((w + b) & 3). Balances heavy (high-row) ranges across SMSPs,
    // since warp w always executes on SMSP w for all co-resident CTAs.
    int wid = tid >> 5;
    int lane = tid & 31;
    int row = (((wid + blockIdx.x) & 3) << 5) + lane;
    size_t base = (size_t)h * LSEQ * DHEAD + (size_t)c * CSIZE * DHEAD;

    const __half* Kg = g_kf + base;
    const __half* Vg = g_vv + base;
    for (int j = tid; j < CSIZE * DHEAD / 4; j += 128) {
        ((float4*)Ks)[j] = ld4h(Kg + 4 * j);
        ((float4*)Vs)[j] = ld4h(Vg + 4 * j);
    }
    __syncthreads();

    float q[DHEAD];
    {
        const __half* qp = g_qf + base + (size_t)row * DHEAD;
        #pragma unroll
        for (int i = 0; i < DHEAD / 4; i++) {
            float4 t = ld4h(qp + 4 * i);
            q[4 * i + 0] = t.x; q[4 * i + 1] = t.y; q[4 * i + 2] = t.z; q[4 * i + 3] = t.w;
        }
    }

    const float* Pg = g_S + (size_t)(h * NCHUNK + c) * DHEAD * DHEAD;
    const float* Zg = g_Z + (size_t)(h * NCHUNK + c) * DHEAD;

    float out[DHEAD];
    float den = 0.f;
    #pragma unroll
    for (int d = 0; d < DHEAD; d++) den = fmaf(q[d], __ldg(&Zg[d]), den);
    #pragma unroll
    for (int e = 0; e < DHEAD; e++) out[e] = 0.f;
    #pragma unroll 4
    for (int d = 0; d < DHEAD; d++) {
        float qd = q[d];
        const float4* pr = (const float4*)(Pg + d * DHEAD);
        #pragma unroll
        for (int i = 0; i < DHEAD / 4; i++) {
            float4 p = __ldg(&pr[i]);
            out[4 * i + 0] = fmaf(qd, p.x, out[4 * i + 0]);
            out[4 * i + 1] = fmaf(qd, p.y, out[4 * i + 1]);
            out[4 * i + 2] = fmaf(qd, p.z, out[4 * i + 2]);
            out[4 * i + 3] = fmaf(qd, p.w, out[4 * i + 3]);
        }
    }

    for (int j = 0; j <= row; j++) {
        const float4* kr = (const float4*)(Ks + j * DHEAD);
        float s0 = 0.f, s1 = 0.f, s2 = 0.f, s3 = 0.f;
        #pragma unroll
        for (int i = 0; i < DHEAD / 4; i += 4) {
            float4 k0 = kr[i], k1 = kr[i + 1], k2 = kr[i + 2], k3 = kr[i + 3];
            s0 = fmaf(q[4 * i + 0], k0.x, s0); s0 = fmaf(q[4 * i + 1], k0.y, s0);
            s0 = fmaf(q[4 * i + 2], k0.z, s0); s0 = fmaf(q[4 * i + 3], k0.w, s0);
            s1 = fmaf(q[4 * i + 4], k1.x, s1); s1 = fmaf(q[4 * i + 5], k1.y, s1);
            s1 = fmaf(q[4 * i + 6], k1.z, s1); s1 = fmaf(q[4 * i + 7], k1.w, s1);
            s2 = fmaf(q[4 * i + 8], k2.x, s2); s2 = fmaf(q[4 * i + 9], k2.y, s2);
            s2 = fmaf(q[4 * i + 10], k2.z, s2); s2 = fmaf(q[4 * i + 11], k2.w, s2);
            s3 = fmaf(q[4 * i + 12], k3.x, s3); s3 = fmaf(q[4 * i + 13], k3.y, s3);
            s3 = fmaf(q[4 * i + 14], k3.z, s3); s3 = fmaf(q[4 * i + 15], k3.w, s3);
        }
        float s = (s0 + s1) + (s2 + s3);
        den += s;
        const float4* vr = (const float4*)(Vs + j * DHEAD);
        #pragma unroll
        for (int i = 0; i < DHEAD / 4; i++) {
            float4 vv4 = vr[i];
            out[4 * i + 0] = fmaf(s, vv4.x, out[4 * i + 0]);
            out[4 * i + 1] = fmaf(s, vv4.y, out[4 * i + 1]);
            out[4 * i + 2] = fmaf(s, vv4.z, out[4 * i + 2]);
            out[4 * i + 3] = fmaf(s, vv4.w, out[4 * i + 3]);
        }
    }

    float inv = 1.f / (den + DEN_EPS);
    int l = c * CSIZE + row;
    __half* op = g_at + (size_t)l * DMODEL + h * DHEAD;
    #pragma unroll
    for (int e = 0; e < DHEAD; e += 2) {
        __half2 hv = __floats2half2_rn(out[e] * inv, out[e + 1] * inv);
        *(__half2*)&op[e] = hv;
    }
}

// ---------------- host launcher ----------------
extern "C" void kernel_launch(void* const* d_in, const int* in_sizes, int n_in,
                              void* d_out, int out_size) {
    const float* x      = (const float*)d_in[0];
    const float* W_qkv  = (const float*)d_in[1];
    const float* b_qkv  = (const float*)d_in[2];
    const float* W_sem  = (const float*)d_in[3];
    const float* b_sem  = (const float*)d_in[4];
    const float* W_ctx  = (const float*)d_in[5];
    const float* b_ctx  = (const float*)d_in[6];
    const float* W_proj = (const float*)d_in[7];
    const float* b_proj = (const float*)d_in[8];
    const float* ln_g   = (const float*)d_in[9];
    const float* ln_b   = (const float*)d_in[10];
    float* out = (float*)d_out;

    __half *p_a, *p_x, *p_wq, *p_ws, *p_wp, *p_at, *p_qkvh, *p_semh;
    float *p_bsc;
    cudaGetSymbolAddress((void**)&p_a, g_a);
    cudaGetSymbolAddress((void**)&p_x, g_x);
    cudaGetSymbolAddress((void**)&p_wq, g_wqkv);
    cudaGetSymbolAddress((void**)&p_ws, g_wsc);
    cudaGetSymbolAddress((void**)&p_wp, g_wpr);
    cudaGetSymbolAddress((void**)&p_at, g_at);
    cudaGetSymbolAddress((void**)&p_bsc, g_bsc);
    cudaGetSymbolAddress((void**)&p_qkvh, g_qkvh);
    cudaGetSymbolAddress((void**)&p_semh, g_semh);

    cudaFuncSetAttribute(gemm_mma<1>, cudaFuncAttributeMaxDynamicSharedMemorySize, GEMM_SMEM);
    cudaFuncSetAttribute(gemm_mma<0>, cudaFuncAttributeMaxDynamicSharedMemorySize, GEMM_SMEM);
    cudaFuncSetAttribute(chunk_attn_kernel, cudaFuncAttributeMaxDynamicSharedMemorySize, SMEM_C);

    // prep: transpose + fp16 + bias concat + LN (single launch)
    prep_kernel<<<dim3(279, 24), dim3(32, 8)>>>(W_qkv, W_sem, W_ctx, W_proj,
                                                b_sem, b_ctx, x, ln_g, ln_b);

    // fp16 tensor-core GEMMs (fp16 outputs for intermediates)
    gemm_mma<1><<<dim3(2304 / 128, LSEQ / 128), 256, GEMM_SMEM>>>(p_a, p_wq, b_qkv, p_qkvh, 2304);
    gemm_mma<1><<<dim3(3072 / 128, LSEQ / 128), 256, GEMM_SMEM>>>(p_x, p_ws, p_bsc, p_semh, 3072);

    // gate + feature map (fp16 in/out)
    features_kernel<<<(LSEQ * DMODEL / 4 + 255) / 256, 256>>>();

    // chunked linear attention
    chunk_sums_kernel<<<NHEAD * NCHUNK, 256>>>();
    scan_states_kernel<<<dim3(NHEAD, 4), 256>>>();
    chunk_attn_kernel<<<NHEAD * NCHUNK, 128, SMEM_C>>>();

    // output projection (fp32 out -> d_out)
    gemm_mma<0><<<dim3(768 / 128, LSEQ / 128), 256, GEMM_SMEM>>>(p_at, p_wp, b_proj, out, 768);
}

// round 16
// speedup vs baseline: 1.6408x; 1.0172x over previous
#include <cuda_runtime.h>
#include <cuda_fp16.h>
#include <math.h>
#include <stdint.h>

// ---------------- problem constants ----------------
#define LSEQ 2048
#define DMODEL 768
#define KDIM 768
#define NHEAD 12
#define DHEAD 64
#define NCHUNK 32
#define CSIZE 64          // chunk size (NCHUNK*CSIZE == LSEQ)
#define LN_EPS 1e-5f
#define DEN_EPS 1e-6f

// ---------------- scratch (device globals) ----------------
__device__ __align__(128) __half g_a   [LSEQ * DMODEL];   // LN(x) fp16
__device__ __align__(128) __half g_x   [LSEQ * DMODEL];   // x fp16
__device__ __align__(128) __half g_wqkv[2304 * KDIM];     // W_qkv^T fp16
__device__ __align__(128) __half g_wsc [3072 * KDIM];     // [W_sem;W_ctx]^T fp16
__device__ __align__(128) __half g_wpr [768 * KDIM];      // W_proj^T fp16
__device__ __align__(128) __half g_at  [LSEQ * DMODEL];   // attn out fp16
__device__ __align__(128) float g_bsc[3072];
__device__ __align__(128) __half g_qkvh[LSEQ * 3 * DMODEL];  // qkv GEMM out fp16
__device__ __align__(128) __half g_semh[LSEQ * 3072];        // sem/ctx GEMM out fp16
__device__ __align__(128) __half g_qf[NHEAD * LSEQ * DHEAD]; // features fp16
__device__ __align__(128) __half g_kf[NHEAD * LSEQ * DHEAD];
__device__ __align__(128) __half g_vv[NHEAD * LSEQ * DHEAD];
__device__ float g_S [NHEAD * NCHUNK * DHEAD * DHEAD];
__device__ float g_Z [NHEAD * NCHUNK * DHEAD];

// ---------------- PTX helpers (family-portable only) ----------------
__device__ __forceinline__ uint32_t smem_u32(const void* p) {
    uint32_t a;
    asm("{ .reg .u64 t; cvta.to.shared.u64 t, %1; cvt.u32.u64 %0, t; }" : "=r"(a) : "l"(p));
    return a;
}
__device__ __forceinline__ void cp_async16(uint32_t dst, const void* src) {
    asm volatile("cp.async.cg.shared.global [%0], [%1], 16;" :: "r"(dst), "l"(src));
}
__device__ __forceinline__ void cp_commit() {
    asm volatile("cp.async.commit_group;" ::: "memory");
}
__device__ __forceinline__ void cp_wait1() {
    asm volatile("cp.async.wait_group 1;" ::: "memory");
}
__device__ __forceinline__ float tanh_fast(float x) {
    float y;
    asm("tanh.approx.f32 %0, %1;" : "=f"(y) : "f"(x));
    return y;
}
__device__ __forceinline__ float4 ld4h(const __half* p) {
    uint2 u = *(const uint2*)p;
    float2 fa = __half22float2(*(__half2*)&u.x);
    float2 fb = __half22float2(*(__half2*)&u.y);
    return make_float4(fa.x, fa.y, fb.x, fb.y);
}
__device__ __forceinline__ void st4h(__half* p, float4 v) {
    uint2 u;
    *(__half2*)&u.x = __floats2half2_rn(v.x, v.y);
    *(__half2*)&u.y = __floats2half2_rn(v.z, v.w);
    *(uint2*)p = u;
}
#define LDSM4(r0, r1, r2, r3, a) \
    asm volatile("ldmatrix.sync.aligned.m8n8.x4.shared.b16 {%0,%1,%2,%3}, [%4];" \
                 : "=r"(r0), "=r"(r1), "=r"(r2), "=r"(r3) : "r"(a))
#define MMAF16(d, a0, a1, a2, a3, b0, b1) \
    asm volatile("mma.sync.aligned.m16n8k16.row.col.f32.f16.f16.f32 " \
                 "{%0,%1,%2,%3}, {%4,%5,%6,%7}, {%8,%9}, {%0,%1,%2,%3};" \
                 : "+f"((d)[0]), "+f"((d)[1]), "+f"((d)[2]), "+f"((d)[3]) \
                 : "r"(a0), "r"(a1), "r"(a2), "r"(a3), "r"(b0), "r"(b1))

// ---------------- GEMM: C[2048,Ntot] = A @ B^T + bias (fp16, BK=64) ----------------
#define BK 64
#define ROWB 144
#define TILEB (128 * ROWB)
#define STAGEB (2 * TILEB)
#define NSTAGE 3
#define GEMM_SMEM (NSTAGE * STAGEB)   // 110592 B -> 2 CTAs/SM
#define NKT (KDIM / BK)               // 12

__device__ __forceinline__ void g_load_stage(
    uint32_t smem_base, int s, int tid,
    const __half* a, const __half* b)
{
    uint32_t stb = smem_base + (uint32_t)(s % NSTAGE) * STAGEB;
    int kk = s * BK;
    #pragma unroll
    for (int t = 0; t < 2; t++) {
        const __half* base = t ? b : a;
        #pragma unroll
        for (int i = 0; i < 4; i++) {
            int c = tid + i * 256;
            int r = c >> 3;
            int seg = c & 7;
            cp_async16(stb + (uint32_t)t * TILEB + (uint32_t)(r * ROWB + seg * 16),
                       base + (size_t)r * KDIM + kk + seg * 8);
        }
    }
}

// OUTH=1: store fp16; OUTH=0: store fp32
template<int OUTH>
__global__ __launch_bounds__(256, 2)
void gemm_mma(const __half* __restrict__ A, const __half* __restrict__ BT,
              const float* __restrict__ bias, void* __restrict__ Cv, int Ntot)
{
    extern __shared__ __align__(128) char smem[];
    const int tid = threadIdx.x;
    const int wid = tid >> 5;
    const int lane = tid & 31;
    const int wm = wid & 1;
    const int wn = wid >> 1;
    const int bx = blockIdx.x, by = blockIdx.y;

    uint32_t smem_base = smem_u32(smem);

    const __half* a = A + (size_t)by * 128 * KDIM;
    const __half* b = BT + (size_t)bx * 128 * KDIM;

    float acc[4][4][4];
    #pragma unroll
    for (int i = 0; i < 4; i++)
        #pragma unroll
        for (int j = 0; j < 4; j++)
            #pragma unroll
            for (int t = 0; t < 4; t++) acc[i][j][t] = 0.f;

    const uint32_t a_row = (uint32_t)(lane & 15);
    const uint32_t a_byt = (uint32_t)((lane >> 4) * 16);
    const uint32_t b_row = (uint32_t)((lane & 7) + ((lane >> 4) << 3));
    const uint32_t b_byt = (uint32_t)(((lane >> 3) & 1) * 16);

    g_load_stage(smem_base, 0, tid, a, b); cp_commit();
    g_load_stage(smem_base, 1, tid, a, b); cp_commit();

    for (int s = 0; s < NKT; s++) {
        cp_wait1();
        __syncthreads();
        if (s + 2 < NKT) g_load_stage(smem_base, s + 2, tid, a, b);
        cp_commit();

        uint32_t stb = smem_base + (uint32_t)(s % NSTAGE) * STAGEB;
        #pragma unroll
        for (int k16 = 0; k16 < 4; k16++) {
            const uint32_t koff = (uint32_t)(k16 * 32);
            uint32_t af[4][4];
            #pragma unroll
            for (int mt = 0; mt < 4; mt++) {
                uint32_t addr = stb + (uint32_t)(wm * 64 + mt * 16 + a_row) * ROWB
                              + koff + a_byt;
                LDSM4(af[mt][0], af[mt][1], af[mt][2], af[mt][3], addr);
            }
            uint32_t bf[2][4];
            #pragma unroll
            for (int nb = 0; nb < 2; nb++) {
                uint32_t addr = stb + TILEB + (uint32_t)(wn * 32 + nb * 16 + b_row) * ROWB
                              + koff + b_byt;
                LDSM4(bf[nb][0], bf[nb][1], bf[nb][2], bf[nb][3], addr);
            }
            #pragma unroll
            for (int mt = 0; mt < 4; mt++)
                #pragma unroll
                for (int nt = 0; nt < 4; nt++)
                    MMAF16(acc[mt][nt],
                           af[mt][0], af[mt][1], af[mt][2], af[mt][3],
                           bf[nt >> 1][(nt & 1) * 2], bf[nt >> 1][(nt & 1) * 2 + 1]);
        }
    }

    int r0 = by * 128 + wm * 64 + (lane >> 2);
    int c0 = bx * 128 + wn * 32 + (lane & 3) * 2;
    #pragma unroll
    for (int mt = 0; mt < 4; mt++) {
        #pragma unroll
        for (int nt = 0; nt < 4; nt++) {
            int r = r0 + mt * 16;
            int c = c0 + nt * 8;
            float b0 = bias[c], b1 = bias[c + 1];
            if (OUTH) {
                __half* C = (__half*)Cv;
                *(__half2*)&C[(size_t)r * Ntot + c] =
                    __floats2half2_rn(acc[mt][nt][0] + b0, acc[mt][nt][1] + b1);
                *(__half2*)&C[(size_t)(r + 8) * Ntot + c] =
                    __floats2half2_rn(acc[mt][nt][2] + b0, acc[mt][nt][3] + b1);
            } else {
                float* C = (float*)Cv;
                float2 v0 = { acc[mt][nt][0] + b0, acc[mt][nt][1] + b1 };
                float2 v1 = { acc[mt][nt][2] + b0, acc[mt][nt][3] + b1 };
                *(float2*)&C[(size_t)r * Ntot + c] = v0;
                *(float2*)&C[(size_t)(r + 8) * Ntot + c] = v1;
            }
        }
    }
}

// ---------------- prep: weight transpose + fp16, bias concat, LN (one launch) ----------------
__global__ void prep_kernel(const float* __restrict__ Wq,
                            const float* __restrict__ Ws,
                            const float* __restrict__ Wc,
                            const float* __restrict__ Wp,
                            const float* __restrict__ bs,
                            const float* __restrict__ bc,
                            const float* __restrict__ x,
                            const float* __restrict__ gamma,
                            const float* __restrict__ beta)
{
    __shared__ float tile[32][33];
    __shared__ float red1[8], red2[8];
    int bx = blockIdx.x;
    int tid = threadIdx.y * 32 + threadIdx.x;

    if (bx == 192) {
        int i = blockIdx.y * 128 + tid;
        if (i < 1536) g_bsc[i] = bs[i];
        else if (i < 3072) g_bsc[i] = bc[i - 1536];
        return;
    }
    if (bx >= 193) {
        int row = (bx - 193) * 24 + blockIdx.y;
        if (row >= LSEQ) return;
        const float* xr = x + (size_t)row * DMODEL;

        float s = 0.f, s2 = 0.f;
        for (int i = tid; i < DMODEL; i += 256) {
            float v = xr[i];
            s += v;
            s2 = fmaf(v, v, s2);
        }
        #pragma unroll
        for (int o = 16; o > 0; o >>= 1) {
            s  += __shfl_down_sync(0xffffffffu, s, o);
            s2 += __shfl_down_sync(0xffffffffu, s2, o);
        }
        if ((tid & 31) == 0) { red1[tid >> 5] = s; red2[tid >> 5] = s2; }
        __syncthreads();
        if (tid < 8) {
            s = red1[tid]; s2 = red2[tid];
            #pragma unroll
            for (int o = 4; o > 0; o >>= 1) {
                s  += __shfl_down_sync(0xffu, s, o);
                s2 += __shfl_down_sync(0xffu, s2, o);
            }
            if (tid == 0) { red1[0] = s; red2[0] = s2; }
        }
        __syncthreads();
        float mu = red1[0] * (1.f / DMODEL);
        float var = red2[0] * (1.f / DMODEL) - mu * mu;
        float inv = rsqrtf(var + LN_EPS);

        for (int i = tid; i < DMODEL; i += 256) {
            float xv = xr[i];
            float ln = (xv - mu) * inv * gamma[i] + beta[i];
            g_a[(size_t)row * DMODEL + i] = __float2half(ln);
            g_x[(size_t)row * DMODEL + i] = __float2half(xv);
        }
        return;
    }

    const float* W; int N, rowOff;
    __half* oT;
    if (bx < 72)       { W = Wq; N = 2304; rowOff = 0;    oT = g_wqkv; }
    else if (bx < 120) { W = Ws; N = 1536; rowOff = 0;    oT = g_wsc;  bx -= 72; }
    else if (bx < 168) { W = Wc; N = 1536; rowOff = 1536; oT = g_wsc;  bx -= 120; }
    else               { W = Wp; N = 768;  rowOff = 0;    oT = g_wpr;  bx -= 168; }

    int n0 = bx * 32, k0 = blockIdx.y * 32;
    int tx = threadIdx.x, ty = threadIdx.y;
    #pragma unroll
    for (int i = 0; i < 4; i++)
        tile[ty + i * 8][tx] = W[(size_t)(k0 + ty + i * 8) * N + n0 + tx];
    __syncthreads();
    #pragma unroll
    for (int i = 0; i < 4; i++) {
        int n = ty + i * 8;
        oT[(size_t)(rowOff + n0 + n) * KDIM + k0 + tx] = __float2half(tile[tx][n]);
    }
}

// ---------------- gate + feature map (fp16 in/out, x4 vectorized) ----------------
__device__ __forceinline__ float softplus_nb(float x) {
    return __logf(1.f + __expf(x));
}
__device__ __forceinline__ float elu1(float x) {
    return (x > 0.f) ? x + 1.f : __expf(x);
}

__global__ void features_kernel() {
    int idx4 = blockIdx.x * blockDim.x + threadIdx.x;
    if (idx4 >= LSEQ * DMODEL / 4) return;
    int l = idx4 / (DMODEL / 4);
    int d = (idx4 - l * (DMODEL / 4)) * 4;

    const __half* scr = g_semh + (size_t)l * 3072;
    float4 sa4 = ld4h(scr + d);
    float4 sp4 = ld4h(scr + 768 + d);
    float4 ca4 = ld4h(scr + 1536 + d);
    float4 cp4 = ld4h(scr + 2304 + d);

    const __half* qr = g_qkvh + (size_t)l * 2304;
    float4 q4 = ld4h(qr + d);
    float4 k4 = ld4h(qr + 768 + d);
    float4 v4 = ld4h(qr + 1536 + d);

    float4 qf4, kf4;
    {
        float z, gate;
        z = softplus_nb(sa4.x) * softplus_nb(ca4.x) * __cosf(sp4.x - cp4.x);
        gate = fmaf(0.5f, tanh_fast(0.5f * z), 0.5f);
        qf4.x = elu1(q4.x); kf4.x = elu1(k4.x * gate);
        z = softplus_nb(sa4.y) * softplus_nb(ca4.y) * __cosf(sp4.y - cp4.y);
        gate = fmaf(0.5f, tanh_fast(0.5f * z), 0.5f);
        qf4.y = elu1(q4.y); kf4.y = elu1(k4.y * gate);
        z = softplus_nb(sa4.z) * softplus_nb(ca4.z) * __cosf(sp4.z - cp4.z);
        gate = fmaf(0.5f, tanh_fast(0.5f * z), 0.5f);
        qf4.z = elu1(q4.z); kf4.z = elu1(k4.z * gate);
        z = softplus_nb(sa4.w) * softplus_nb(ca4.w) * __cosf(sp4.w - cp4.w);
        gate = fmaf(0.5f, tanh_fast(0.5f * z), 0.5f);
        qf4.w = elu1(q4.w); kf4.w = elu1(k4.w * gate);
    }

    int h = d >> 6;
    int dh = d & 63;
    size_t o = (size_t)h * LSEQ * DHEAD + (size_t)l * DHEAD + dh;
    st4h(&g_qf[o], qf4);
    st4h(&g_kf[o], kf4);
    st4h(&g_vv[o], v4);
}

// ---------------- phase A: per-chunk state sums (CSIZE=64) ----------------
__global__ __launch_bounds__(256)
void chunk_sums_kernel() {
    int h = blockIdx.x / NCHUNK;
    int c = blockIdx.x % NCHUNK;
    const __half* Kb = g_kf + (size_t)h * LSEQ * DHEAD + (size_t)c * CSIZE * DHEAD;
    const __half* Vb = g_vv + (size_t)h * LSEQ * DHEAD + (size_t)c * CSIZE * DHEAD;

    __shared__ float ks[16][64];
    __shared__ float vs[16][64];
    int tid = threadIdx.x;
    int te = tid & 15;
    int td = tid >> 4;

    float acc[4][4];
    #pragma unroll
    for (int i = 0; i < 4; i++)
        #pragma unroll
        for (int j = 0; j < 4; j++) acc[i][j] = 0.f;
    float zacc[4] = {0.f, 0.f, 0.f, 0.f};

    int lr = tid >> 4;
    int lc = (tid & 15) * 4;

    for (int p0 = 0; p0 < CSIZE; p0 += 16) {
        *(float4*)&ks[lr][lc] = ld4h(&Kb[(size_t)(p0 + lr) * DHEAD + lc]);
        *(float4*)&vs[lr][lc] = ld4h(&Vb[(size_t)(p0 + lr) * DHEAD + lc]);
        __syncthreads();
        #pragma unroll
        for (int p = 0; p < 16; p++) {
            float kk[4], vvv[4];
            #pragma unroll
            for (int i = 0; i < 4; i++) kk[i] = ks[p][td * 4 + i];
            #pragma unroll
            for (int j = 0; j < 4; j++) vvv[j] = vs[p][te * 4 + j];
            #pragma unroll
            for (int i = 0; i < 4; i++)
                #pragma unroll
                for (int j = 0; j < 4; j++)
                    acc[i][j] = fmaf(kk[i], vvv[j], acc[i][j]);
            if (te == 0) {
                #pragma unroll
                for (int i = 0; i < 4; i++) zacc[i] += kk[i];
            }
        }
        __syncthreads();
    }

    float* Sb = g_S + (size_t)(h * NCHUNK + c) * DHEAD * DHEAD;
    #pragma unroll
    for (int i = 0; i < 4; i++)
        #pragma unroll
        for (int j = 0; j < 4; j++)
            Sb[(size_t)(td * 4 + i) * DHEAD + te * 4 + j] = acc[i][j];
    if (te == 0) {
        float* Zb = g_Z + (size_t)(h * NCHUNK + c) * DHEAD;
        #pragma unroll
        for (int i = 0; i < 4; i++) Zb[td * 4 + i] = zacc[i];
    }
}

// ---------------- phase B: exclusive scan over chunks (grid (12,4), 32 steps) ----------------
__global__ __launch_bounds__(256)
void scan_states_kernel() {
    int h = blockIdx.x;
    int part = blockIdx.y;
    int tid = threadIdx.x;
    float pref[4] = {0.f, 0.f, 0.f, 0.f};
    float prefz = 0.f;

    for (int c = 0; c < NCHUNK; c++) {
        float* Sb = g_S + (size_t)(h * NCHUNK + c) * DHEAD * DHEAD + part * 1024;
        #pragma unroll
        for (int i = 0; i < 4; i++) {
            int idx = tid + i * 256;
            float cur = Sb[idx];
            Sb[idx] = pref[i];
            pref[i] += cur;
        }
        if (part == 0 && tid < DHEAD) {
            float* Zb = g_Z + (size_t)(h * NCHUNK + c) * DHEAD;
            float cur = Zb[tid];
            Zb[tid] = prefz;
            prefz += cur;
        }
    }
}

// ---------------- phase C: per-chunk causal output (CSIZE=64, 64 threads) ----------------
#define SMEM_C (2 * CSIZE * DHEAD * 4)   // 32768 B

__global__ __launch_bounds__(64)
void chunk_attn_kernel() {
    int h = blockIdx.x / NCHUNK;
    int c = blockIdx.x % NCHUNK;
    extern __shared__ float sh[];
    float* Ks = sh;
    float* Vs = Ks + CSIZE * DHEAD;

    int tid = threadIdx.x;
    // SMSP stagger over 2 warps
    int wid = tid >> 5;
    int lane = tid & 31;
    int row = (((wid + blockIdx.x) & 1) << 5) + lane;
    size_t base = (size_t)h * LSEQ * DHEAD + (size_t)c * CSIZE * DHEAD;

    const __half* Kg = g_kf + base;
    const __half* Vg = g_vv + base;
    for (int j = tid; j < CSIZE * DHEAD / 4; j += 64) {
        ((float4*)Ks)[j] = ld4h(Kg + 4 * j);
        ((float4*)Vs)[j] = ld4h(Vg + 4 * j);
    }
    __syncthreads();

    float q[DHEAD];
    {
        const __half* qp = g_qf + base + (size_t)row * DHEAD;
        #pragma unroll
        for (int i = 0; i < DHEAD / 4; i++) {
            float4 t = ld4h(qp + 4 * i);
            q[4 * i + 0] = t.x; q[4 * i + 1] = t.y; q[4 * i + 2] = t.z; q[4 * i + 3] = t.w;
        }
    }

    const float* Pg = g_S + (size_t)(h * NCHUNK + c) * DHEAD * DHEAD;
    const float* Zg = g_Z + (size_t)(h * NCHUNK + c) * DHEAD;

    float out[DHEAD];
    float den = 0.f;
    #pragma unroll
    for (int d = 0; d < DHEAD; d++) den = fmaf(q[d], __ldg(&Zg[d]), den);
    #pragma unroll
    for (int e = 0; e < DHEAD; e++) out[e] = 0.f;
    #pragma unroll 4
    for (int d = 0; d < DHEAD; d++) {
        float qd = q[d];
        const float4* pr = (const float4*)(Pg + d * DHEAD);
        #pragma unroll
        for (int i = 0; i < DHEAD / 4; i++) {
            float4 p = __ldg(&pr[i]);
            out[4 * i + 0] = fmaf(qd, p.x, out[4 * i + 0]);
            out[4 * i + 1] = fmaf(qd, p.y, out[4 * i + 1]);
            out[4 * i + 2] = fmaf(qd, p.z, out[4 * i + 2]);
            out[4 * i + 3] = fmaf(qd, p.w, out[4 * i + 3]);
        }
    }

    for (int j = 0; j <= row; j++) {
        const float4* kr = (const float4*)(Ks + j * DHEAD);
        float s0 = 0.f, s1 = 0.f, s2 = 0.f, s3 = 0.f;
        #pragma unroll
        for (int i = 0; i < DHEAD / 4; i += 4) {
            float4 k0 = kr[i], k1 = kr[i + 1], k2 = kr[i + 2], k3 = kr[i + 3];
            s0 = fmaf(q[4 * i + 0], k0.x, s0); s0 = fmaf(q[4 * i + 1], k0.y, s0);
            s0 = fmaf(q[4 * i + 2], k0.z, s0); s0 = fmaf(q[4 * i + 3], k0.w, s0);
            s1 = fmaf(q[4 * i + 4], k1.x, s1); s1 = fmaf(q[4 * i + 5], k1.y, s1);
            s1 = fmaf(q[4 * i + 6], k1.z, s1); s1 = fmaf(q[4 * i + 7], k1.w, s1);
            s2 = fmaf(q[4 * i + 8], k2.x, s2); s2 = fmaf(q[4 * i + 9], k2.y, s2);
            s2 = fmaf(q[4 * i + 10], k2.z, s2); s2 = fmaf(q[4 * i + 11], k2.w, s2);
            s3 = fmaf(q[4 * i + 12], k3.x, s3); s3 = fmaf(q[4 * i + 13], k3.y, s3);
            s3 = fmaf(q[4 * i + 14], k3.z, s3); s3 = fmaf(q[4 * i + 15], k3.w, s3);
        }
        float s = (s0 + s1) + (s2 + s3);
        den += s;
        const float4* vr = (const float4*)(Vs + j * DHEAD);
        #pragma unroll
        for (int i = 0; i < DHEAD / 4; i++) {
            float4 vv4 = vr[i];
            out[4 * i + 0] = fmaf(s, vv4.x, out[4 * i + 0]);
            out[4 * i + 1] = fmaf(s, vv4.y, out[4 * i + 1]);
            out[4 * i + 2] = fmaf(s, vv4.z, out[4 * i + 2]);
            out[4 * i + 3] = fmaf(s, vv4.w, out[4 * i + 3]);
        }
    }

    float inv = 1.f / (den + DEN_EPS);
    int l = c * CSIZE + row;
    __half* op = g_at + (size_t)l * DMODEL + h * DHEAD;
    #pragma unroll
    for (int e = 0; e < DHEAD; e += 2) {
        __half2 hv = __floats2half2_rn(out[e] * inv, out[e + 1] * inv);
        *(__half2*)&op[e] = hv;
    }
}

// ---------------- host launcher ----------------
extern "C" void kernel_launch(void* const* d_in, const int* in_sizes, int n_in,
                              void* d_out, int out_size) {
    const float* x      = (const float*)d_in[0];
    const float* W_qkv  = (const float*)d_in[1];
    const float* b_qkv  = (const float*)d_in[2];
    const float* W_sem  = (const float*)d_in[3];
    const float* b_sem  = (const float*)d_in[4];
    const float* W_ctx  = (const float*)d_in[5];
    const float* b_ctx  = (const float*)d_in[6];
    const float* W_proj = (const float*)d_in[7];
    const float* b_proj = (const float*)d_in[8];
    const float* ln_g   = (const float*)d_in[9];
    const float* ln_b   = (const float*)d_in[10];
    float* out = (float*)d_out;

    __half *p_a, *p_x, *p_wq, *p_ws, *p_wp, *p_at, *p_qkvh, *p_semh;
    float *p_bsc;
    cudaGetSymbolAddress((void**)&p_a, g_a);
    cudaGetSymbolAddress((void**)&p_x, g_x);
    cudaGetSymbolAddress((void**)&p_wq, g_wqkv);
    cudaGetSymbolAddress((void**)&p_ws, g_wsc);
    cudaGetSymbolAddress((void**)&p_wp, g_wpr);
    cudaGetSymbolAddress((void**)&p_at, g_at);
    cudaGetSymbolAddress((void**)&p_bsc, g_bsc);
    cudaGetSymbolAddress((void**)&p_qkvh, g_qkvh);
    cudaGetSymbolAddress((void**)&p_semh, g_semh);

    cudaFuncSetAttribute(gemm_mma<1>, cudaFuncAttributeMaxDynamicSharedMemorySize, GEMM_SMEM);
    cudaFuncSetAttribute(gemm_mma<0>, cudaFuncAttributeMaxDynamicSharedMemorySize, GEMM_SMEM);
    cudaFuncSetAttribute(chunk_attn_kernel, cudaFuncAttributeMaxDynamicSharedMemorySize, SMEM_C);

    // prep: transpose + fp16 + bias concat + LN (single launch)
    prep_kernel<<<dim3(279, 24), dim3(32, 8)>>>(W_qkv, W_sem, W_ctx, W_proj,
                                                b_sem, b_ctx, x, ln_g, ln_b);

    // fp16 tensor-core GEMMs (fp16 outputs for intermediates)
    gemm_mma<1><<<dim3(2304 / 128, LSEQ / 128), 256, GEMM_SMEM>>>(p_a, p_wq, b_qkv, p_qkvh, 2304);
    gemm_mma<1><<<dim3(3072 / 128, LSEQ / 128), 256, GEMM_SMEM>>>(p_x, p_ws, p_bsc, p_semh, 3072);

    // gate + feature map (fp16 in/out)
    features_kernel<<<(LSEQ * DMODEL / 4 + 255) / 256, 256>>>();

    // chunked linear attention (CSIZE=64)
    chunk_sums_kernel<<<NHEAD * NCHUNK, 256>>>();
    scan_states_kernel<<<dim3(NHEAD, 4), 256>>>();
    chunk_attn_kernel<<<NHEAD * NCHUNK, 64, SMEM_C>>>();

    // output projection (fp32 out -> d_out)
    gemm_mma<0><<<dim3(768 / 128, LSEQ / 128), 256, GEMM_SMEM>>>(p_at, p_wp, b_proj, out, 768);
}